// round 8
// baseline (speedup 1.0000x reference)
#include <cuda_runtime.h>
#include <cuda_bf16.h>
#include <math.h>
#include <stdint.h>

#define NB      2048
#define EXPR    8000
#define H1      1024
#define H2      100
#define M_TOT   4096
#define DD      78
#define DN      200
#define NPG     64
#define EPG     128
#define NG      2048
#define NT_ALL  131072
#define ET_TOT  262144
#define KTOP    52

__device__ float g_h1[M_TOT * H1];
__device__ float g_dx[NG * 400];
__device__ __nv_bfloat16 g_Ahi[(size_t)M_TOT * EXPR];
__device__ __nv_bfloat16 g_Alo[(size_t)M_TOT * EXPR];
__device__ __nv_bfloat16 g_Bhi[(size_t)H1 * EXPR];
__device__ __nv_bfloat16 g_Blo[(size_t)H1 * EXPR];
__device__ __nv_bfloat16 g_dxhi[(size_t)NT_ALL * 80];
__device__ __nv_bfloat16 g_dxlo[(size_t)NT_ALL * 80];
__device__ __nv_bfloat16 g_wxhi[400 * 80];
__device__ __nv_bfloat16 g_wxlo[400 * 80];
__device__ float g_xl[(size_t)NT_ALL * 400];
__device__ float g_wa2[DN], g_wb2[DN];
__device__ float g_tw[DN];
__device__ float g_winv;

__device__ __forceinline__ unsigned smem_u32(const void* p) {
    unsigned a;
    asm("{ .reg .u64 t; cvta.to.shared.u64 t, %1; cvt.u32.u64 %0, t; }" : "=r"(a) : "l"(p));
    return a;
}
__device__ __forceinline__ void cpa16(unsigned s, const void* g) {
    asm volatile("cp.async.cg.shared.global [%0], [%1], 16;" :: "r"(s), "l"(g));
}
__device__ __forceinline__ void cpa_commit() { asm volatile("cp.async.commit_group;" ::: "memory"); }
template<int N> __device__ __forceinline__ void cpa_wait() {
    asm volatile("cp.async.wait_group %0;" :: "n"(N) : "memory");
}
__device__ __forceinline__ void ldmx4(unsigned* r, unsigned addr) {
    asm volatile("ldmatrix.sync.aligned.m8n8.x4.shared.b16 {%0,%1,%2,%3}, [%4];"
        : "=r"(r[0]), "=r"(r[1]), "=r"(r[2]), "=r"(r[3]) : "r"(addr));
}
__device__ __forceinline__ void mma16816(float* d, const unsigned* a, const unsigned* b) {
    asm volatile("mma.sync.aligned.m16n8k16.row.col.f32.bf16.bf16.f32 "
        "{%0,%1,%2,%3}, {%4,%5,%6,%7}, {%8,%9}, {%0,%1,%2,%3};"
        : "+f"(d[0]), "+f"(d[1]), "+f"(d[2]), "+f"(d[3])
        : "r"(a[0]), "r"(a[1]), "r"(a[2]), "r"(a[3]), "r"(b[0]), "r"(b[1]));
}

__device__ __forceinline__ void split4(__nv_bfloat16* hi, __nv_bfloat16* lo, float4 v) {
    __nv_bfloat16 h0=__float2bfloat16_rn(v.x), h1=__float2bfloat16_rn(v.y);
    __nv_bfloat16 h2=__float2bfloat16_rn(v.z), h3=__float2bfloat16_rn(v.w);
    union { __nv_bfloat16 b[4]; uint2 u; } H, L;
    H.b[0]=h0; H.b[1]=h1; H.b[2]=h2; H.b[3]=h3;
    L.b[0]=__float2bfloat16_rn(v.x-__bfloat162float(h0));
    L.b[1]=__float2bfloat16_rn(v.y-__bfloat162float(h1));
    L.b[2]=__float2bfloat16_rn(v.z-__bfloat162float(h2));
    L.b[3]=__float2bfloat16_rn(v.w-__bfloat162float(h3));
    *(uint2*)hi = H.u;  *(uint2*)lo = L.u;
}
__device__ __forceinline__ void split2(__nv_bfloat16* hi, __nv_bfloat16* lo, float a, float b) {
    __nv_bfloat16 h0=__float2bfloat16_rn(a), h1=__float2bfloat16_rn(b);
    union { __nv_bfloat16 v[2]; unsigned u; } H, L;
    H.v[0]=h0; H.v[1]=h1;
    L.v[0]=__float2bfloat16_rn(a-__bfloat162float(h0));
    L.v[1]=__float2bfloat16_rn(b-__bfloat162float(h1));
    *(unsigned*)hi = H.u;  *(unsigned*)lo = L.u;
}

__global__ __launch_bounds__(256) void prep_kernel(
    const float* __restrict__ x1, const float* __restrict__ x2,
    const float* __restrict__ W1,
    const float* __restrict__ bn0_s, const float* __restrict__ bn0_t)
{
    const long NA = (long)M_TOT * 2000;
    const long NT4 = NA + (long)H1 * 2000;
    long i = (long)blockIdx.x * 256 + threadIdx.x;
    if (i >= NT4) return;
    if (i < NA) {
        int row = (int)(i / 2000), k4 = (int)(i % 2000);
        const float* src = (row < NB) ? (x1 + (size_t)row * EXPR) : (x2 + (size_t)(row - NB) * EXPR);
        float4 v = *(const float4*)(src + k4 * 4);
        float4 s = *(const float4*)(bn0_s + k4 * 4);
        float4 t = *(const float4*)(bn0_t + k4 * 4);
        v.x = v.x*s.x + t.x;  v.y = v.y*s.y + t.y;  v.z = v.z*s.z + t.z;  v.w = v.w*s.w + t.w;
        size_t eo = (size_t)row * EXPR + (size_t)k4 * 4;
        split4(g_Ahi + eo, g_Alo + eo, v);
    } else {
        long j = i - NA;
        int row = (int)(j / 2000), k4 = (int)(j % 2000);
        float4 v = *(const float4*)(W1 + (size_t)row * EXPR + k4 * 4);
        size_t eo = (size_t)row * EXPR + (size_t)k4 * 4;
        split4(g_Bhi + eo, g_Blo + eo, v);
    }
}

__global__ __launch_bounds__(256) void prep2_kernel(const float* __restrict__ dx)
{
    long i = (long)blockIdx.x * 256 + threadIdx.x;
    if (i >= (long)NT_ALL * 40) return;
    int n = (int)(i / 40), kp = (int)(i % 40);
    int k0 = 2 * kp;
    float a = (k0     < DD) ? dx[(size_t)n * DD + k0]     : 0.f;
    float b = (k0 + 1 < DD) ? dx[(size_t)n * DD + k0 + 1] : 0.f;
    size_t eo = (size_t)n * 80 + k0;
    split2(g_dxhi + eo, g_dxlo + eo, a, b);
}

__global__ __launch_bounds__(256) void wprep_kernel(
    const float* __restrict__ Wrel, const float* __restrict__ Wroot,
    const float* __restrict__ brel,
    const float* __restrict__ bnd_s, const float* __restrict__ bnd_t,
    const float* __restrict__ topk_w)
{
    int i = blockIdx.x * 256 + threadIdx.x;
    if (i < 400 * 40) {
        int n = i / 40, kp = i % 40;
        int k0 = 2 * kp;
        float a = 0.f, b = 0.f;
        if (k0 < DD)     a = (n < DN) ? Wrel[n*DD + k0]     : Wroot[(n-DN)*DD + k0];
        if (k0 + 1 < DD) b = (n < DN) ? Wrel[n*DD + k0 + 1] : Wroot[(n-DN)*DD + k0 + 1];
        split2(g_wxhi + n*80 + k0, g_wxlo + n*80 + k0, a, b);
    }
    if (i < DN) {
        float al = bnd_s[i];
        g_wa2[i] = al;
        g_wb2[i] = brel[i]*al + bnd_t[i];
        g_tw[i]  = topk_w[i];
    }
    if (i == 0) {
        float s = 0.f;
        for (int c = 0; c < DN; ++c) s += topk_w[c]*topk_w[c];
        g_winv = rsqrtf(s);
    }
}

// ---------------- GEMM1: fixed 3-stage pipeline (1 barrier/chunk, early loads) ----------------
#define KC    32
#define NCH   250
#define AST   40
#define OFF_AH 0
#define OFF_AL 20480
#define OFF_BH 40960
#define OFF_BL 51200
#define STG    61440
#define G1_DSMEM (3 * STG)

__global__ void __launch_bounds__(512, 1) gemm1_mma(
    const float* __restrict__ b1, const float* __restrict__ bn1_s,
    const float* __restrict__ bn1_t)
{
    extern __shared__ char dynsm[];
    __shared__ float s_alpha[128], s_beta[128];
    const unsigned sb = smem_u32(dynsm);
    const int tid = threadIdx.x;
    const int warp = tid >> 5, lane = tid & 31;
    const int m0 = blockIdx.y * 256;
    const int n0 = blockIdx.x * 128;
    const int wm = (warp >> 2) * 64;
    const int wn = (warp & 3) * 32;

    if (tid < 128) {
        float al = bn1_s[n0 + tid];
        s_alpha[tid] = al;
        s_beta[tid]  = b1[n0 + tid] * al + bn1_t[n0 + tid];
    }

    auto load_chunk = [&](int c, int s) {
        const unsigned st = sb + s * STG;
        const long k0 = (long)c * KC;
        #pragma unroll
        for (int t = 0; t < 2; ++t) {
            int i = tid + (t << 9);
            int r = i >> 2, q = i & 3;
            unsigned off = r * 80 + q * 16;
            size_t go = (size_t)(m0 + r) * EXPR + k0 + q * 8;
            cpa16(st + OFF_AH + off, g_Ahi + go);
            cpa16(st + OFF_AL + off, g_Alo + go);
        }
        {
            int r = tid >> 2, q = tid & 3;
            unsigned off = r * 80 + q * 16;
            size_t go = (size_t)(n0 + r) * EXPR + k0 + q * 8;
            cpa16(st + OFF_BH + off, g_Bhi + go);
            cpa16(st + OFF_BL + off, g_Blo + go);
        }
        cpa_commit();
    };

    float acc[4][4][4];
    #pragma unroll
    for (int i = 0; i < 4; ++i)
        #pragma unroll
        for (int j = 0; j < 4; ++j)
            #pragma unroll
            for (int q = 0; q < 4; ++q) acc[i][j][q] = 0.f;

    load_chunk(0, 0);
    load_chunk(1, 1);

    const int arow = lane & 15;
    const int acol = (lane >> 4) << 3;

    for (int c = 0; c < NCH; ++c) {
        const int s = c - (c / 3) * 3;
        if (c + 1 < NCH) cpa_wait<1>(); else cpa_wait<0>();
        __syncthreads();
        // issue next loads immediately: stage (c+2)%3 was last read in chunk c-1,
        // fenced by the barrier above.
        if (c + 2 < NCH) {
            int s2 = (c + 2) - ((c + 2) / 3) * 3;
            load_chunk(c + 2, s2);
        }

        const unsigned aH = sb + s * STG;
        const unsigned aL = aH + OFF_AL;
        const unsigned bH = aH + OFF_BH;
        const unsigned bL = aH + OFF_BL;

        #pragma unroll
        for (int ks = 0; ks < KC; ks += 16) {
            unsigned ah[16], bh[8], u[16];
            #pragma unroll
            for (int i = 0; i < 4; ++i)
                ldmx4(&ah[4*i], aH + ((wm + i*16 + arow) * AST + ks + acol) * 2);
            #pragma unroll
            for (int j2 = 0; j2 < 2; ++j2) {
                unsigned tr[4];
                ldmx4(tr, bH + ((wn + j2*16 + arow) * AST + ks + acol) * 2);
                bh[4*j2 + 0] = tr[0];  bh[4*j2 + 1] = tr[2];
                bh[4*j2 + 2] = tr[1];  bh[4*j2 + 3] = tr[3];
            }
            #pragma unroll
            for (int i = 0; i < 4; ++i)
                #pragma unroll
                for (int j = 0; j < 4; ++j)
                    mma16816(acc[i][j], &ah[4*i], &bh[2*j]);
            #pragma unroll
            for (int j2 = 0; j2 < 2; ++j2) {
                unsigned tr[4];
                ldmx4(tr, bL + ((wn + j2*16 + arow) * AST + ks + acol) * 2);
                u[4*j2 + 0] = tr[0];  u[4*j2 + 1] = tr[2];
                u[4*j2 + 2] = tr[1];  u[4*j2 + 3] = tr[3];
            }
            #pragma unroll
            for (int i = 0; i < 4; ++i)
                #pragma unroll
                for (int j = 0; j < 4; ++j)
                    mma16816(acc[i][j], &ah[4*i], &u[2*j]);
            #pragma unroll
            for (int i = 0; i < 4; ++i)
                ldmx4(&u[4*i], aL + ((wm + i*16 + arow) * AST + ks + acol) * 2);
            #pragma unroll
            for (int i = 0; i < 4; ++i)
                #pragma unroll
                for (int j = 0; j < 4; ++j)
                    mma16816(acc[i][j], &u[4*i], &bh[2*j]);
        }
    }

    const int er = lane >> 2, ec = (lane & 3) * 2;
    #pragma unroll
    for (int i = 0; i < 4; ++i) {
        #pragma unroll
        for (int j = 0; j < 4; ++j) {
            int nl = wn + j*8 + ec;
            float a0 = s_alpha[nl], a1 = s_alpha[nl+1];
            float e0 = s_beta[nl],  e1 = s_beta[nl+1];
            int mg0 = m0 + wm + i*16 + er;
            float2 v0, v1;
            v0.x = fmaxf(acc[i][j][0]*a0 + e0, 0.f);
            v0.y = fmaxf(acc[i][j][1]*a1 + e1, 0.f);
            v1.x = fmaxf(acc[i][j][2]*a0 + e0, 0.f);
            v1.y = fmaxf(acc[i][j][3]*a1 + e1, 0.f);
            *(float2*)&g_h1[(size_t)mg0 * H1 + n0 + nl]       = v0;
            *(float2*)&g_h1[(size_t)(mg0 + 8) * H1 + n0 + nl] = v1;
        }
    }
}

// ---------------- XL GEMM (unchanged) ----------------
#define XAST 88
#define XOFF_AH 0
#define XOFF_AL 22528
#define XOFF_BH 45056
#define XOFF_BL 59136
#define XL_DSMEM 73216

__global__ void __launch_bounds__(256, 1) xl_gemm()
{
    extern __shared__ char dynsm[];
    const unsigned sb = smem_u32(dynsm);
    const int tid = threadIdx.x;
    const int warp = tid >> 5, lane = tid & 31;
    const int m0 = blockIdx.y * 128;
    const int n0 = blockIdx.x * 80;

    #pragma unroll
    for (int t = 0; t < 5; ++t) {
        int i = tid + t * 256;
        int r = i / 10, q = i - r * 10;
        unsigned off = r * 176 + q * 16;
        size_t go = (size_t)(m0 + r) * 80 + q * 8;
        cpa16(sb + XOFF_AH + off, g_dxhi + go);
        cpa16(sb + XOFF_AL + off, g_dxlo + go);
    }
    #pragma unroll
    for (int t = 0; t < 4; ++t) {
        int i = tid + t * 256;
        if (i < 800) {
            int r = i / 10, q = i - r * 10;
            unsigned off = r * 176 + q * 16;
            size_t go = (size_t)(n0 + r) * 80 + q * 8;
            cpa16(sb + XOFF_BH + off, g_wxhi + go);
            cpa16(sb + XOFF_BL + off, g_wxlo + go);
        }
    }
    cpa_commit();
    cpa_wait<0>();
    __syncthreads();

    float acc[10][4];
    #pragma unroll
    for (int j = 0; j < 10; ++j)
        #pragma unroll
        for (int q = 0; q < 4; ++q) acc[j][q] = 0.f;

    const int arow = lane & 15;
    const int acol = (lane >> 4) << 3;
    const unsigned aH = sb + XOFF_AH, aL = sb + XOFF_AL;
    const unsigned bH = sb + XOFF_BH, bL = sb + XOFF_BL;

    #pragma unroll
    for (int ks = 0; ks < 80; ks += 16) {
        unsigned ah[4], al[4], bh[20], bl[20];
        ldmx4(ah, aH + ((warp*16 + arow) * XAST + ks + acol) * 2);
        ldmx4(al, aL + ((warp*16 + arow) * XAST + ks + acol) * 2);
        #pragma unroll
        for (int jb = 0; jb < 5; ++jb) {
            unsigned tr[4];
            ldmx4(tr, bH + ((jb*16 + arow) * XAST + ks + acol) * 2);
            bh[4*jb+0] = tr[0];  bh[4*jb+1] = tr[2];
            bh[4*jb+2] = tr[1];  bh[4*jb+3] = tr[3];
            ldmx4(tr, bL + ((jb*16 + arow) * XAST + ks + acol) * 2);
            bl[4*jb+0] = tr[0];  bl[4*jb+1] = tr[2];
            bl[4*jb+2] = tr[1];  bl[4*jb+3] = tr[3];
        }
        #pragma unroll
        for (int j = 0; j < 10; ++j) {
            mma16816(acc[j], ah, &bh[2*j]);
            mma16816(acc[j], ah, &bl[2*j]);
            mma16816(acc[j], al, &bh[2*j]);
        }
    }

    const int er = lane >> 2, ec = (lane & 3) * 2;
    const int grow = m0 + warp*16 + er;
    #pragma unroll
    for (int j = 0; j < 10; ++j) {
        int gc = n0 + 8*j + ec;
        *(float2*)&g_xl[(size_t)grow * 400 + gc]       = make_float2(acc[j][0], acc[j][1]);
        *(float2*)&g_xl[(size_t)(grow + 8) * 400 + gc] = make_float2(acc[j][2], acc[j][3]);
    }
}

// ---------------- GEMM2 v2: M-tile 16, 256 CTAs ----------------
#define G2_BK 16
__global__ __launch_bounds__(256) void gemm2_kernel(
    const float* __restrict__ W2, const float* __restrict__ b2,
    const float* __restrict__ bn2_s, const float* __restrict__ bn2_t,
    float* __restrict__ out)
{
    __shared__ float As[16 * G2_BK];
    __shared__ float Bs[112 * 17];
    const int tid = threadIdx.x;
    const int tx = tid & 15, ty = tid >> 4;   // ty = row 0..15
    const int m0 = blockIdx.x * 16;
    const float* pA = g_h1 + (size_t)(m0 + ty) * H1 + tx;

    float aPre;  float bPre[7];
    aPre = *pA;
    #pragma unroll
    for (int it = 0; it < 7; ++it) {
        int i = tid + it*256;
        if (i < 1600) bPre[it] = W2[(size_t)(i/16) * H1 + (i & 15)];
    }
    As[ty*G2_BK + tx] = aPre;
    #pragma unroll
    for (int it = 0; it < 7; ++it) {
        int i = tid + it*256;
        if (i < 1600) Bs[(i/16)*17 + (i & 15)] = bPre[it];
    }
    __syncthreads();

    float acc[7];
    #pragma unroll
    for (int j = 0; j < 7; ++j) acc[j] = 0.f;

    const int NT_K = H1 / G2_BK;   // 64
    for (int kt = 0; kt < NT_K; ++kt) {
        const bool has = (kt + 1) < NT_K;
        const int k0n = (kt + 1) * G2_BK;
        if (has) {
            aPre = *(pA + k0n);
            #pragma unroll
            for (int it = 0; it < 7; ++it) {
                int i = tid + it*256;
                if (i < 1600) bPre[it] = W2[(size_t)(i/16) * H1 + k0n + (i & 15)];
            }
        }
        #pragma unroll
        for (int kk = 0; kk < G2_BK; ++kk) {
            float a0 = As[ty*G2_BK + kk];
            #pragma unroll
            for (int j = 0; j < 7; ++j) {
                acc[j] += a0 * Bs[(tx + 16*j)*17 + kk];
            }
        }
        __syncthreads();
        if (has) {
            As[ty*G2_BK + tx] = aPre;
            #pragma unroll
            for (int it = 0; it < 7; ++it) {
                int i = tid + it*256;
                if (i < 1600) Bs[(i/16)*17 + (i & 15)] = bPre[it];
            }
            __syncthreads();
        }
    }

    const int m = m0 + ty;
    #pragma unroll
    for (int j = 0; j < 7; ++j) {
        int n = tx + 16*j;
        if (n >= H2) continue;
        float al = bn2_s[n];
        float be = b2[n]*al + bn2_t[n];
        float v = fmaxf(acc[j]*al + be, 0.f);
        size_t o = (m < NB) ? ((size_t)m*H2 + n) : ((size_t)NB*H2 + (size_t)(m - NB)*H2 + n);
        out[o] = v;
    }
}

// ---------------- Drug encoder v5 (unchanged) ----------------
#define VXL 201
#define VH  209
#define OXL 0
#define OH  12864
#define OWA 26240
#define OWB 26440
#define OTW 26640
#define OSC 26840
#define OFL 26904
#define OES 26968
#define OED 27096
#define OCN 27224
#define OST 27288
#define OCU 27353
#define OLS 27417
#define DTOT 27545
#define DRUG_SMEM_BYTES (DTOT * 4)
#define DRUG_GRID 296

__global__ __launch_bounds__(512, 2) void drug_kernel(const int* __restrict__ edge_index)
{
    extern __shared__ float sm[];
    float* xl    = sm + OXL;
    float* hsh   = sm + OH;
    float* wa    = sm + OWA;
    float* wb    = sm + OWB;
    float* tw    = sm + OTW;
    float* score = sm + OSC;
    int*   flag  = (int*)(sm + OFL);
    int*   es    = (int*)(sm + OES);
    int*   ed    = (int*)(sm + OED);
    int*   cnt   = (int*)(sm + OCN);
    int*   start = (int*)(sm + OST);
    int*   cur   = (int*)(sm + OCU);
    int*   list  = (int*)(sm + OLS);

    const int tid = threadIdx.x;
    const int g0 = (int)(((long)blockIdx.x * NG) / DRUG_GRID);
    const int g1 = (int)(((long)(blockIdx.x + 1) * NG) / DRUG_GRID);
    const float winv = g_winv;

    if (tid < DN) { wa[tid] = g_wa2[tid]; wb[tid] = g_wb2[tid]; tw[tid] = g_tw[tid]; }
    __syncthreads();

    const int ni   = tid >> 3;
    const int part = tid & 7;
    const int c0   = part * 25;

    for (int g = g0; g < g1; ++g) {
        const int base = g * NPG;
        for (int i = tid; i < NPG * DN; i += 512) {
            int nn = i / DN, c = i - nn * DN;
            xl[nn * VXL + c] = g_xl[(size_t)(base + nn) * 400 + c];
        }
        if (tid < EPG) {
            es[tid] = edge_index[g*EPG + tid] - base;
            ed[tid] = edge_index[ET_TOT + g*EPG + tid] - base;
        }
        if (tid < NPG) cnt[tid] = 0;
        __syncthreads();
        if (tid < EPG) atomicAdd(&cnt[ed[tid]], 1);
        __syncthreads();
        if (tid == 0) {
            int run = 0;
            for (int nn = 0; nn < NPG; ++nn) { start[nn] = run; run += cnt[nn]; }
            start[NPG] = run;
        }
        __syncthreads();
        if (tid < NPG) cur[tid] = start[tid];
        __syncthreads();
        if (tid < EPG) {
            int pos = atomicAdd(&cur[ed[tid]], 1);
            list[pos] = es[tid];
        }
        __syncthreads();

        {
            float acc[25];
            const float* xr = g_xl + (size_t)(base + ni) * 400 + DN + c0;
            #pragma unroll
            for (int c = 0; c < 25; ++c) acc[c] = xr[c];
            const int b0 = start[ni], b1 = start[ni + 1];
            for (int e = b0; e < b1; ++e) {
                const float* xp = xl + list[e] * VXL + c0;
                #pragma unroll
                for (int c = 0; c < 25; ++c) acc[c] += xp[c];
            }
            #pragma unroll
            for (int c = 0; c < 25; ++c) {
                int cc = c0 + c;
                hsh[ni * VH + cc] = fmaxf(acc[c] * wa[cc] + wb[cc], 0.f);
            }
        }
        __syncthreads();

        {
            float s = 0.f;
            const float* hp  = &hsh[ni * VH + c0];
            const float* twp = &tw[c0];
            #pragma unroll
            for (int c = 0; c < 25; ++c) s += hp[c] * twp[c];
            s += __shfl_xor_sync(0xffffffffu, s, 1);
            s += __shfl_xor_sync(0xffffffffu, s, 2);
            s += __shfl_xor_sync(0xffffffffu, s, 4);
            if (part == 0) score[ni] = tanhf(s * winv);
        }
        __syncthreads();
        if (tid < NPG) {
            float sn = score[tid];
            int r = 0;
            for (int m2 = 0; m2 < NPG; ++m2) {
                float sv = score[m2];
                r += (sv > sn) || (sv == sn && m2 < tid);
            }
            flag[tid] = (r < KTOP) ? 1 : 0;
        }
        __syncthreads();
        if (tid < DN) {
            const int c = tid;
            float mx = -1e30f, sum = 0.f, mxs = -1e30f, sums = 0.f;
            for (int n2 = 0; n2 < NPG; ++n2) {
                float v = hsh[n2 * VH + c];
                mx = fmaxf(mx, v); sum += v;
                if (flag[n2]) {
                    float w = v * score[n2];
                    mxs = fmaxf(mxs, w); sums += w;
                }
            }
            g_dx[(size_t)g*400 + c]      = fmaxf(mx + 3.f*mxs, 0.f);
            g_dx[(size_t)g*400 + DN + c] = fmaxf(sum*(1.f/NPG) + 3.f*(sums*(1.f/KTOP)), 0.f);
        }
        __syncthreads();
    }
}

__global__ __launch_bounds__(256) void resp_kernel(
    const float* __restrict__ Wp, const float* __restrict__ bp,
    float* __restrict__ out)
{
    const int row = blockIdx.x * 8 + (threadIdx.x >> 5);
    const int lane = threadIdx.x & 31;
    float s = 0.f;
    for (int i = lane; i < 500; i += 32) {
        float z = (i < H2) ? out[(size_t)row*H2 + i] : g_dx[(size_t)row*400 + (i - H2)];
        s += z * Wp[i];
    }
    #pragma unroll
    for (int o = 16; o; o >>= 1) s += __shfl_down_sync(0xffffffffu, s, o);
    if (lane == 0) out[(size_t)2*NB*H2 + row] = s + bp[0];
}

extern "C" void kernel_launch(void* const* d_in, const int* in_sizes, int n_in,
                              void* d_out, int out_size)
{
    const float* x1     = (const float*)d_in[0];
    const float* x2     = (const float*)d_in[1];
    const int*   eidx   = (const int*)d_in[4];
    const float* drug_x = (const float*)d_in[5];
    const float* bn0_s  = (const float*)d_in[6];
    const float* bn0_t  = (const float*)d_in[7];
    const float* W1     = (const float*)d_in[8];
    const float* b1     = (const float*)d_in[9];
    const float* bn1_s  = (const float*)d_in[10];
    const float* bn1_t  = (const float*)d_in[11];
    const float* W2     = (const float*)d_in[12];
    const float* b2     = (const float*)d_in[13];
    const float* bn2_s  = (const float*)d_in[14];
    const float* bn2_t  = (const float*)d_in[15];
    const float* Wrel   = (const float*)d_in[16];
    const float* brel   = (const float*)d_in[17];
    const float* Wroot  = (const float*)d_in[18];
    const float* bnd_s  = (const float*)d_in[19];
    const float* bnd_t  = (const float*)d_in[20];
    const float* topk_w = (const float*)d_in[21];
    const float* Wp     = (const float*)d_in[22];
    const float* bp     = (const float*)d_in[23];
    float* out = (float*)d_out;

    cudaFuncSetAttribute(drug_kernel, cudaFuncAttributeMaxDynamicSharedMemorySize, DRUG_SMEM_BYTES);
    cudaFuncSetAttribute(gemm1_mma, cudaFuncAttributeMaxDynamicSharedMemorySize, G1_DSMEM);
    cudaFuncSetAttribute(xl_gemm, cudaFuncAttributeMaxDynamicSharedMemorySize, XL_DSMEM);

    wprep_kernel<<<63, 256>>>(Wrel, Wroot, brel, bnd_s, bnd_t, topk_w);
    const long NT4 = (long)M_TOT * 2000 + (long)H1 * 2000;
    prep_kernel<<<(int)((NT4 + 255) / 256), 256>>>(x1, x2, W1, bn0_s, bn0_t);
    prep2_kernel<<<20480, 256>>>(drug_x);
    gemm1_mma<<<dim3(8, 16), 512, G1_DSMEM>>>(b1, bn1_s, bn1_t);
    xl_gemm<<<dim3(5, 1024), 256, XL_DSMEM>>>();
    gemm2_kernel<<<M_TOT / 16, 256>>>(W2, b2, bn2_s, bn2_t, out);
    drug_kernel<<<DRUG_GRID, 512, DRUG_SMEM_BYTES>>>(eidx);
    resp_kernel<<<NG / 8, 256>>>(Wp, bp, out);
}

// round 9
// speedup vs baseline: 1.2002x; 1.2002x over previous
#include <cuda_runtime.h>
#include <cuda_bf16.h>
#include <cuda_fp16.h>
#include <math.h>
#include <stdint.h>

#define NB      2048
#define EXPR    8000
#define H1      1024
#define H2      100
#define M_TOT   4096
#define DD      78
#define DN      200
#define NPG     64
#define EPG     128
#define NG      2048
#define NT_ALL  131072
#define ET_TOT  262144
#define KTOP    52

__device__ float g_h1[M_TOT * H1];
__device__ float g_dx[NG * 400];
__device__ __half g_Ahi[(size_t)M_TOT * EXPR];
__device__ __half g_Alo[(size_t)M_TOT * EXPR];
__device__ __half g_Bh[(size_t)H1 * EXPR];
__device__ __nv_bfloat16 g_dxhi[(size_t)NT_ALL * 80];
__device__ __nv_bfloat16 g_dxlo[(size_t)NT_ALL * 80];
__device__ __nv_bfloat16 g_wxhi[400 * 80];
__device__ __nv_bfloat16 g_wxlo[400 * 80];
__device__ float g_xl[(size_t)NT_ALL * 400];
__device__ float g_wa2[DN], g_wb2[DN];
__device__ float g_tw[DN];
__device__ float g_winv;

__device__ __forceinline__ unsigned smem_u32(const void* p) {
    unsigned a;
    asm("{ .reg .u64 t; cvta.to.shared.u64 t, %1; cvt.u32.u64 %0, t; }" : "=r"(a) : "l"(p));
    return a;
}
__device__ __forceinline__ void cpa16(unsigned s, const void* g) {
    asm volatile("cp.async.cg.shared.global [%0], [%1], 16;" :: "r"(s), "l"(g));
}
__device__ __forceinline__ void cpa_commit() { asm volatile("cp.async.commit_group;" ::: "memory"); }
template<int N> __device__ __forceinline__ void cpa_wait() {
    asm volatile("cp.async.wait_group %0;" :: "n"(N) : "memory");
}
__device__ __forceinline__ void ldmx4(unsigned* r, unsigned addr) {
    asm volatile("ldmatrix.sync.aligned.m8n8.x4.shared.b16 {%0,%1,%2,%3}, [%4];"
        : "=r"(r[0]), "=r"(r[1]), "=r"(r[2]), "=r"(r[3]) : "r"(addr));
}
__device__ __forceinline__ void mma16816bf(float* d, const unsigned* a, const unsigned* b) {
    asm volatile("mma.sync.aligned.m16n8k16.row.col.f32.bf16.bf16.f32 "
        "{%0,%1,%2,%3}, {%4,%5,%6,%7}, {%8,%9}, {%0,%1,%2,%3};"
        : "+f"(d[0]), "+f"(d[1]), "+f"(d[2]), "+f"(d[3])
        : "r"(a[0]), "r"(a[1]), "r"(a[2]), "r"(a[3]), "r"(b[0]), "r"(b[1]));
}
__device__ __forceinline__ void mma16816h(float* d, const unsigned* a, const unsigned* b) {
    asm volatile("mma.sync.aligned.m16n8k16.row.col.f32.f16.f16.f32 "
        "{%0,%1,%2,%3}, {%4,%5,%6,%7}, {%8,%9}, {%0,%1,%2,%3};"
        : "+f"(d[0]), "+f"(d[1]), "+f"(d[2]), "+f"(d[3])
        : "r"(a[0]), "r"(a[1]), "r"(a[2]), "r"(a[3]), "r"(b[0]), "r"(b[1]));
}

// fp16 hi/lo split (A operand: exact to ~2^-22)
__device__ __forceinline__ void split4h(__half* hi, __half* lo, float4 v) {
    __half h0=__float2half_rn(v.x), h1=__float2half_rn(v.y);
    __half h2=__float2half_rn(v.z), h3=__float2half_rn(v.w);
    union { __half b[4]; uint2 u; } H, L;
    H.b[0]=h0; H.b[1]=h1; H.b[2]=h2; H.b[3]=h3;
    L.b[0]=__float2half_rn(v.x-__half2float(h0));
    L.b[1]=__float2half_rn(v.y-__half2float(h1));
    L.b[2]=__float2half_rn(v.z-__half2float(h2));
    L.b[3]=__float2half_rn(v.w-__half2float(h3));
    *(uint2*)hi = H.u;  *(uint2*)lo = L.u;
}
__device__ __forceinline__ void conv4h(__half* dst, float4 v) {
    union { __half b[4]; uint2 u; } H;
    H.b[0]=__float2half_rn(v.x); H.b[1]=__float2half_rn(v.y);
    H.b[2]=__float2half_rn(v.z); H.b[3]=__float2half_rn(v.w);
    *(uint2*)dst = H.u;
}
// bf16 split (drug path, unchanged)
__device__ __forceinline__ void split2(__nv_bfloat16* hi, __nv_bfloat16* lo, float a, float b) {
    __nv_bfloat16 h0=__float2bfloat16_rn(a), h1=__float2bfloat16_rn(b);
    union { __nv_bfloat16 v[2]; unsigned u; } H, L;
    H.v[0]=h0; H.v[1]=h1;
    L.v[0]=__float2bfloat16_rn(a-__bfloat162float(h0));
    L.v[1]=__float2bfloat16_rn(b-__bfloat162float(h1));
    *(unsigned*)hi = H.u;  *(unsigned*)lo = L.u;
}

__global__ __launch_bounds__(256) void prep_kernel(
    const float* __restrict__ x1, const float* __restrict__ x2,
    const float* __restrict__ W1,
    const float* __restrict__ bn0_s, const float* __restrict__ bn0_t)
{
    const long NA = (long)M_TOT * 2000;
    const long NT4 = NA + (long)H1 * 2000;
    long i = (long)blockIdx.x * 256 + threadIdx.x;
    if (i >= NT4) return;
    if (i < NA) {
        int row = (int)(i / 2000), k4 = (int)(i % 2000);
        const float* src = (row < NB) ? (x1 + (size_t)row * EXPR) : (x2 + (size_t)(row - NB) * EXPR);
        float4 v = *(const float4*)(src + k4 * 4);
        float4 s = *(const float4*)(bn0_s + k4 * 4);
        float4 t = *(const float4*)(bn0_t + k4 * 4);
        v.x = v.x*s.x + t.x;  v.y = v.y*s.y + t.y;  v.z = v.z*s.z + t.z;  v.w = v.w*s.w + t.w;
        size_t eo = (size_t)row * EXPR + (size_t)k4 * 4;
        split4h(g_Ahi + eo, g_Alo + eo, v);
    } else {
        long j = i - NA;
        int row = (int)(j / 2000), k4 = (int)(j % 2000);
        float4 v = *(const float4*)(W1 + (size_t)row * EXPR + k4 * 4);
        conv4h(g_Bh + (size_t)row * EXPR + (size_t)k4 * 4, v);
    }
}

__global__ __launch_bounds__(256) void prep2_kernel(const float* __restrict__ dx)
{
    long i = (long)blockIdx.x * 256 + threadIdx.x;
    if (i >= (long)NT_ALL * 40) return;
    int n = (int)(i / 40), kp = (int)(i % 40);
    int k0 = 2 * kp;
    float a = (k0     < DD) ? dx[(size_t)n * DD + k0]     : 0.f;
    float b = (k0 + 1 < DD) ? dx[(size_t)n * DD + k0 + 1] : 0.f;
    size_t eo = (size_t)n * 80 + k0;
    split2(g_dxhi + eo, g_dxlo + eo, a, b);
}

__global__ __launch_bounds__(256) void wprep_kernel(
    const float* __restrict__ Wrel, const float* __restrict__ Wroot,
    const float* __restrict__ brel,
    const float* __restrict__ bnd_s, const float* __restrict__ bnd_t,
    const float* __restrict__ topk_w)
{
    int i = blockIdx.x * 256 + threadIdx.x;
    if (i < 400 * 40) {
        int n = i / 40, kp = i % 40;
        int k0 = 2 * kp;
        float a = 0.f, b = 0.f;
        if (k0 < DD)     a = (n < DN) ? Wrel[n*DD + k0]     : Wroot[(n-DN)*DD + k0];
        if (k0 + 1 < DD) b = (n < DN) ? Wrel[n*DD + k0 + 1] : Wroot[(n-DN)*DD + k0 + 1];
        split2(g_wxhi + n*80 + k0, g_wxlo + n*80 + k0, a, b);
    }
    if (i < DN) {
        float al = bnd_s[i];
        g_wa2[i] = al;
        g_wb2[i] = brel[i]*al + bnd_t[i];
        g_tw[i]  = topk_w[i];
    }
    if (i == 0) {
        float s = 0.f;
        for (int c = 0; c < DN; ++c) s += topk_w[c]*topk_w[c];
        g_winv = rsqrtf(s);
    }
}

// ---------------- GEMM1: fp16 2-pass split (ah*bh + al*bh) ----------------
#define KC    32
#define NCH   250
#define AST   40
#define OFF_AH 0
#define OFF_AL 20480
#define OFF_B  40960
#define STG    51200
#define G1_DSMEM (3 * STG)

__global__ void __launch_bounds__(512, 1) gemm1_mma(
    const float* __restrict__ b1, const float* __restrict__ bn1_s,
    const float* __restrict__ bn1_t)
{
    extern __shared__ char dynsm[];
    __shared__ float s_alpha[128], s_beta[128];
    const unsigned sb = smem_u32(dynsm);
    const int tid = threadIdx.x;
    const int warp = tid >> 5, lane = tid & 31;
    const int m0 = blockIdx.y * 256;
    const int n0 = blockIdx.x * 128;
    const int wm = (warp >> 2) * 64;
    const int wn = (warp & 3) * 32;

    if (tid < 128) {
        float al = bn1_s[n0 + tid];
        s_alpha[tid] = al;
        s_beta[tid]  = b1[n0 + tid] * al + bn1_t[n0 + tid];
    }

    auto load_chunk = [&](int c, int s) {
        const unsigned st = sb + s * STG;
        const long k0 = (long)c * KC;
        #pragma unroll
        for (int t = 0; t < 2; ++t) {
            int i = tid + (t << 9);
            int r = i >> 2, q = i & 3;
            unsigned off = r * 80 + q * 16;
            size_t go = (size_t)(m0 + r) * EXPR + k0 + q * 8;
            cpa16(st + OFF_AH + off, g_Ahi + go);
            cpa16(st + OFF_AL + off, g_Alo + go);
        }
        {
            int r = tid >> 2, q = tid & 3;
            unsigned off = r * 80 + q * 16;
            size_t go = (size_t)(n0 + r) * EXPR + k0 + q * 8;
            cpa16(st + OFF_B + off, g_Bh + go);
        }
        cpa_commit();
    };

    float acc[4][4][4];
    #pragma unroll
    for (int i = 0; i < 4; ++i)
        #pragma unroll
        for (int j = 0; j < 4; ++j)
            #pragma unroll
            for (int q = 0; q < 4; ++q) acc[i][j][q] = 0.f;

    load_chunk(0, 0);
    load_chunk(1, 1);

    const int arow = lane & 15;
    const int acol = (lane >> 4) << 3;

    for (int c = 0; c < NCH; ++c) {
        const int s = c - (c / 3) * 3;
        if (c + 1 < NCH) cpa_wait<1>(); else cpa_wait<0>();
        __syncthreads();
        if (c + 2 < NCH) {
            int s2 = (c + 2) - ((c + 2) / 3) * 3;
            load_chunk(c + 2, s2);
        }

        const unsigned aH = sb + s * STG;
        const unsigned aL = aH + (OFF_AL - OFF_AH);
        const unsigned bB = aH + (OFF_B  - OFF_AH);

        #pragma unroll
        for (int ks = 0; ks < KC; ks += 16) {
            unsigned ah[16], al[16], bh[8];
            #pragma unroll
            for (int i = 0; i < 4; ++i)
                ldmx4(&ah[4*i], aH + ((wm + i*16 + arow) * AST + ks + acol) * 2);
            #pragma unroll
            for (int j2 = 0; j2 < 2; ++j2) {
                unsigned tr[4];
                ldmx4(tr, bB + ((wn + j2*16 + arow) * AST + ks + acol) * 2);
                bh[4*j2 + 0] = tr[0];  bh[4*j2 + 1] = tr[2];
                bh[4*j2 + 2] = tr[1];  bh[4*j2 + 3] = tr[3];
            }
            #pragma unroll
            for (int i = 0; i < 4; ++i)
                #pragma unroll
                for (int j = 0; j < 4; ++j)
                    mma16816h(acc[i][j], &ah[4*i], &bh[2*j]);
            #pragma unroll
            for (int i = 0; i < 4; ++i)
                ldmx4(&al[4*i], aL + ((wm + i*16 + arow) * AST + ks + acol) * 2);
            #pragma unroll
            for (int i = 0; i < 4; ++i)
                #pragma unroll
                for (int j = 0; j < 4; ++j)
                    mma16816h(acc[i][j], &al[4*i], &bh[2*j]);
        }
    }

    const int er = lane >> 2, ec = (lane & 3) * 2;
    #pragma unroll
    for (int i = 0; i < 4; ++i) {
        #pragma unroll
        for (int j = 0; j < 4; ++j) {
            int nl = wn + j*8 + ec;
            float a0 = s_alpha[nl], a1 = s_alpha[nl+1];
            float e0 = s_beta[nl],  e1 = s_beta[nl+1];
            int mg0 = m0 + wm + i*16 + er;
            float2 v0, v1;
            v0.x = fmaxf(acc[i][j][0]*a0 + e0, 0.f);
            v0.y = fmaxf(acc[i][j][1]*a1 + e1, 0.f);
            v1.x = fmaxf(acc[i][j][2]*a0 + e0, 0.f);
            v1.y = fmaxf(acc[i][j][3]*a1 + e1, 0.f);
            *(float2*)&g_h1[(size_t)mg0 * H1 + n0 + nl]       = v0;
            *(float2*)&g_h1[(size_t)(mg0 + 8) * H1 + n0 + nl] = v1;
        }
    }
}

// ---------------- XL GEMM (bf16 3-split, unchanged) ----------------
#define XAST 88
#define XOFF_AH 0
#define XOFF_AL 22528
#define XOFF_BH 45056
#define XOFF_BL 59136
#define XL_DSMEM 73216

__global__ void __launch_bounds__(256, 1) xl_gemm()
{
    extern __shared__ char dynsm[];
    const unsigned sb = smem_u32(dynsm);
    const int tid = threadIdx.x;
    const int warp = tid >> 5, lane = tid & 31;
    const int m0 = blockIdx.y * 128;
    const int n0 = blockIdx.x * 80;

    #pragma unroll
    for (int t = 0; t < 5; ++t) {
        int i = tid + t * 256;
        int r = i / 10, q = i - r * 10;
        unsigned off = r * 176 + q * 16;
        size_t go = (size_t)(m0 + r) * 80 + q * 8;
        cpa16(sb + XOFF_AH + off, g_dxhi + go);
        cpa16(sb + XOFF_AL + off, g_dxlo + go);
    }
    #pragma unroll
    for (int t = 0; t < 4; ++t) {
        int i = tid + t * 256;
        if (i < 800) {
            int r = i / 10, q = i - r * 10;
            unsigned off = r * 176 + q * 16;
            size_t go = (size_t)(n0 + r) * 80 + q * 8;
            cpa16(sb + XOFF_BH + off, g_wxhi + go);
            cpa16(sb + XOFF_BL + off, g_wxlo + go);
        }
    }
    cpa_commit();
    cpa_wait<0>();
    __syncthreads();

    float acc[10][4];
    #pragma unroll
    for (int j = 0; j < 10; ++j)
        #pragma unroll
        for (int q = 0; q < 4; ++q) acc[j][q] = 0.f;

    const int arow = lane & 15;
    const int acol = (lane >> 4) << 3;
    const unsigned aH = sb + XOFF_AH, aL = sb + XOFF_AL;
    const unsigned bH = sb + XOFF_BH, bL = sb + XOFF_BL;

    #pragma unroll
    for (int ks = 0; ks < 80; ks += 16) {
        unsigned ah[4], al[4], bh[20], bl[20];
        ldmx4(ah, aH + ((warp*16 + arow) * XAST + ks + acol) * 2);
        ldmx4(al, aL + ((warp*16 + arow) * XAST + ks + acol) * 2);
        #pragma unroll
        for (int jb = 0; jb < 5; ++jb) {
            unsigned tr[4];
            ldmx4(tr, bH + ((jb*16 + arow) * XAST + ks + acol) * 2);
            bh[4*jb+0] = tr[0];  bh[4*jb+1] = tr[2];
            bh[4*jb+2] = tr[1];  bh[4*jb+3] = tr[3];
            ldmx4(tr, bL + ((jb*16 + arow) * XAST + ks + acol) * 2);
            bl[4*jb+0] = tr[0];  bl[4*jb+1] = tr[2];
            bl[4*jb+2] = tr[1];  bl[4*jb+3] = tr[3];
        }
        #pragma unroll
        for (int j = 0; j < 10; ++j) {
            mma16816bf(acc[j], ah, &bh[2*j]);
            mma16816bf(acc[j], ah, &bl[2*j]);
            mma16816bf(acc[j], al, &bh[2*j]);
        }
    }

    const int er = lane >> 2, ec = (lane & 3) * 2;
    const int grow = m0 + warp*16 + er;
    #pragma unroll
    for (int j = 0; j < 10; ++j) {
        int gc = n0 + 8*j + ec;
        *(float2*)&g_xl[(size_t)grow * 400 + gc]       = make_float2(acc[j][0], acc[j][1]);
        *(float2*)&g_xl[(size_t)(grow + 8) * 400 + gc] = make_float2(acc[j][2], acc[j][3]);
    }
}

// ---------------- GEMM2 (reverted to 32-row version) ----------------
#define G2_BK 16
__global__ __launch_bounds__(256) void gemm2_kernel(
    const float* __restrict__ W2, const float* __restrict__ b2,
    const float* __restrict__ bn2_s, const float* __restrict__ bn2_t,
    float* __restrict__ out)
{
    __shared__ float As[32 * G2_BK];
    __shared__ float Bs[112 * 17];
    const int tid = threadIdx.x;
    const int tx = tid & 15, ty = tid >> 4;
    const int m0 = blockIdx.x * 32;
    const int rowA = tid >> 3, c2 = (tid & 7) * 2;
    const float* pA = g_h1 + (size_t)(m0 + rowA) * H1 + c2;

    float2 aPre;  float bPre[7];
    aPre = *(const float2*)(pA);
    #pragma unroll
    for (int it = 0; it < 7; ++it) {
        int i = tid + it*256;
        if (i < 1600) bPre[it] = W2[(size_t)(i/16) * H1 + (i & 15)];
    }
    As[rowA*G2_BK + c2] = aPre.x;  As[rowA*G2_BK + c2 + 1] = aPre.y;
    #pragma unroll
    for (int it = 0; it < 7; ++it) {
        int i = tid + it*256;
        if (i < 1600) Bs[(i/16)*17 + (i & 15)] = bPre[it];
    }
    __syncthreads();

    float acc0[7], acc1[7];
    #pragma unroll
    for (int j = 0; j < 7; ++j) { acc0[j] = 0.f; acc1[j] = 0.f; }

    const int NT_K = H1 / G2_BK;
    for (int kt = 0; kt < NT_K; ++kt) {
        const bool has = (kt + 1) < NT_K;
        const int k0n = (kt + 1) * G2_BK;
        if (has) {
            aPre = *(const float2*)(pA + k0n);
            #pragma unroll
            for (int it = 0; it < 7; ++it) {
                int i = tid + it*256;
                if (i < 1600) bPre[it] = W2[(size_t)(i/16) * H1 + k0n + (i & 15)];
            }
        }
        #pragma unroll
        for (int kk = 0; kk < G2_BK; ++kk) {
            float a0 = As[ty*G2_BK + kk];
            float a1 = As[(ty + 16)*G2_BK + kk];
            #pragma unroll
            for (int j = 0; j < 7; ++j) {
                float bv = Bs[(tx + 16*j)*17 + kk];
                acc0[j] += a0 * bv;
                acc1[j] += a1 * bv;
            }
        }
        __syncthreads();
        if (has) {
            As[rowA*G2_BK + c2] = aPre.x;  As[rowA*G2_BK + c2 + 1] = aPre.y;
            #pragma unroll
            for (int it = 0; it < 7; ++it) {
                int i = tid + it*256;
                if (i < 1600) Bs[(i/16)*17 + (i & 15)] = bPre[it];
            }
            __syncthreads();
        }
    }

    #pragma unroll
    for (int j = 0; j < 7; ++j) {
        int n = tx + 16*j;
        if (n >= H2) continue;
        float al = bn2_s[n];
        float be = b2[n]*al + bn2_t[n];
        int m_a = m0 + ty, m_b = m0 + ty + 16;
        float va = fmaxf(acc0[j]*al + be, 0.f);
        float vb = fmaxf(acc1[j]*al + be, 0.f);
        size_t oa = (m_a < NB) ? ((size_t)m_a*H2 + n) : ((size_t)NB*H2 + (size_t)(m_a - NB)*H2 + n);
        size_t ob = (m_b < NB) ? ((size_t)m_b*H2 + n) : ((size_t)NB*H2 + (size_t)(m_b - NB)*H2 + n);
        out[oa] = va;
        out[ob] = vb;
    }
}

// ---------------- Drug encoder v5 (unchanged) ----------------
#define VXL 201
#define VH  209
#define OXL 0
#define OH  12864
#define OWA 26240
#define OWB 26440
#define OTW 26640
#define OSC 26840
#define OFL 26904
#define OES 26968
#define OED 27096
#define OCN 27224
#define OST 27288
#define OCU 27353
#define OLS 27417
#define DTOT 27545
#define DRUG_SMEM_BYTES (DTOT * 4)
#define DRUG_GRID 296

__global__ __launch_bounds__(512, 2) void drug_kernel(const int* __restrict__ edge_index)
{
    extern __shared__ float sm[];
    float* xl    = sm + OXL;
    float* hsh   = sm + OH;
    float* wa    = sm + OWA;
    float* wb    = sm + OWB;
    float* tw    = sm + OTW;
    float* score = sm + OSC;
    int*   flag  = (int*)(sm + OFL);
    int*   es    = (int*)(sm + OES);
    int*   ed    = (int*)(sm + OED);
    int*   cnt   = (int*)(sm + OCN);
    int*   start = (int*)(sm + OST);
    int*   cur   = (int*)(sm + OCU);
    int*   list  = (int*)(sm + OLS);

    const int tid = threadIdx.x;
    const int g0 = (int)(((long)blockIdx.x * NG) / DRUG_GRID);
    const int g1 = (int)(((long)(blockIdx.x + 1) * NG) / DRUG_GRID);
    const float winv = g_winv;

    if (tid < DN) { wa[tid] = g_wa2[tid]; wb[tid] = g_wb2[tid]; tw[tid] = g_tw[tid]; }
    __syncthreads();

    const int ni   = tid >> 3;
    const int part = tid & 7;
    const int c0   = part * 25;

    for (int g = g0; g < g1; ++g) {
        const int base = g * NPG;
        for (int i = tid; i < NPG * DN; i += 512) {
            int nn = i / DN, c = i - nn * DN;
            xl[nn * VXL + c] = g_xl[(size_t)(base + nn) * 400 + c];
        }
        if (tid < EPG) {
            es[tid] = edge_index[g*EPG + tid] - base;
            ed[tid] = edge_index[ET_TOT + g*EPG + tid] - base;
        }
        if (tid < NPG) cnt[tid] = 0;
        __syncthreads();
        if (tid < EPG) atomicAdd(&cnt[ed[tid]], 1);
        __syncthreads();
        if (tid == 0) {
            int run = 0;
            for (int nn = 0; nn < NPG; ++nn) { start[nn] = run; run += cnt[nn]; }
            start[NPG] = run;
        }
        __syncthreads();
        if (tid < NPG) cur[tid] = start[tid];
        __syncthreads();
        if (tid < EPG) {
            int pos = atomicAdd(&cur[ed[tid]], 1);
            list[pos] = es[tid];
        }
        __syncthreads();

        {
            float acc[25];
            const float* xr = g_xl + (size_t)(base + ni) * 400 + DN + c0;
            #pragma unroll
            for (int c = 0; c < 25; ++c) acc[c] = xr[c];
            const int b0 = start[ni], b1 = start[ni + 1];
            for (int e = b0; e < b1; ++e) {
                const float* xp = xl + list[e] * VXL + c0;
                #pragma unroll
                for (int c = 0; c < 25; ++c) acc[c] += xp[c];
            }
            #pragma unroll
            for (int c = 0; c < 25; ++c) {
                int cc = c0 + c;
                hsh[ni * VH + cc] = fmaxf(acc[c] * wa[cc] + wb[cc], 0.f);
            }
        }
        __syncthreads();

        {
            float s = 0.f;
            const float* hp  = &hsh[ni * VH + c0];
            const float* twp = &tw[c0];
            #pragma unroll
            for (int c = 0; c < 25; ++c) s += hp[c] * twp[c];
            s += __shfl_xor_sync(0xffffffffu, s, 1);
            s += __shfl_xor_sync(0xffffffffu, s, 2);
            s += __shfl_xor_sync(0xffffffffu, s, 4);
            if (part == 0) score[ni] = tanhf(s * winv);
        }
        __syncthreads();
        if (tid < NPG) {
            float sn = score[tid];
            int r = 0;
            for (int m2 = 0; m2 < NPG; ++m2) {
                float sv = score[m2];
                r += (sv > sn) || (sv == sn && m2 < tid);
            }
            flag[tid] = (r < KTOP) ? 1 : 0;
        }
        __syncthreads();
        if (tid < DN) {
            const int c = tid;
            float mx = -1e30f, sum = 0.f, mxs = -1e30f, sums = 0.f;
            for (int n2 = 0; n2 < NPG; ++n2) {
                float v = hsh[n2 * VH + c];
                mx = fmaxf(mx, v); sum += v;
                if (flag[n2]) {
                    float w = v * score[n2];
                    mxs = fmaxf(mxs, w); sums += w;
                }
            }
            g_dx[(size_t)g*400 + c]      = fmaxf(mx + 3.f*mxs, 0.f);
            g_dx[(size_t)g*400 + DN + c] = fmaxf(sum*(1.f/NPG) + 3.f*(sums*(1.f/KTOP)), 0.f);
        }
        __syncthreads();
    }
}

__global__ __launch_bounds__(256) void resp_kernel(
    const float* __restrict__ Wp, const float* __restrict__ bp,
    float* __restrict__ out)
{
    const int row = blockIdx.x * 8 + (threadIdx.x >> 5);
    const int lane = threadIdx.x & 31;
    float s = 0.f;
    for (int i = lane; i < 500; i += 32) {
        float z = (i < H2) ? out[(size_t)row*H2 + i] : g_dx[(size_t)row*400 + (i - H2)];
        s += z * Wp[i];
    }
    #pragma unroll
    for (int o = 16; o; o >>= 1) s += __shfl_down_sync(0xffffffffu, s, o);
    if (lane == 0) out[(size_t)2*NB*H2 + row] = s + bp[0];
}

extern "C" void kernel_launch(void* const* d_in, const int* in_sizes, int n_in,
                              void* d_out, int out_size)
{
    const float* x1     = (const float*)d_in[0];
    const float* x2     = (const float*)d_in[1];
    const int*   eidx   = (const int*)d_in[4];
    const float* drug_x = (const float*)d_in[5];
    const float* bn0_s  = (const float*)d_in[6];
    const float* bn0_t  = (const float*)d_in[7];
    const float* W1     = (const float*)d_in[8];
    const float* b1     = (const float*)d_in[9];
    const float* bn1_s  = (const float*)d_in[10];
    const float* bn1_t  = (const float*)d_in[11];
    const float* W2     = (const float*)d_in[12];
    const float* b2     = (const float*)d_in[13];
    const float* bn2_s  = (const float*)d_in[14];
    const float* bn2_t  = (const float*)d_in[15];
    const float* Wrel   = (const float*)d_in[16];
    const float* brel   = (const float*)d_in[17];
    const float* Wroot  = (const float*)d_in[18];
    const float* bnd_s  = (const float*)d_in[19];
    const float* bnd_t  = (const float*)d_in[20];
    const float* topk_w = (const float*)d_in[21];
    const float* Wp     = (const float*)d_in[22];
    const float* bp     = (const float*)d_in[23];
    float* out = (float*)d_out;

    cudaFuncSetAttribute(drug_kernel, cudaFuncAttributeMaxDynamicSharedMemorySize, DRUG_SMEM_BYTES);
    cudaFuncSetAttribute(gemm1_mma, cudaFuncAttributeMaxDynamicSharedMemorySize, G1_DSMEM);
    cudaFuncSetAttribute(xl_gemm, cudaFuncAttributeMaxDynamicSharedMemorySize, XL_DSMEM);

    wprep_kernel<<<63, 256>>>(Wrel, Wroot, brel, bnd_s, bnd_t, topk_w);
    const long NT4 = (long)M_TOT * 2000 + (long)H1 * 2000;
    prep_kernel<<<(int)((NT4 + 255) / 256), 256>>>(x1, x2, W1, bn0_s, bn0_t);
    prep2_kernel<<<20480, 256>>>(drug_x);
    gemm1_mma<<<dim3(8, 16), 512, G1_DSMEM>>>(b1, bn1_s, bn1_t);
    xl_gemm<<<dim3(5, 1024), 256, XL_DSMEM>>>();
    gemm2_kernel<<<M_TOT / 32, 256>>>(W2, b2, bn2_s, bn2_t, out);
    drug_kernel<<<DRUG_GRID, 512, DRUG_SMEM_BYTES>>>(eidx);
    resp_kernel<<<NG / 8, 256>>>(Wp, bp, out);
}

// round 10
// speedup vs baseline: 1.2351x; 1.0291x over previous
#include <cuda_runtime.h>
#include <cuda_bf16.h>
#include <cuda_fp16.h>
#include <math.h>
#include <stdint.h>

#define NB      2048
#define EXPR    8000
#define H1      1024
#define H2      100
#define M_TOT   4096
#define DD      78
#define DN      200
#define NPG     64
#define EPG     128
#define NG      2048
#define NT_ALL  131072
#define ET_TOT  262144
#define KTOP    52

__device__ float g_h1[M_TOT * H1];
__device__ float g_dx[NG * 400];
__device__ __half g_Ahi[(size_t)M_TOT * EXPR];
__device__ __half g_Alo[(size_t)M_TOT * EXPR];
__device__ __half g_Bh[(size_t)H1 * EXPR];
__device__ __nv_bfloat16 g_dxhi[(size_t)NT_ALL * 80];
__device__ __nv_bfloat16 g_dxlo[(size_t)NT_ALL * 80];
__device__ __nv_bfloat16 g_wxhi[400 * 80];
__device__ __nv_bfloat16 g_wxlo[400 * 80];
__device__ float g_xl[(size_t)NT_ALL * 400];
__device__ float g_wa2[DN], g_wb2[DN];
__device__ float g_tw[DN];
__device__ float g_winv;

__device__ __forceinline__ unsigned smem_u32(const void* p) {
    unsigned a;
    asm("{ .reg .u64 t; cvta.to.shared.u64 t, %1; cvt.u32.u64 %0, t; }" : "=r"(a) : "l"(p));
    return a;
}
__device__ __forceinline__ void cpa16(unsigned s, const void* g) {
    asm volatile("cp.async.cg.shared.global [%0], [%1], 16;" :: "r"(s), "l"(g));
}
__device__ __forceinline__ void cpa_commit() { asm volatile("cp.async.commit_group;" ::: "memory"); }
template<int N> __device__ __forceinline__ void cpa_wait() {
    asm volatile("cp.async.wait_group %0;" :: "n"(N) : "memory");
}
__device__ __forceinline__ void ldmx4(unsigned* r, unsigned addr) {
    asm volatile("ldmatrix.sync.aligned.m8n8.x4.shared.b16 {%0,%1,%2,%3}, [%4];"
        : "=r"(r[0]), "=r"(r[1]), "=r"(r[2]), "=r"(r[3]) : "r"(addr));
}
__device__ __forceinline__ void mma16816bf(float* d, const unsigned* a, const unsigned* b) {
    asm volatile("mma.sync.aligned.m16n8k16.row.col.f32.bf16.bf16.f32 "
        "{%0,%1,%2,%3}, {%4,%5,%6,%7}, {%8,%9}, {%0,%1,%2,%3};"
        : "+f"(d[0]), "+f"(d[1]), "+f"(d[2]), "+f"(d[3])
        : "r"(a[0]), "r"(a[1]), "r"(a[2]), "r"(a[3]), "r"(b[0]), "r"(b[1]));
}
__device__ __forceinline__ void mma16816h(float* d, const unsigned* a, const unsigned* b) {
    asm volatile("mma.sync.aligned.m16n8k16.row.col.f32.f16.f16.f32 "
        "{%0,%1,%2,%3}, {%4,%5,%6,%7}, {%8,%9}, {%0,%1,%2,%3};"
        : "+f"(d[0]), "+f"(d[1]), "+f"(d[2]), "+f"(d[3])
        : "r"(a[0]), "r"(a[1]), "r"(a[2]), "r"(a[3]), "r"(b[0]), "r"(b[1]));
}

__device__ __forceinline__ void split4h(__half* hi, __half* lo, float4 v) {
    __half h0=__float2half_rn(v.x), h1=__float2half_rn(v.y);
    __half h2=__float2half_rn(v.z), h3=__float2half_rn(v.w);
    union { __half b[4]; uint2 u; } H, L;
    H.b[0]=h0; H.b[1]=h1; H.b[2]=h2; H.b[3]=h3;
    L.b[0]=__float2half_rn(v.x-__half2float(h0));
    L.b[1]=__float2half_rn(v.y-__half2float(h1));
    L.b[2]=__float2half_rn(v.z-__half2float(h2));
    L.b[3]=__float2half_rn(v.w-__half2float(h3));
    *(uint2*)hi = H.u;  *(uint2*)lo = L.u;
}
__device__ __forceinline__ void conv4h(__half* dst, float4 v) {
    union { __half b[4]; uint2 u; } H;
    H.b[0]=__float2half_rn(v.x); H.b[1]=__float2half_rn(v.y);
    H.b[2]=__float2half_rn(v.z); H.b[3]=__float2half_rn(v.w);
    *(uint2*)dst = H.u;
}
__device__ __forceinline__ void split2(__nv_bfloat16* hi, __nv_bfloat16* lo, float a, float b) {
    __nv_bfloat16 h0=__float2bfloat16_rn(a), h1=__float2bfloat16_rn(b);
    union { __nv_bfloat16 v[2]; unsigned u; } H, L;
    H.v[0]=h0; H.v[1]=h1;
    L.v[0]=__float2bfloat16_rn(a-__bfloat162float(h0));
    L.v[1]=__float2bfloat16_rn(b-__bfloat162float(h1));
    *(unsigned*)hi = H.u;  *(unsigned*)lo = L.u;
}

__global__ __launch_bounds__(256) void prep_kernel(
    const float* __restrict__ x1, const float* __restrict__ x2,
    const float* __restrict__ W1,
    const float* __restrict__ bn0_s, const float* __restrict__ bn0_t)
{
    const long NA = (long)M_TOT * 2000;
    const long NT4 = NA + (long)H1 * 2000;
    long i = (long)blockIdx.x * 256 + threadIdx.x;
    if (i >= NT4) return;
    if (i < NA) {
        int row = (int)(i / 2000), k4 = (int)(i % 2000);
        const float* src = (row < NB) ? (x1 + (size_t)row * EXPR) : (x2 + (size_t)(row - NB) * EXPR);
        float4 v = *(const float4*)(src + k4 * 4);
        float4 s = *(const float4*)(bn0_s + k4 * 4);
        float4 t = *(const float4*)(bn0_t + k4 * 4);
        v.x = v.x*s.x + t.x;  v.y = v.y*s.y + t.y;  v.z = v.z*s.z + t.z;  v.w = v.w*s.w + t.w;
        size_t eo = (size_t)row * EXPR + (size_t)k4 * 4;
        split4h(g_Ahi + eo, g_Alo + eo, v);
    } else {
        long j = i - NA;
        int row = (int)(j / 2000), k4 = (int)(j % 2000);
        float4 v = *(const float4*)(W1 + (size_t)row * EXPR + k4 * 4);
        conv4h(g_Bh + (size_t)row * EXPR + (size_t)k4 * 4, v);
    }
}

__global__ __launch_bounds__(256) void prep2_kernel(const float* __restrict__ dx)
{
    long i = (long)blockIdx.x * 256 + threadIdx.x;
    if (i >= (long)NT_ALL * 40) return;
    int n = (int)(i / 40), kp = (int)(i % 40);
    int k0 = 2 * kp;
    float a = (k0     < DD) ? dx[(size_t)n * DD + k0]     : 0.f;
    float b = (k0 + 1 < DD) ? dx[(size_t)n * DD + k0 + 1] : 0.f;
    size_t eo = (size_t)n * 80 + k0;
    split2(g_dxhi + eo, g_dxlo + eo, a, b);
}

__global__ __launch_bounds__(256) void wprep_kernel(
    const float* __restrict__ Wrel, const float* __restrict__ Wroot,
    const float* __restrict__ brel,
    const float* __restrict__ bnd_s, const float* __restrict__ bnd_t,
    const float* __restrict__ topk_w)
{
    int i = blockIdx.x * 256 + threadIdx.x;
    if (i < 400 * 40) {
        int n = i / 40, kp = i % 40;
        int k0 = 2 * kp;
        float a = 0.f, b = 0.f;
        if (k0 < DD)     a = (n < DN) ? Wrel[n*DD + k0]     : Wroot[(n-DN)*DD + k0];
        if (k0 + 1 < DD) b = (n < DN) ? Wrel[n*DD + k0 + 1] : Wroot[(n-DN)*DD + k0 + 1];
        split2(g_wxhi + n*80 + k0, g_wxlo + n*80 + k0, a, b);
    }
    if (i < DN) {
        float al = bnd_s[i];
        g_wa2[i] = al;
        g_wb2[i] = brel[i]*al + bnd_t[i];
        g_tw[i]  = topk_w[i];
    }
    if (i == 0) {
        float s = 0.f;
        for (int c = 0; c < DN; ++c) s += topk_w[c]*topk_w[c];
        g_winv = rsqrtf(s);
    }
}

// ---------------- GEMM1: fp16 2-pass, 1024 threads (8 warps/SMSP) ----------------
#define KC    32
#define NCH   250
#define AST   40
#define OFF_AH 0
#define OFF_AL 20480
#define OFF_B  40960
#define STG    51200
#define G1_DSMEM (3 * STG)

__global__ void __launch_bounds__(1024, 1) gemm1_mma(
    const float* __restrict__ b1, const float* __restrict__ bn1_s,
    const float* __restrict__ bn1_t)
{
    extern __shared__ char dynsm[];
    __shared__ float s_alpha[128], s_beta[128];
    const unsigned sb = smem_u32(dynsm);
    const int tid = threadIdx.x;
    const int warp = tid >> 5, lane = tid & 31;
    const int m0 = blockIdx.y * 256;
    const int n0 = blockIdx.x * 128;
    const int wm = (warp >> 2) * 32;     // 8 warp-rows of 32
    const int wn = (warp & 3) * 32;      // 4 warp-cols of 32

    if (tid < 128) {
        float al = bn1_s[n0 + tid];
        s_alpha[tid] = al;
        s_beta[tid]  = b1[n0 + tid] * al + bn1_t[n0 + tid];
    }

    auto load_chunk = [&](int c, int s) {
        const unsigned st = sb + s * STG;
        const long k0 = (long)c * KC;
        {
            int r = tid >> 2, q = tid & 3;            // 256 rows x 4 chunks
            unsigned off = r * 80 + q * 16;
            size_t go = (size_t)(m0 + r) * EXPR + k0 + q * 8;
            cpa16(st + OFF_AH + off, g_Ahi + go);
            cpa16(st + OFF_AL + off, g_Alo + go);
        }
        if (tid < 512) {
            int r = tid >> 2, q = tid & 3;            // 128 rows x 4 chunks
            unsigned off = r * 80 + q * 16;
            size_t go = (size_t)(n0 + r) * EXPR + k0 + q * 8;
            cpa16(st + OFF_B + off, g_Bh + go);
        }
        cpa_commit();
    };

    float acc[2][4][4];
    #pragma unroll
    for (int i = 0; i < 2; ++i)
        #pragma unroll
        for (int j = 0; j < 4; ++j)
            #pragma unroll
            for (int q = 0; q < 4; ++q) acc[i][j][q] = 0.f;

    load_chunk(0, 0);
    load_chunk(1, 1);

    const int arow = lane & 15;
    const int acol = (lane >> 4) << 3;

    for (int c = 0; c < NCH; ++c) {
        const int s = c - (c / 3) * 3;
        if (c + 1 < NCH) cpa_wait<1>(); else cpa_wait<0>();
        __syncthreads();
        if (c + 2 < NCH) {
            int s2 = (c + 2) - ((c + 2) / 3) * 3;
            load_chunk(c + 2, s2);
        }

        const unsigned aH = sb + s * STG;
        const unsigned aL = aH + (OFF_AL - OFF_AH);
        const unsigned bB = aH + (OFF_B  - OFF_AH);

        #pragma unroll
        for (int ks = 0; ks < KC; ks += 16) {
            unsigned ah[8], al[8], bh[8];
            #pragma unroll
            for (int i = 0; i < 2; ++i)
                ldmx4(&ah[4*i], aH + ((wm + i*16 + arow) * AST + ks + acol) * 2);
            #pragma unroll
            for (int j2 = 0; j2 < 2; ++j2) {
                unsigned tr[4];
                ldmx4(tr, bB + ((wn + j2*16 + arow) * AST + ks + acol) * 2);
                bh[4*j2 + 0] = tr[0];  bh[4*j2 + 1] = tr[2];
                bh[4*j2 + 2] = tr[1];  bh[4*j2 + 3] = tr[3];
            }
            #pragma unroll
            for (int i = 0; i < 2; ++i)
                #pragma unroll
                for (int j = 0; j < 4; ++j)
                    mma16816h(acc[i][j], &ah[4*i], &bh[2*j]);
            #pragma unroll
            for (int i = 0; i < 2; ++i)
                ldmx4(&al[4*i], aL + ((wm + i*16 + arow) * AST + ks + acol) * 2);
            #pragma unroll
            for (int i = 0; i < 2; ++i)
                #pragma unroll
                for (int j = 0; j < 4; ++j)
                    mma16816h(acc[i][j], &al[4*i], &bh[2*j]);
        }
    }

    const int er = lane >> 2, ec = (lane & 3) * 2;
    #pragma unroll
    for (int i = 0; i < 2; ++i) {
        #pragma unroll
        for (int j = 0; j < 4; ++j) {
            int nl = wn + j*8 + ec;
            float a0 = s_alpha[nl], a1 = s_alpha[nl+1];
            float e0 = s_beta[nl],  e1 = s_beta[nl+1];
            int mg0 = m0 + wm + i*16 + er;
            float2 v0, v1;
            v0.x = fmaxf(acc[i][j][0]*a0 + e0, 0.f);
            v0.y = fmaxf(acc[i][j][1]*a1 + e1, 0.f);
            v1.x = fmaxf(acc[i][j][2]*a0 + e0, 0.f);
            v1.y = fmaxf(acc[i][j][3]*a1 + e1, 0.f);
            *(float2*)&g_h1[(size_t)mg0 * H1 + n0 + nl]       = v0;
            *(float2*)&g_h1[(size_t)(mg0 + 8) * H1 + n0 + nl] = v1;
        }
    }
}

// ---------------- XL GEMM (unchanged) ----------------
#define XAST 88
#define XOFF_AH 0
#define XOFF_AL 22528
#define XOFF_BH 45056
#define XOFF_BL 59136
#define XL_DSMEM 73216

__global__ void __launch_bounds__(256, 1) xl_gemm()
{
    extern __shared__ char dynsm[];
    const unsigned sb = smem_u32(dynsm);
    const int tid = threadIdx.x;
    const int warp = tid >> 5, lane = tid & 31;
    const int m0 = blockIdx.y * 128;
    const int n0 = blockIdx.x * 80;

    #pragma unroll
    for (int t = 0; t < 5; ++t) {
        int i = tid + t * 256;
        int r = i / 10, q = i - r * 10;
        unsigned off = r * 176 + q * 16;
        size_t go = (size_t)(m0 + r) * 80 + q * 8;
        cpa16(sb + XOFF_AH + off, g_dxhi + go);
        cpa16(sb + XOFF_AL + off, g_dxlo + go);
    }
    #pragma unroll
    for (int t = 0; t < 4; ++t) {
        int i = tid + t * 256;
        if (i < 800) {
            int r = i / 10, q = i - r * 10;
            unsigned off = r * 176 + q * 16;
            size_t go = (size_t)(n0 + r) * 80 + q * 8;
            cpa16(sb + XOFF_BH + off, g_wxhi + go);
            cpa16(sb + XOFF_BL + off, g_wxlo + go);
        }
    }
    cpa_commit();
    cpa_wait<0>();
    __syncthreads();

    float acc[10][4];
    #pragma unroll
    for (int j = 0; j < 10; ++j)
        #pragma unroll
        for (int q = 0; q < 4; ++q) acc[j][q] = 0.f;

    const int arow = lane & 15;
    const int acol = (lane >> 4) << 3;
    const unsigned aH = sb + XOFF_AH, aL = sb + XOFF_AL;
    const unsigned bH = sb + XOFF_BH, bL = sb + XOFF_BL;

    #pragma unroll
    for (int ks = 0; ks < 80; ks += 16) {
        unsigned ah[4], al[4], bh[20], bl[20];
        ldmx4(ah, aH + ((warp*16 + arow) * XAST + ks + acol) * 2);
        ldmx4(al, aL + ((warp*16 + arow) * XAST + ks + acol) * 2);
        #pragma unroll
        for (int jb = 0; jb < 5; ++jb) {
            unsigned tr[4];
            ldmx4(tr, bH + ((jb*16 + arow) * XAST + ks + acol) * 2);
            bh[4*jb+0] = tr[0];  bh[4*jb+1] = tr[2];
            bh[4*jb+2] = tr[1];  bh[4*jb+3] = tr[3];
            ldmx4(tr, bL + ((jb*16 + arow) * XAST + ks + acol) * 2);
            bl[4*jb+0] = tr[0];  bl[4*jb+1] = tr[2];
            bl[4*jb+2] = tr[1];  bl[4*jb+3] = tr[3];
        }
        #pragma unroll
        for (int j = 0; j < 10; ++j) {
            mma16816bf(acc[j], ah, &bh[2*j]);
            mma16816bf(acc[j], ah, &bl[2*j]);
            mma16816bf(acc[j], al, &bh[2*j]);
        }
    }

    const int er = lane >> 2, ec = (lane & 3) * 2;
    const int grow = m0 + warp*16 + er;
    #pragma unroll
    for (int j = 0; j < 10; ++j) {
        int gc = n0 + 8*j + ec;
        *(float2*)&g_xl[(size_t)grow * 400 + gc]       = make_float2(acc[j][0], acc[j][1]);
        *(float2*)&g_xl[(size_t)(grow + 8) * 400 + gc] = make_float2(acc[j][2], acc[j][3]);
    }
}

// ---------------- GEMM2 (32-row version, unchanged) ----------------
#define G2_BK 16
__global__ __launch_bounds__(256) void gemm2_kernel(
    const float* __restrict__ W2, const float* __restrict__ b2,
    const float* __restrict__ bn2_s, const float* __restrict__ bn2_t,
    float* __restrict__ out)
{
    __shared__ float As[32 * G2_BK];
    __shared__ float Bs[112 * 17];
    const int tid = threadIdx.x;
    const int tx = tid & 15, ty = tid >> 4;
    const int m0 = blockIdx.x * 32;
    const int rowA = tid >> 3, c2 = (tid & 7) * 2;
    const float* pA = g_h1 + (size_t)(m0 + rowA) * H1 + c2;

    float2 aPre;  float bPre[7];
    aPre = *(const float2*)(pA);
    #pragma unroll
    for (int it = 0; it < 7; ++it) {
        int i = tid + it*256;
        if (i < 1600) bPre[it] = W2[(size_t)(i/16) * H1 + (i & 15)];
    }
    As[rowA*G2_BK + c2] = aPre.x;  As[rowA*G2_BK + c2 + 1] = aPre.y;
    #pragma unroll
    for (int it = 0; it < 7; ++it) {
        int i = tid + it*256;
        if (i < 1600) Bs[(i/16)*17 + (i & 15)] = bPre[it];
    }
    __syncthreads();

    float acc0[7], acc1[7];
    #pragma unroll
    for (int j = 0; j < 7; ++j) { acc0[j] = 0.f; acc1[j] = 0.f; }

    const int NT_K = H1 / G2_BK;
    for (int kt = 0; kt < NT_K; ++kt) {
        const bool has = (kt + 1) < NT_K;
        const int k0n = (kt + 1) * G2_BK;
        if (has) {
            aPre = *(const float2*)(pA + k0n);
            #pragma unroll
            for (int it = 0; it < 7; ++it) {
                int i = tid + it*256;
                if (i < 1600) bPre[it] = W2[(size_t)(i/16) * H1 + k0n + (i & 15)];
            }
        }
        #pragma unroll
        for (int kk = 0; kk < G2_BK; ++kk) {
            float a0 = As[ty*G2_BK + kk];
            float a1 = As[(ty + 16)*G2_BK + kk];
            #pragma unroll
            for (int j = 0; j < 7; ++j) {
                float bv = Bs[(tx + 16*j)*17 + kk];
                acc0[j] += a0 * bv;
                acc1[j] += a1 * bv;
            }
        }
        __syncthreads();
        if (has) {
            As[rowA*G2_BK + c2] = aPre.x;  As[rowA*G2_BK + c2 + 1] = aPre.y;
            #pragma unroll
            for (int it = 0; it < 7; ++it) {
                int i = tid + it*256;
                if (i < 1600) Bs[(i/16)*17 + (i & 15)] = bPre[it];
            }
            __syncthreads();
        }
    }

    #pragma unroll
    for (int j = 0; j < 7; ++j) {
        int n = tx + 16*j;
        if (n >= H2) continue;
        float al = bn2_s[n];
        float be = b2[n]*al + bn2_t[n];
        int m_a = m0 + ty, m_b = m0 + ty + 16;
        float va = fmaxf(acc0[j]*al + be, 0.f);
        float vb = fmaxf(acc1[j]*al + be, 0.f);
        size_t oa = (m_a < NB) ? ((size_t)m_a*H2 + n) : ((size_t)NB*H2 + (size_t)(m_a - NB)*H2 + n);
        size_t ob = (m_b < NB) ? ((size_t)m_b*H2 + n) : ((size_t)NB*H2 + (size_t)(m_b - NB)*H2 + n);
        out[oa] = va;
        out[ob] = vb;
    }
}

// ---------------- Drug encoder v5 (unchanged) ----------------
#define VXL 201
#define VH  209
#define OXL 0
#define OH  12864
#define OWA 26240
#define OWB 26440
#define OTW 26640
#define OSC 26840
#define OFL 26904
#define OES 26968
#define OED 27096
#define OCN 27224
#define OST 27288
#define OCU 27353
#define OLS 27417
#define DTOT 27545
#define DRUG_SMEM_BYTES (DTOT * 4)
#define DRUG_GRID 296

__global__ __launch_bounds__(512, 2) void drug_kernel(const int* __restrict__ edge_index)
{
    extern __shared__ float sm[];
    float* xl    = sm + OXL;
    float* hsh   = sm + OH;
    float* wa    = sm + OWA;
    float* wb    = sm + OWB;
    float* tw    = sm + OTW;
    float* score = sm + OSC;
    int*   flag  = (int*)(sm + OFL);
    int*   es    = (int*)(sm + OES);
    int*   ed    = (int*)(sm + OED);
    int*   cnt   = (int*)(sm + OCN);
    int*   start = (int*)(sm + OST);
    int*   cur   = (int*)(sm + OCU);
    int*   list  = (int*)(sm + OLS);

    const int tid = threadIdx.x;
    const int g0 = (int)(((long)blockIdx.x * NG) / DRUG_GRID);
    const int g1 = (int)(((long)(blockIdx.x + 1) * NG) / DRUG_GRID);
    const float winv = g_winv;

    if (tid < DN) { wa[tid] = g_wa2[tid]; wb[tid] = g_wb2[tid]; tw[tid] = g_tw[tid]; }
    __syncthreads();

    const int ni   = tid >> 3;
    const int part = tid & 7;
    const int c0   = part * 25;

    for (int g = g0; g < g1; ++g) {
        const int base = g * NPG;
        for (int i = tid; i < NPG * DN; i += 512) {
            int nn = i / DN, c = i - nn * DN;
            xl[nn * VXL + c] = g_xl[(size_t)(base + nn) * 400 + c];
        }
        if (tid < EPG) {
            es[tid] = edge_index[g*EPG + tid] - base;
            ed[tid] = edge_index[ET_TOT + g*EPG + tid] - base;
        }
        if (tid < NPG) cnt[tid] = 0;
        __syncthreads();
        if (tid < EPG) atomicAdd(&cnt[ed[tid]], 1);
        __syncthreads();
        if (tid == 0) {
            int run = 0;
            for (int nn = 0; nn < NPG; ++nn) { start[nn] = run; run += cnt[nn]; }
            start[NPG] = run;
        }
        __syncthreads();
        if (tid < NPG) cur[tid] = start[tid];
        __syncthreads();
        if (tid < EPG) {
            int pos = atomicAdd(&cur[ed[tid]], 1);
            list[pos] = es[tid];
        }
        __syncthreads();

        {
            float acc[25];
            const float* xr = g_xl + (size_t)(base + ni) * 400 + DN + c0;
            #pragma unroll
            for (int c = 0; c < 25; ++c) acc[c] = xr[c];
            const int b0 = start[ni], b1 = start[ni + 1];
            for (int e = b0; e < b1; ++e) {
                const float* xp = xl + list[e] * VXL + c0;
                #pragma unroll
                for (int c = 0; c < 25; ++c) acc[c] += xp[c];
            }
            #pragma unroll
            for (int c = 0; c < 25; ++c) {
                int cc = c0 + c;
                hsh[ni * VH + cc] = fmaxf(acc[c] * wa[cc] + wb[cc], 0.f);
            }
        }
        __syncthreads();

        {
            float s = 0.f;
            const float* hp  = &hsh[ni * VH + c0];
            const float* twp = &tw[c0];
            #pragma unroll
            for (int c = 0; c < 25; ++c) s += hp[c] * twp[c];
            s += __shfl_xor_sync(0xffffffffu, s, 1);
            s += __shfl_xor_sync(0xffffffffu, s, 2);
            s += __shfl_xor_sync(0xffffffffu, s, 4);
            if (part == 0) score[ni] = tanhf(s * winv);
        }
        __syncthreads();
        if (tid < NPG) {
            float sn = score[tid];
            int r = 0;
            for (int m2 = 0; m2 < NPG; ++m2) {
                float sv = score[m2];
                r += (sv > sn) || (sv == sn && m2 < tid);
            }
            flag[tid] = (r < KTOP) ? 1 : 0;
        }
        __syncthreads();
        if (tid < DN) {
            const int c = tid;
            float mx = -1e30f, sum = 0.f, mxs = -1e30f, sums = 0.f;
            for (int n2 = 0; n2 < NPG; ++n2) {
                float v = hsh[n2 * VH + c];
                mx = fmaxf(mx, v); sum += v;
                if (flag[n2]) {
                    float w = v * score[n2];
                    mxs = fmaxf(mxs, w); sums += w;
                }
            }
            g_dx[(size_t)g*400 + c]      = fmaxf(mx + 3.f*mxs, 0.f);
            g_dx[(size_t)g*400 + DN + c] = fmaxf(sum*(1.f/NPG) + 3.f*(sums*(1.f/KTOP)), 0.f);
        }
        __syncthreads();
    }
}

__global__ __launch_bounds__(256) void resp_kernel(
    const float* __restrict__ Wp, const float* __restrict__ bp,
    float* __restrict__ out)
{
    const int row = blockIdx.x * 8 + (threadIdx.x >> 5);
    const int lane = threadIdx.x & 31;
    float s = 0.f;
    for (int i = lane; i < 500; i += 32) {
        float z = (i < H2) ? out[(size_t)row*H2 + i] : g_dx[(size_t)row*400 + (i - H2)];
        s += z * Wp[i];
    }
    #pragma unroll
    for (int o = 16; o; o >>= 1) s += __shfl_down_sync(0xffffffffu, s, o);
    if (lane == 0) out[(size_t)2*NB*H2 + row] = s + bp[0];
}

extern "C" void kernel_launch(void* const* d_in, const int* in_sizes, int n_in,
                              void* d_out, int out_size)
{
    const float* x1     = (const float*)d_in[0];
    const float* x2     = (const float*)d_in[1];
    const int*   eidx   = (const int*)d_in[4];
    const float* drug_x = (const float*)d_in[5];
    const float* bn0_s  = (const float*)d_in[6];
    const float* bn0_t  = (const float*)d_in[7];
    const float* W1     = (const float*)d_in[8];
    const float* b1     = (const float*)d_in[9];
    const float* bn1_s  = (const float*)d_in[10];
    const float* bn1_t  = (const float*)d_in[11];
    const float* W2     = (const float*)d_in[12];
    const float* b2     = (const float*)d_in[13];
    const float* bn2_s  = (const float*)d_in[14];
    const float* bn2_t  = (const float*)d_in[15];
    const float* Wrel   = (const float*)d_in[16];
    const float* brel   = (const float*)d_in[17];
    const float* Wroot  = (const float*)d_in[18];
    const float* bnd_s  = (const float*)d_in[19];
    const float* bnd_t  = (const float*)d_in[20];
    const float* topk_w = (const float*)d_in[21];
    const float* Wp     = (const float*)d_in[22];
    const float* bp     = (const float*)d_in[23];
    float* out = (float*)d_out;

    cudaFuncSetAttribute(drug_kernel, cudaFuncAttributeMaxDynamicSharedMemorySize, DRUG_SMEM_BYTES);
    cudaFuncSetAttribute(gemm1_mma, cudaFuncAttributeMaxDynamicSharedMemorySize, G1_DSMEM);
    cudaFuncSetAttribute(xl_gemm, cudaFuncAttributeMaxDynamicSharedMemorySize, XL_DSMEM);

    wprep_kernel<<<63, 256>>>(Wrel, Wroot, brel, bnd_s, bnd_t, topk_w);
    const long NT4 = (long)M_TOT * 2000 + (long)H1 * 2000;
    prep_kernel<<<(int)((NT4 + 255) / 256), 256>>>(x1, x2, W1, bn0_s, bn0_t);
    prep2_kernel<<<20480, 256>>>(drug_x);
    gemm1_mma<<<dim3(8, 16), 1024, G1_DSMEM>>>(b1, bn1_s, bn1_t);
    xl_gemm<<<dim3(5, 1024), 256, XL_DSMEM>>>();
    gemm2_kernel<<<M_TOT / 32, 256>>>(W2, b2, bn2_s, bn2_t, out);
    drug_kernel<<<DRUG_GRID, 512, DRUG_SMEM_BYTES>>>(eidx);
    resp_kernel<<<NG / 8, 256>>>(Wp, bp, out);
}

// round 11
// speedup vs baseline: 1.6461x; 1.3327x over previous
#include <cuda_runtime.h>
#include <cuda_bf16.h>
#include <cuda_fp16.h>
#include <math.h>
#include <stdint.h>

#define NB      2048
#define EXPR    8000
#define H1      1024
#define H2      100
#define M_TOT   4096
#define DD      78
#define DN      200
#define NPG     64
#define EPG     128
#define NG      2048
#define NT_ALL  131072
#define ET_TOT  262144
#define KTOP    52

__device__ float g_h1[M_TOT * H1];
__device__ float g_dx[NG * 400];
__device__ __half g_Ah[(size_t)M_TOT * EXPR];
__device__ __half g_Bh[(size_t)H1 * EXPR];
__device__ __nv_bfloat16 g_dxhi[(size_t)NT_ALL * 80];
__device__ __nv_bfloat16 g_dxlo[(size_t)NT_ALL * 80];
__device__ __nv_bfloat16 g_wxhi[400 * 80];
__device__ __nv_bfloat16 g_wxlo[400 * 80];
__device__ float g_xl[(size_t)NT_ALL * 400];
__device__ float g_wa2[DN], g_wb2[DN];
__device__ float g_tw[DN];
__device__ float g_winv;

__device__ __forceinline__ unsigned smem_u32(const void* p) {
    unsigned a;
    asm("{ .reg .u64 t; cvta.to.shared.u64 t, %1; cvt.u32.u64 %0, t; }" : "=r"(a) : "l"(p));
    return a;
}
__device__ __forceinline__ void cpa16(unsigned s, const void* g) {
    asm volatile("cp.async.cg.shared.global [%0], [%1], 16;" :: "r"(s), "l"(g));
}
__device__ __forceinline__ void cpa_commit() { asm volatile("cp.async.commit_group;" ::: "memory"); }
template<int N> __device__ __forceinline__ void cpa_wait() {
    asm volatile("cp.async.wait_group %0;" :: "n"(N) : "memory");
}
__device__ __forceinline__ void ldmx4(unsigned* r, unsigned addr) {
    asm volatile("ldmatrix.sync.aligned.m8n8.x4.shared.b16 {%0,%1,%2,%3}, [%4];"
        : "=r"(r[0]), "=r"(r[1]), "=r"(r[2]), "=r"(r[3]) : "r"(addr));
}
__device__ __forceinline__ void mma16816bf(float* d, const unsigned* a, const unsigned* b) {
    asm volatile("mma.sync.aligned.m16n8k16.row.col.f32.bf16.bf16.f32 "
        "{%0,%1,%2,%3}, {%4,%5,%6,%7}, {%8,%9}, {%0,%1,%2,%3};"
        : "+f"(d[0]), "+f"(d[1]), "+f"(d[2]), "+f"(d[3])
        : "r"(a[0]), "r"(a[1]), "r"(a[2]), "r"(a[3]), "r"(b[0]), "r"(b[1]));
}
__device__ __forceinline__ void mma16816h(float* d, const unsigned* a, const unsigned* b) {
    asm volatile("mma.sync.aligned.m16n8k16.row.col.f32.f16.f16.f32 "
        "{%0,%1,%2,%3}, {%4,%5,%6,%7}, {%8,%9}, {%0,%1,%2,%3};"
        : "+f"(d[0]), "+f"(d[1]), "+f"(d[2]), "+f"(d[3])
        : "r"(a[0]), "r"(a[1]), "r"(a[2]), "r"(a[3]), "r"(b[0]), "r"(b[1]));
}

__device__ __forceinline__ void conv4h(__half* dst, float4 v) {
    union { __half b[4]; uint2 u; } H;
    H.b[0]=__float2half_rn(v.x); H.b[1]=__float2half_rn(v.y);
    H.b[2]=__float2half_rn(v.z); H.b[3]=__float2half_rn(v.w);
    *(uint2*)dst = H.u;
}
__device__ __forceinline__ void split2(__nv_bfloat16* hi, __nv_bfloat16* lo, float a, float b) {
    __nv_bfloat16 h0=__float2bfloat16_rn(a), h1=__float2bfloat16_rn(b);
    union { __nv_bfloat16 v[2]; unsigned u; } H, L;
    H.v[0]=h0; H.v[1]=h1;
    L.v[0]=__float2bfloat16_rn(a-__bfloat162float(h0));
    L.v[1]=__float2bfloat16_rn(b-__bfloat162float(h1));
    *(unsigned*)hi = H.u;  *(unsigned*)lo = L.u;
}

__global__ __launch_bounds__(256) void prep_kernel(
    const float* __restrict__ x1, const float* __restrict__ x2,
    const float* __restrict__ W1,
    const float* __restrict__ bn0_s, const float* __restrict__ bn0_t)
{
    const long NA = (long)M_TOT * 2000;
    const long NT4 = NA + (long)H1 * 2000;
    long i = (long)blockIdx.x * 256 + threadIdx.x;
    if (i >= NT4) return;
    if (i < NA) {
        int row = (int)(i / 2000), k4 = (int)(i % 2000);
        const float* src = (row < NB) ? (x1 + (size_t)row * EXPR) : (x2 + (size_t)(row - NB) * EXPR);
        float4 v = *(const float4*)(src + k4 * 4);
        float4 s = *(const float4*)(bn0_s + k4 * 4);
        float4 t = *(const float4*)(bn0_t + k4 * 4);
        v.x = v.x*s.x + t.x;  v.y = v.y*s.y + t.y;  v.z = v.z*s.z + t.z;  v.w = v.w*s.w + t.w;
        conv4h(g_Ah + (size_t)row * EXPR + (size_t)k4 * 4, v);
    } else {
        long j = i - NA;
        int row = (int)(j / 2000), k4 = (int)(j % 2000);
        float4 v = *(const float4*)(W1 + (size_t)row * EXPR + k4 * 4);
        conv4h(g_Bh + (size_t)row * EXPR + (size_t)k4 * 4, v);
    }
}

__global__ __launch_bounds__(256) void prep2_kernel(const float* __restrict__ dx)
{
    long i = (long)blockIdx.x * 256 + threadIdx.x;
    if (i >= (long)NT_ALL * 40) return;
    int n = (int)(i / 40), kp = (int)(i % 40);
    int k0 = 2 * kp;
    float a = (k0     < DD) ? dx[(size_t)n * DD + k0]     : 0.f;
    float b = (k0 + 1 < DD) ? dx[(size_t)n * DD + k0 + 1] : 0.f;
    size_t eo = (size_t)n * 80 + k0;
    split2(g_dxhi + eo, g_dxlo + eo, a, b);
}

__global__ __launch_bounds__(256) void wprep_kernel(
    const float* __restrict__ Wrel, const float* __restrict__ Wroot,
    const float* __restrict__ brel,
    const float* __restrict__ bnd_s, const float* __restrict__ bnd_t,
    const float* __restrict__ topk_w)
{
    int i = blockIdx.x * 256 + threadIdx.x;
    if (i < 400 * 40) {
        int n = i / 40, kp = i % 40;
        int k0 = 2 * kp;
        float a = 0.f, b = 0.f;
        if (k0 < DD)     a = (n < DN) ? Wrel[n*DD + k0]     : Wroot[(n-DN)*DD + k0];
        if (k0 + 1 < DD) b = (n < DN) ? Wrel[n*DD + k0 + 1] : Wroot[(n-DN)*DD + k0 + 1];
        split2(g_wxhi + n*80 + k0, g_wxlo + n*80 + k0, a, b);
    }
    if (i < DN) {
        float al = bnd_s[i];
        g_wa2[i] = al;
        g_wb2[i] = brel[i]*al + bnd_t[i];
        g_tw[i]  = topk_w[i];
    }
    if (i == 0) {
        float s = 0.f;
        for (int c = 0; c < DN; ++c) s += topk_w[c]*topk_w[c];
        g_winv = rsqrtf(s);
    }
}

// ---------------- GEMM1: single-pass fp16, 1024 threads ----------------
#define KC    32
#define NCH   250
#define AST   40
#define OFF_A 0
#define OFF_B 20480
#define STG   30720
#define G1_DSMEM (3 * STG)

__global__ void __launch_bounds__(1024, 1) gemm1_mma(
    const float* __restrict__ b1, const float* __restrict__ bn1_s,
    const float* __restrict__ bn1_t)
{
    extern __shared__ char dynsm[];
    __shared__ float s_alpha[128], s_beta[128];
    const unsigned sb = smem_u32(dynsm);
    const int tid = threadIdx.x;
    const int warp = tid >> 5, lane = tid & 31;
    const int m0 = blockIdx.y * 256;
    const int n0 = blockIdx.x * 128;
    const int wm = (warp >> 2) * 32;
    const int wn = (warp & 3) * 32;

    if (tid < 128) {
        float al = bn1_s[n0 + tid];
        s_alpha[tid] = al;
        s_beta[tid]  = b1[n0 + tid] * al + bn1_t[n0 + tid];
    }

    auto load_chunk = [&](int c, int s) {
        const unsigned st = sb + s * STG;
        const long k0 = (long)c * KC;
        {
            int r = tid >> 2, q = tid & 3;
            unsigned off = r * 80 + q * 16;
            size_t go = (size_t)(m0 + r) * EXPR + k0 + q * 8;
            cpa16(st + OFF_A + off, g_Ah + go);
        }
        if (tid < 512) {
            int r = tid >> 2, q = tid & 3;
            unsigned off = r * 80 + q * 16;
            size_t go = (size_t)(n0 + r) * EXPR + k0 + q * 8;
            cpa16(st + OFF_B + off, g_Bh + go);
        }
        cpa_commit();
    };

    float acc[2][4][4];
    #pragma unroll
    for (int i = 0; i < 2; ++i)
        #pragma unroll
        for (int j = 0; j < 4; ++j)
            #pragma unroll
            for (int q = 0; q < 4; ++q) acc[i][j][q] = 0.f;

    load_chunk(0, 0);
    load_chunk(1, 1);

    const int arow = lane & 15;
    const int acol = (lane >> 4) << 3;

    for (int c = 0; c < NCH; ++c) {
        const int s = c - (c / 3) * 3;
        if (c + 1 < NCH) cpa_wait<1>(); else cpa_wait<0>();
        __syncthreads();
        if (c + 2 < NCH) {
            int s2 = (c + 2) - ((c + 2) / 3) * 3;
            load_chunk(c + 2, s2);
        }

        const unsigned aA = sb + s * STG;
        const unsigned bB = aA + OFF_B;

        #pragma unroll
        for (int ks = 0; ks < KC; ks += 16) {
            unsigned ah[8], bh[8];
            #pragma unroll
            for (int i = 0; i < 2; ++i)
                ldmx4(&ah[4*i], aA + ((wm + i*16 + arow) * AST + ks + acol) * 2);
            #pragma unroll
            for (int j2 = 0; j2 < 2; ++j2) {
                unsigned tr[4];
                ldmx4(tr, bB + ((wn + j2*16 + arow) * AST + ks + acol) * 2);
                bh[4*j2 + 0] = tr[0];  bh[4*j2 + 1] = tr[2];
                bh[4*j2 + 2] = tr[1];  bh[4*j2 + 3] = tr[3];
            }
            #pragma unroll
            for (int i = 0; i < 2; ++i)
                #pragma unroll
                for (int j = 0; j < 4; ++j)
                    mma16816h(acc[i][j], &ah[4*i], &bh[2*j]);
        }
    }

    const int er = lane >> 2, ec = (lane & 3) * 2;
    #pragma unroll
    for (int i = 0; i < 2; ++i) {
        #pragma unroll
        for (int j = 0; j < 4; ++j) {
            int nl = wn + j*8 + ec;
            float a0 = s_alpha[nl], a1 = s_alpha[nl+1];
            float e0 = s_beta[nl],  e1 = s_beta[nl+1];
            int mg0 = m0 + wm + i*16 + er;
            float2 v0, v1;
            v0.x = fmaxf(acc[i][j][0]*a0 + e0, 0.f);
            v0.y = fmaxf(acc[i][j][1]*a1 + e1, 0.f);
            v1.x = fmaxf(acc[i][j][2]*a0 + e0, 0.f);
            v1.y = fmaxf(acc[i][j][3]*a1 + e1, 0.f);
            *(float2*)&g_h1[(size_t)mg0 * H1 + n0 + nl]       = v0;
            *(float2*)&g_h1[(size_t)(mg0 + 8) * H1 + n0 + nl] = v1;
        }
    }
}

// ---------------- XL GEMM (unchanged) ----------------
#define XAST 88
#define XOFF_AH 0
#define XOFF_AL 22528
#define XOFF_BH 45056
#define XOFF_BL 59136
#define XL_DSMEM 73216

__global__ void __launch_bounds__(256, 1) xl_gemm()
{
    extern __shared__ char dynsm[];
    const unsigned sb = smem_u32(dynsm);
    const int tid = threadIdx.x;
    const int warp = tid >> 5, lane = tid & 31;
    const int m0 = blockIdx.y * 128;
    const int n0 = blockIdx.x * 80;

    #pragma unroll
    for (int t = 0; t < 5; ++t) {
        int i = tid + t * 256;
        int r = i / 10, q = i - r * 10;
        unsigned off = r * 176 + q * 16;
        size_t go = (size_t)(m0 + r) * 80 + q * 8;
        cpa16(sb + XOFF_AH + off, g_dxhi + go);
        cpa16(sb + XOFF_AL + off, g_dxlo + go);
    }
    #pragma unroll
    for (int t = 0; t < 4; ++t) {
        int i = tid + t * 256;
        if (i < 800) {
            int r = i / 10, q = i - r * 10;
            unsigned off = r * 176 + q * 16;
            size_t go = (size_t)(n0 + r) * 80 + q * 8;
            cpa16(sb + XOFF_BH + off, g_wxhi + go);
            cpa16(sb + XOFF_BL + off, g_wxlo + go);
        }
    }
    cpa_commit();
    cpa_wait<0>();
    __syncthreads();

    float acc[10][4];
    #pragma unroll
    for (int j = 0; j < 10; ++j)
        #pragma unroll
        for (int q = 0; q < 4; ++q) acc[j][q] = 0.f;

    const int arow = lane & 15;
    const int acol = (lane >> 4) << 3;
    const unsigned aH = sb + XOFF_AH, aL = sb + XOFF_AL;
    const unsigned bH = sb + XOFF_BH, bL = sb + XOFF_BL;

    #pragma unroll
    for (int ks = 0; ks < 80; ks += 16) {
        unsigned ah[4], al[4], bh[20], bl[20];
        ldmx4(ah, aH + ((warp*16 + arow) * XAST + ks + acol) * 2);
        ldmx4(al, aL + ((warp*16 + arow) * XAST + ks + acol) * 2);
        #pragma unroll
        for (int jb = 0; jb < 5; ++jb) {
            unsigned tr[4];
            ldmx4(tr, bH + ((jb*16 + arow) * XAST + ks + acol) * 2);
            bh[4*jb+0] = tr[0];  bh[4*jb+1] = tr[2];
            bh[4*jb+2] = tr[1];  bh[4*jb+3] = tr[3];
            ldmx4(tr, bL + ((jb*16 + arow) * XAST + ks + acol) * 2);
            bl[4*jb+0] = tr[0];  bl[4*jb+1] = tr[2];
            bl[4*jb+2] = tr[1];  bl[4*jb+3] = tr[3];
        }
        #pragma unroll
        for (int j = 0; j < 10; ++j) {
            mma16816bf(acc[j], ah, &bh[2*j]);
            mma16816bf(acc[j], ah, &bl[2*j]);
            mma16816bf(acc[j], al, &bh[2*j]);
        }
    }

    const int er = lane >> 2, ec = (lane & 3) * 2;
    const int grow = m0 + warp*16 + er;
    #pragma unroll
    for (int j = 0; j < 10; ++j) {
        int gc = n0 + 8*j + ec;
        *(float2*)&g_xl[(size_t)grow * 400 + gc]       = make_float2(acc[j][0], acc[j][1]);
        *(float2*)&g_xl[(size_t)(grow + 8) * 400 + gc] = make_float2(acc[j][2], acc[j][3]);
    }
}

// ---------------- GEMM2 (unchanged) ----------------
#define G2_BK 16
__global__ __launch_bounds__(256) void gemm2_kernel(
    const float* __restrict__ W2, const float* __restrict__ b2,
    const float* __restrict__ bn2_s, const float* __restrict__ bn2_t,
    float* __restrict__ out)
{
    __shared__ float As[32 * G2_BK];
    __shared__ float Bs[112 * 17];
    const int tid = threadIdx.x;
    const int tx = tid & 15, ty = tid >> 4;
    const int m0 = blockIdx.x * 32;
    const int rowA = tid >> 3, c2 = (tid & 7) * 2;
    const float* pA = g_h1 + (size_t)(m0 + rowA) * H1 + c2;

    float2 aPre;  float bPre[7];
    aPre = *(const float2*)(pA);
    #pragma unroll
    for (int it = 0; it < 7; ++it) {
        int i = tid + it*256;
        if (i < 1600) bPre[it] = W2[(size_t)(i/16) * H1 + (i & 15)];
    }
    As[rowA*G2_BK + c2] = aPre.x;  As[rowA*G2_BK + c2 + 1] = aPre.y;
    #pragma unroll
    for (int it = 0; it < 7; ++it) {
        int i = tid + it*256;
        if (i < 1600) Bs[(i/16)*17 + (i & 15)] = bPre[it];
    }
    __syncthreads();

    float acc0[7], acc1[7];
    #pragma unroll
    for (int j = 0; j < 7; ++j) { acc0[j] = 0.f; acc1[j] = 0.f; }

    const int NT_K = H1 / G2_BK;
    for (int kt = 0; kt < NT_K; ++kt) {
        const bool has = (kt + 1) < NT_K;
        const int k0n = (kt + 1) * G2_BK;
        if (has) {
            aPre = *(const float2*)(pA + k0n);
            #pragma unroll
            for (int it = 0; it < 7; ++it) {
                int i = tid + it*256;
                if (i < 1600) bPre[it] = W2[(size_t)(i/16) * H1 + k0n + (i & 15)];
            }
        }
        #pragma unroll
        for (int kk = 0; kk < G2_BK; ++kk) {
            float a0 = As[ty*G2_BK + kk];
            float a1 = As[(ty + 16)*G2_BK + kk];
            #pragma unroll
            for (int j = 0; j < 7; ++j) {
                float bv = Bs[(tx + 16*j)*17 + kk];
                acc0[j] += a0 * bv;
                acc1[j] += a1 * bv;
            }
        }
        __syncthreads();
        if (has) {
            As[rowA*G2_BK + c2] = aPre.x;  As[rowA*G2_BK + c2 + 1] = aPre.y;
            #pragma unroll
            for (int it = 0; it < 7; ++it) {
                int i = tid + it*256;
                if (i < 1600) Bs[(i/16)*17 + (i & 15)] = bPre[it];
            }
            __syncthreads();
        }
    }

    #pragma unroll
    for (int j = 0; j < 7; ++j) {
        int n = tx + 16*j;
        if (n >= H2) continue;
        float al = bn2_s[n];
        float be = b2[n]*al + bn2_t[n];
        int m_a = m0 + ty, m_b = m0 + ty + 16;
        float va = fmaxf(acc0[j]*al + be, 0.f);
        float vb = fmaxf(acc1[j]*al + be, 0.f);
        size_t oa = (m_a < NB) ? ((size_t)m_a*H2 + n) : ((size_t)NB*H2 + (size_t)(m_a - NB)*H2 + n);
        size_t ob = (m_b < NB) ? ((size_t)m_b*H2 + n) : ((size_t)NB*H2 + (size_t)(m_b - NB)*H2 + n);
        out[oa] = va;
        out[ob] = vb;
    }
}

// ---------------- Drug encoder v5 (unchanged) ----------------
#define VXL 201
#define VH  209
#define OXL 0
#define OH  12864
#define OWA 26240
#define OWB 26440
#define OTW 26640
#define OSC 26840
#define OFL 26904
#define OES 26968
#define OED 27096
#define OCN 27224
#define OST 27288
#define OCU 27353
#define OLS 27417
#define DTOT 27545
#define DRUG_SMEM_BYTES (DTOT * 4)
#define DRUG_GRID 296

__global__ __launch_bounds__(512, 2) void drug_kernel(const int* __restrict__ edge_index)
{
    extern __shared__ float sm[];
    float* xl    = sm + OXL;
    float* hsh   = sm + OH;
    float* wa    = sm + OWA;
    float* wb    = sm + OWB;
    float* tw    = sm + OTW;
    float* score = sm + OSC;
    int*   flag  = (int*)(sm + OFL);
    int*   es    = (int*)(sm + OES);
    int*   ed    = (int*)(sm + OED);
    int*   cnt   = (int*)(sm + OCN);
    int*   start = (int*)(sm + OST);
    int*   cur   = (int*)(sm + OCU);
    int*   list  = (int*)(sm + OLS);

    const int tid = threadIdx.x;
    const int g0 = (int)(((long)blockIdx.x * NG) / DRUG_GRID);
    const int g1 = (int)(((long)(blockIdx.x + 1) * NG) / DRUG_GRID);
    const float winv = g_winv;

    if (tid < DN) { wa[tid] = g_wa2[tid]; wb[tid] = g_wb2[tid]; tw[tid] = g_tw[tid]; }
    __syncthreads();

    const int ni   = tid >> 3;
    const int part = tid & 7;
    const int c0   = part * 25;

    for (int g = g0; g < g1; ++g) {
        const int base = g * NPG;
        for (int i = tid; i < NPG * DN; i += 512) {
            int nn = i / DN, c = i - nn * DN;
            xl[nn * VXL + c] = g_xl[(size_t)(base + nn) * 400 + c];
        }
        if (tid < EPG) {
            es[tid] = edge_index[g*EPG + tid] - base;
            ed[tid] = edge_index[ET_TOT + g*EPG + tid] - base;
        }
        if (tid < NPG) cnt[tid] = 0;
        __syncthreads();
        if (tid < EPG) atomicAdd(&cnt[ed[tid]], 1);
        __syncthreads();
        if (tid == 0) {
            int run = 0;
            for (int nn = 0; nn < NPG; ++nn) { start[nn] = run; run += cnt[nn]; }
            start[NPG] = run;
        }
        __syncthreads();
        if (tid < NPG) cur[tid] = start[tid];
        __syncthreads();
        if (tid < EPG) {
            int pos = atomicAdd(&cur[ed[tid]], 1);
            list[pos] = es[tid];
        }
        __syncthreads();

        {
            float acc[25];
            const float* xr = g_xl + (size_t)(base + ni) * 400 + DN + c0;
            #pragma unroll
            for (int c = 0; c < 25; ++c) acc[c] = xr[c];
            const int b0 = start[ni], b1 = start[ni + 1];
            for (int e = b0; e < b1; ++e) {
                const float* xp = xl + list[e] * VXL + c0;
                #pragma unroll
                for (int c = 0; c < 25; ++c) acc[c] += xp[c];
            }
            #pragma unroll
            for (int c = 0; c < 25; ++c) {
                int cc = c0 + c;
                hsh[ni * VH + cc] = fmaxf(acc[c] * wa[cc] + wb[cc], 0.f);
            }
        }
        __syncthreads();

        {
            float s = 0.f;
            const float* hp  = &hsh[ni * VH + c0];
            const float* twp = &tw[c0];
            #pragma unroll
            for (int c = 0; c < 25; ++c) s += hp[c] * twp[c];
            s += __shfl_xor_sync(0xffffffffu, s, 1);
            s += __shfl_xor_sync(0xffffffffu, s, 2);
            s += __shfl_xor_sync(0xffffffffu, s, 4);
            if (part == 0) score[ni] = tanhf(s * winv);
        }
        __syncthreads();
        if (tid < NPG) {
            float sn = score[tid];
            int r = 0;
            for (int m2 = 0; m2 < NPG; ++m2) {
                float sv = score[m2];
                r += (sv > sn) || (sv == sn && m2 < tid);
            }
            flag[tid] = (r < KTOP) ? 1 : 0;
        }
        __syncthreads();
        if (tid < DN) {
            const int c = tid;
            float mx = -1e30f, sum = 0.f, mxs = -1e30f, sums = 0.f;
            for (int n2 = 0; n2 < NPG; ++n2) {
                float v = hsh[n2 * VH + c];
                mx = fmaxf(mx, v); sum += v;
                if (flag[n2]) {
                    float w = v * score[n2];
                    mxs = fmaxf(mxs, w); sums += w;
                }
            }
            g_dx[(size_t)g*400 + c]      = fmaxf(mx + 3.f*mxs, 0.f);
            g_dx[(size_t)g*400 + DN + c] = fmaxf(sum*(1.f/NPG) + 3.f*(sums*(1.f/KTOP)), 0.f);
        }
        __syncthreads();
    }
}

__global__ __launch_bounds__(256) void resp_kernel(
    const float* __restrict__ Wp, const float* __restrict__ bp,
    float* __restrict__ out)
{
    const int row = blockIdx.x * 8 + (threadIdx.x >> 5);
    const int lane = threadIdx.x & 31;
    float s = 0.f;
    for (int i = lane; i < 500; i += 32) {
        float z = (i < H2) ? out[(size_t)row*H2 + i] : g_dx[(size_t)row*400 + (i - H2)];
        s += z * Wp[i];
    }
    #pragma unroll
    for (int o = 16; o; o >>= 1) s += __shfl_down_sync(0xffffffffu, s, o);
    if (lane == 0) out[(size_t)2*NB*H2 + row] = s + bp[0];
}

extern "C" void kernel_launch(void* const* d_in, const int* in_sizes, int n_in,
                              void* d_out, int out_size)
{
    const float* x1     = (const float*)d_in[0];
    const float* x2     = (const float*)d_in[1];
    const int*   eidx   = (const int*)d_in[4];
    const float* drug_x = (const float*)d_in[5];
    const float* bn0_s  = (const float*)d_in[6];
    const float* bn0_t  = (const float*)d_in[7];
    const float* W1     = (const float*)d_in[8];
    const float* b1     = (const float*)d_in[9];
    const float* bn1_s  = (const float*)d_in[10];
    const float* bn1_t  = (const float*)d_in[11];
    const float* W2     = (const float*)d_in[12];
    const float* b2     = (const float*)d_in[13];
    const float* bn2_s  = (const float*)d_in[14];
    const float* bn2_t  = (const float*)d_in[15];
    const float* Wrel   = (const float*)d_in[16];
    const float* brel   = (const float*)d_in[17];
    const float* Wroot  = (const float*)d_in[18];
    const float* bnd_s  = (const float*)d_in[19];
    const float* bnd_t  = (const float*)d_in[20];
    const float* topk_w = (const float*)d_in[21];
    const float* Wp     = (const float*)d_in[22];
    const float* bp     = (const float*)d_in[23];
    float* out = (float*)d_out;

    cudaFuncSetAttribute(drug_kernel, cudaFuncAttributeMaxDynamicSharedMemorySize, DRUG_SMEM_BYTES);
    cudaFuncSetAttribute(gemm1_mma, cudaFuncAttributeMaxDynamicSharedMemorySize, G1_DSMEM);
    cudaFuncSetAttribute(xl_gemm, cudaFuncAttributeMaxDynamicSharedMemorySize, XL_DSMEM);

    wprep_kernel<<<63, 256>>>(Wrel, Wroot, brel, bnd_s, bnd_t, topk_w);
    const long NT4 = (long)M_TOT * 2000 + (long)H1 * 2000;
    prep_kernel<<<(int)((NT4 + 255) / 256), 256>>>(x1, x2, W1, bn0_s, bn0_t);
    prep2_kernel<<<20480, 256>>>(drug_x);
    gemm1_mma<<<dim3(8, 16), 1024, G1_DSMEM>>>(b1, bn1_s, bn1_t);
    xl_gemm<<<dim3(5, 1024), 256, XL_DSMEM>>>();
    gemm2_kernel<<<M_TOT / 32, 256>>>(W2, b2, bn2_s, bn2_t, out);
    drug_kernel<<<DRUG_GRID, 512, DRUG_SMEM_BYTES>>>(eidx);
    resp_kernel<<<NG / 8, 256>>>(Wp, bp, out);
}

// round 12
// speedup vs baseline: 1.7869x; 1.0856x over previous
#include <cuda_runtime.h>
#include <cuda_bf16.h>
#include <cuda_fp16.h>
#include <math.h>
#include <stdint.h>

#define NB      2048
#define EXPR    8000
#define H1      1024
#define H2      100
#define M_TOT   4096
#define DD      78
#define DN      200
#define NPG     64
#define EPG     128
#define NG      2048
#define NT_ALL  131072
#define ET_TOT  262144
#define KTOP    52

__device__ __half g_h1h[(size_t)M_TOT * H1];
__device__ float g_dx[NG * 400];
__device__ __half g_Ah[(size_t)M_TOT * EXPR];
__device__ __half g_Bh[(size_t)H1 * EXPR];
__device__ __half g_W2h[(size_t)128 * H1];
__device__ __nv_bfloat16 g_dxhi[(size_t)NT_ALL * 80];
__device__ __nv_bfloat16 g_dxlo[(size_t)NT_ALL * 80];
__device__ __nv_bfloat16 g_wxhi[400 * 80];
__device__ __nv_bfloat16 g_wxlo[400 * 80];
__device__ float g_xl[(size_t)NT_ALL * 400];
__device__ float g_wa2[DN], g_wb2[DN];
__device__ float g_tw[DN];
__device__ float g_winv;

__device__ __forceinline__ unsigned smem_u32(const void* p) {
    unsigned a;
    asm("{ .reg .u64 t; cvta.to.shared.u64 t, %1; cvt.u32.u64 %0, t; }" : "=r"(a) : "l"(p));
    return a;
}
__device__ __forceinline__ void cpa16(unsigned s, const void* g) {
    asm volatile("cp.async.cg.shared.global [%0], [%1], 16;" :: "r"(s), "l"(g));
}
__device__ __forceinline__ void cpa_commit() { asm volatile("cp.async.commit_group;" ::: "memory"); }
template<int N> __device__ __forceinline__ void cpa_wait() {
    asm volatile("cp.async.wait_group %0;" :: "n"(N) : "memory");
}
__device__ __forceinline__ void ldmx4(unsigned* r, unsigned addr) {
    asm volatile("ldmatrix.sync.aligned.m8n8.x4.shared.b16 {%0,%1,%2,%3}, [%4];"
        : "=r"(r[0]), "=r"(r[1]), "=r"(r[2]), "=r"(r[3]) : "r"(addr));
}
__device__ __forceinline__ void mma16816bf(float* d, const unsigned* a, const unsigned* b) {
    asm volatile("mma.sync.aligned.m16n8k16.row.col.f32.bf16.bf16.f32 "
        "{%0,%1,%2,%3}, {%4,%5,%6,%7}, {%8,%9}, {%0,%1,%2,%3};"
        : "+f"(d[0]), "+f"(d[1]), "+f"(d[2]), "+f"(d[3])
        : "r"(a[0]), "r"(a[1]), "r"(a[2]), "r"(a[3]), "r"(b[0]), "r"(b[1]));
}
__device__ __forceinline__ void mma16816h(float* d, const unsigned* a, const unsigned* b) {
    asm volatile("mma.sync.aligned.m16n8k16.row.col.f32.f16.f16.f32 "
        "{%0,%1,%2,%3}, {%4,%5,%6,%7}, {%8,%9}, {%0,%1,%2,%3};"
        : "+f"(d[0]), "+f"(d[1]), "+f"(d[2]), "+f"(d[3])
        : "r"(a[0]), "r"(a[1]), "r"(a[2]), "r"(a[3]), "r"(b[0]), "r"(b[1]));
}

__device__ __forceinline__ void conv4h(__half* dst, float4 v) {
    union { __half b[4]; uint2 u; } H;
    H.b[0]=__float2half_rn(v.x); H.b[1]=__float2half_rn(v.y);
    H.b[2]=__float2half_rn(v.z); H.b[3]=__float2half_rn(v.w);
    *(uint2*)dst = H.u;
}
__device__ __forceinline__ void split2(__nv_bfloat16* hi, __nv_bfloat16* lo, float a, float b) {
    __nv_bfloat16 h0=__float2bfloat16_rn(a), h1=__float2bfloat16_rn(b);
    union { __nv_bfloat16 v[2]; unsigned u; } H, L;
    H.v[0]=h0; H.v[1]=h1;
    L.v[0]=__float2bfloat16_rn(a-__bfloat162float(h0));
    L.v[1]=__float2bfloat16_rn(b-__bfloat162float(h1));
    *(unsigned*)hi = H.u;  *(unsigned*)lo = L.u;
}

// ---------------- prep: x (bn0 folded), W1, W2 -> fp16 ----------------
__global__ __launch_bounds__(256) void prep_kernel(
    const float* __restrict__ x1, const float* __restrict__ x2,
    const float* __restrict__ W1, const float* __restrict__ W2,
    const float* __restrict__ bn0_s, const float* __restrict__ bn0_t)
{
    const long NA = (long)M_TOT * 2000;
    const long NB1 = NA + (long)H1 * 2000;
    const long NT4 = NB1 + 128 * 256;
    long i = (long)blockIdx.x * 256 + threadIdx.x;
    if (i >= NT4) return;
    if (i < NA) {
        int row = (int)(i / 2000), k4 = (int)(i % 2000);
        const float* src = (row < NB) ? (x1 + (size_t)row * EXPR) : (x2 + (size_t)(row - NB) * EXPR);
        float4 v = *(const float4*)(src + k4 * 4);
        float4 s = *(const float4*)(bn0_s + k4 * 4);
        float4 t = *(const float4*)(bn0_t + k4 * 4);
        v.x = v.x*s.x + t.x;  v.y = v.y*s.y + t.y;  v.z = v.z*s.z + t.z;  v.w = v.w*s.w + t.w;
        conv4h(g_Ah + (size_t)row * EXPR + (size_t)k4 * 4, v);
    } else if (i < NB1) {
        long j = i - NA;
        int row = (int)(j / 2000), k4 = (int)(j % 2000);
        float4 v = *(const float4*)(W1 + (size_t)row * EXPR + k4 * 4);
        conv4h(g_Bh + (size_t)row * EXPR + (size_t)k4 * 4, v);
    } else {
        long j = i - NB1;
        int row = (int)(j >> 8), k4 = (int)(j & 255);
        float4 v = make_float4(0.f, 0.f, 0.f, 0.f);
        if (row < H2) v = *(const float4*)(W2 + (size_t)row * H1 + k4 * 4);
        conv4h(g_W2h + (size_t)row * H1 + k4 * 4, v);
    }
}

__global__ __launch_bounds__(256) void prep2_kernel(const float* __restrict__ dx)
{
    long i = (long)blockIdx.x * 256 + threadIdx.x;
    if (i >= (long)NT_ALL * 40) return;
    int n = (int)(i / 40), kp = (int)(i % 40);
    int k0 = 2 * kp;
    float a = (k0     < DD) ? dx[(size_t)n * DD + k0]     : 0.f;
    float b = (k0 + 1 < DD) ? dx[(size_t)n * DD + k0 + 1] : 0.f;
    size_t eo = (size_t)n * 80 + k0;
    split2(g_dxhi + eo, g_dxlo + eo, a, b);
}

__global__ __launch_bounds__(256) void wprep_kernel(
    const float* __restrict__ Wrel, const float* __restrict__ Wroot,
    const float* __restrict__ brel,
    const float* __restrict__ bnd_s, const float* __restrict__ bnd_t,
    const float* __restrict__ topk_w)
{
    int i = blockIdx.x * 256 + threadIdx.x;
    if (i < 400 * 40) {
        int n = i / 40, kp = i % 40;
        int k0 = 2 * kp;
        float a = 0.f, b = 0.f;
        if (k0 < DD)     a = (n < DN) ? Wrel[n*DD + k0]     : Wroot[(n-DN)*DD + k0];
        if (k0 + 1 < DD) b = (n < DN) ? Wrel[n*DD + k0 + 1] : Wroot[(n-DN)*DD + k0 + 1];
        split2(g_wxhi + n*80 + k0, g_wxlo + n*80 + k0, a, b);
    }
    if (i < DN) {
        float al = bnd_s[i];
        g_wa2[i] = al;
        g_wb2[i] = brel[i]*al + bnd_t[i];
        g_tw[i]  = topk_w[i];
    }
    if (i == 0) {
        float s = 0.f;
        for (int c = 0; c < DN; ++c) s += topk_w[c]*topk_w[c];
        g_winv = rsqrtf(s);
    }
}

// ---------------- GEMM1: single-pass fp16, 1024 threads, fp16 output ----------------
#define KC    32
#define NCH   250
#define AST   40
#define OFF_A 0
#define OFF_B 20480
#define STG   30720
#define G1_DSMEM (3 * STG)

__global__ void __launch_bounds__(1024, 1) gemm1_mma(
    const float* __restrict__ b1, const float* __restrict__ bn1_s,
    const float* __restrict__ bn1_t)
{
    extern __shared__ char dynsm[];
    __shared__ float s_alpha[128], s_beta[128];
    const unsigned sb = smem_u32(dynsm);
    const int tid = threadIdx.x;
    const int warp = tid >> 5, lane = tid & 31;
    const int m0 = blockIdx.y * 256;
    const int n0 = blockIdx.x * 128;
    const int wm = (warp >> 2) * 32;
    const int wn = (warp & 3) * 32;

    if (tid < 128) {
        float al = bn1_s[n0 + tid];
        s_alpha[tid] = al;
        s_beta[tid]  = b1[n0 + tid] * al + bn1_t[n0 + tid];
    }

    auto load_chunk = [&](int c, int s) {
        const unsigned st = sb + s * STG;
        const long k0 = (long)c * KC;
        {
            int r = tid >> 2, q = tid & 3;
            unsigned off = r * 80 + q * 16;
            size_t go = (size_t)(m0 + r) * EXPR + k0 + q * 8;
            cpa16(st + OFF_A + off, g_Ah + go);
        }
        if (tid < 512) {
            int r = tid >> 2, q = tid & 3;
            unsigned off = r * 80 + q * 16;
            size_t go = (size_t)(n0 + r) * EXPR + k0 + q * 8;
            cpa16(st + OFF_B + off, g_Bh + go);
        }
        cpa_commit();
    };

    float acc[2][4][4];
    #pragma unroll
    for (int i = 0; i < 2; ++i)
        #pragma unroll
        for (int j = 0; j < 4; ++j)
            #pragma unroll
            for (int q = 0; q < 4; ++q) acc[i][j][q] = 0.f;

    load_chunk(0, 0);
    load_chunk(1, 1);

    const int arow = lane & 15;
    const int acol = (lane >> 4) << 3;

    for (int c = 0; c < NCH; ++c) {
        const int s = c - (c / 3) * 3;
        if (c + 1 < NCH) cpa_wait<1>(); else cpa_wait<0>();
        __syncthreads();
        if (c + 2 < NCH) {
            int s2 = (c + 2) - ((c + 2) / 3) * 3;
            load_chunk(c + 2, s2);
        }

        const unsigned aA = sb + s * STG;
        const unsigned bB = aA + OFF_B;

        #pragma unroll
        for (int ks = 0; ks < KC; ks += 16) {
            unsigned ah[8], bh[8];
            #pragma unroll
            for (int i = 0; i < 2; ++i)
                ldmx4(&ah[4*i], aA + ((wm + i*16 + arow) * AST + ks + acol) * 2);
            #pragma unroll
            for (int j2 = 0; j2 < 2; ++j2) {
                unsigned tr[4];
                ldmx4(tr, bB + ((wn + j2*16 + arow) * AST + ks + acol) * 2);
                bh[4*j2 + 0] = tr[0];  bh[4*j2 + 1] = tr[2];
                bh[4*j2 + 2] = tr[1];  bh[4*j2 + 3] = tr[3];
            }
            #pragma unroll
            for (int i = 0; i < 2; ++i)
                #pragma unroll
                for (int j = 0; j < 4; ++j)
                    mma16816h(acc[i][j], &ah[4*i], &bh[2*j]);
        }
    }

    const int er = lane >> 2, ec = (lane & 3) * 2;
    #pragma unroll
    for (int i = 0; i < 2; ++i) {
        #pragma unroll
        for (int j = 0; j < 4; ++j) {
            int nl = wn + j*8 + ec;
            float a0 = s_alpha[nl], a1 = s_alpha[nl+1];
            float e0 = s_beta[nl],  e1 = s_beta[nl+1];
            int mg0 = m0 + wm + i*16 + er;
            __half2 h0 = __floats2half2_rn(fmaxf(acc[i][j][0]*a0 + e0, 0.f),
                                           fmaxf(acc[i][j][1]*a1 + e1, 0.f));
            __half2 h1v = __floats2half2_rn(fmaxf(acc[i][j][2]*a0 + e0, 0.f),
                                            fmaxf(acc[i][j][3]*a1 + e1, 0.f));
            *(__half2*)&g_h1h[(size_t)mg0 * H1 + n0 + nl]       = h0;
            *(__half2*)&g_h1h[(size_t)(mg0 + 8) * H1 + n0 + nl] = h1v;
        }
    }
}

// ---------------- XL GEMM (unchanged) ----------------
#define XAST 88
#define XOFF_AH 0
#define XOFF_AL 22528
#define XOFF_BH 45056
#define XOFF_BL 59136
#define XL_DSMEM 73216

__global__ void __launch_bounds__(256, 1) xl_gemm()
{
    extern __shared__ char dynsm[];
    const unsigned sb = smem_u32(dynsm);
    const int tid = threadIdx.x;
    const int warp = tid >> 5, lane = tid & 31;
    const int m0 = blockIdx.y * 128;
    const int n0 = blockIdx.x * 80;

    #pragma unroll
    for (int t = 0; t < 5; ++t) {
        int i = tid + t * 256;
        int r = i / 10, q = i - r * 10;
        unsigned off = r * 176 + q * 16;
        size_t go = (size_t)(m0 + r) * 80 + q * 8;
        cpa16(sb + XOFF_AH + off, g_dxhi + go);
        cpa16(sb + XOFF_AL + off, g_dxlo + go);
    }
    #pragma unroll
    for (int t = 0; t < 4; ++t) {
        int i = tid + t * 256;
        if (i < 800) {
            int r = i / 10, q = i - r * 10;
            unsigned off = r * 176 + q * 16;
            size_t go = (size_t)(n0 + r) * 80 + q * 8;
            cpa16(sb + XOFF_BH + off, g_wxhi + go);
            cpa16(sb + XOFF_BL + off, g_wxlo + go);
        }
    }
    cpa_commit();
    cpa_wait<0>();
    __syncthreads();

    float acc[10][4];
    #pragma unroll
    for (int j = 0; j < 10; ++j)
        #pragma unroll
        for (int q = 0; q < 4; ++q) acc[j][q] = 0.f;

    const int arow = lane & 15;
    const int acol = (lane >> 4) << 3;
    const unsigned aH = sb + XOFF_AH, aL = sb + XOFF_AL;
    const unsigned bH = sb + XOFF_BH, bL = sb + XOFF_BL;

    #pragma unroll
    for (int ks = 0; ks < 80; ks += 16) {
        unsigned ah[4], al[4], bh[20], bl[20];
        ldmx4(ah, aH + ((warp*16 + arow) * XAST + ks + acol) * 2);
        ldmx4(al, aL + ((warp*16 + arow) * XAST + ks + acol) * 2);
        #pragma unroll
        for (int jb = 0; jb < 5; ++jb) {
            unsigned tr[4];
            ldmx4(tr, bH + ((jb*16 + arow) * XAST + ks + acol) * 2);
            bh[4*jb+0] = tr[0];  bh[4*jb+1] = tr[2];
            bh[4*jb+2] = tr[1];  bh[4*jb+3] = tr[3];
            ldmx4(tr, bL + ((jb*16 + arow) * XAST + ks + acol) * 2);
            bl[4*jb+0] = tr[0];  bl[4*jb+1] = tr[2];
            bl[4*jb+2] = tr[1];  bl[4*jb+3] = tr[3];
        }
        #pragma unroll
        for (int j = 0; j < 10; ++j) {
            mma16816bf(acc[j], ah, &bh[2*j]);
            mma16816bf(acc[j], ah, &bl[2*j]);
            mma16816bf(acc[j], al, &bh[2*j]);
        }
    }

    const int er = lane >> 2, ec = (lane & 3) * 2;
    const int grow = m0 + warp*16 + er;
    #pragma unroll
    for (int j = 0; j < 10; ++j) {
        int gc = n0 + 8*j + ec;
        *(float2*)&g_xl[(size_t)grow * 400 + gc]       = make_float2(acc[j][0], acc[j][1]);
        *(float2*)&g_xl[(size_t)(grow + 8) * 400 + gc] = make_float2(acc[j][2], acc[j][3]);
    }
}

// ---------------- GEMM2 on tensor cores: 32x128 tile, K=1024 ----------------
__global__ __launch_bounds__(256) void gemm2_mma(
    const float* __restrict__ b2, const float* __restrict__ bn2_s,
    const float* __restrict__ bn2_t, float* __restrict__ out)
{
    __shared__ __align__(16) __half sm2[3 * 6400];   // stage: A 32x40 + B 128x40 halves
    const int tid = threadIdx.x;
    const int warp = tid >> 5, lane = tid & 31;
    const int m0 = blockIdx.x * 32;
    const int wm = (warp >> 2) * 16;
    const int wn = (warp & 3) * 32;
    const unsigned sb = smem_u32(sm2);

    auto load_chunk = [&](int c, int s) {
        const unsigned st = sb + s * 12800;
        if (tid < 128) {
            int r = tid >> 2, q = tid & 3;
            cpa16(st + (r * 40 + q * 8) * 2, g_h1h + (size_t)(m0 + r) * H1 + c * 32 + q * 8);
        }
        #pragma unroll
        for (int t = 0; t < 2; ++t) {
            int i = tid + t * 256;
            int r = i >> 2, q = i & 3;
            cpa16(st + 2560 + (r * 40 + q * 8) * 2, g_W2h + (size_t)r * H1 + c * 32 + q * 8);
        }
        cpa_commit();
    };

    float acc[4][4];
    #pragma unroll
    for (int j = 0; j < 4; ++j)
        #pragma unroll
        for (int q = 0; q < 4; ++q) acc[j][q] = 0.f;

    load_chunk(0, 0);
    load_chunk(1, 1);

    const int arow = lane & 15;
    const int acol = (lane >> 4) << 3;

    for (int c = 0; c < 32; ++c) {
        const int s = c - (c / 3) * 3;
        if (c + 1 < 32) cpa_wait<1>(); else cpa_wait<0>();
        __syncthreads();
        if (c + 2 < 32) {
            int s2 = (c + 2) - ((c + 2) / 3) * 3;
            load_chunk(c + 2, s2);
        }
        const unsigned aA = sb + s * 12800;
        const unsigned bB = aA + 2560;
        #pragma unroll
        for (int ks = 0; ks < 32; ks += 16) {
            unsigned ah[4], bh[8];
            ldmx4(ah, aA + ((wm + arow) * 40 + ks + acol) * 2);
            #pragma unroll
            for (int j2 = 0; j2 < 2; ++j2) {
                unsigned tr[4];
                ldmx4(tr, bB + ((wn + j2*16 + arow) * 40 + ks + acol) * 2);
                bh[4*j2 + 0] = tr[0];  bh[4*j2 + 1] = tr[2];
                bh[4*j2 + 2] = tr[1];  bh[4*j2 + 3] = tr[3];
            }
            #pragma unroll
            for (int j = 0; j < 4; ++j)
                mma16816h(acc[j], ah, &bh[2*j]);
        }
    }

    const int er = lane >> 2, ec = (lane & 3) * 2;
    #pragma unroll
    for (int j = 0; j < 4; ++j) {
        int n = wn + j*8 + ec;
        if (n >= H2) continue;
        float a0 = bn2_s[n],   a1 = bn2_s[n+1];
        float e0 = b2[n]*a0 + bn2_t[n];
        float e1 = b2[n+1]*a1 + bn2_t[n+1];
        int m_a = m0 + wm + er, m_b = m_a + 8;
        float va0 = fmaxf(acc[j][0]*a0 + e0, 0.f);
        float va1 = fmaxf(acc[j][1]*a1 + e1, 0.f);
        float vb0 = fmaxf(acc[j][2]*a0 + e0, 0.f);
        float vb1 = fmaxf(acc[j][3]*a1 + e1, 0.f);
        size_t oa = (m_a < NB) ? ((size_t)m_a*H2 + n) : ((size_t)NB*H2 + (size_t)(m_a - NB)*H2 + n);
        size_t ob = (m_b < NB) ? ((size_t)m_b*H2 + n) : ((size_t)NB*H2 + (size_t)(m_b - NB)*H2 + n);
        out[oa] = va0;  out[oa + 1] = va1;
        out[ob] = vb0;  out[ob + 1] = vb1;
    }
}

// ---------------- Drug encoder v5 (unchanged) ----------------
#define VXL 201
#define VH  209
#define OXL 0
#define OH  12864
#define OWA 26240
#define OWB 26440
#define OTW 26640
#define OSC 26840
#define OFL 26904
#define OES 26968
#define OED 27096
#define OCN 27224
#define OST 27288
#define OCU 27353
#define OLS 27417
#define DTOT 27545
#define DRUG_SMEM_BYTES (DTOT * 4)
#define DRUG_GRID 296

__global__ __launch_bounds__(512, 2) void drug_kernel(const int* __restrict__ edge_index)
{
    extern __shared__ float sm[];
    float* xl    = sm + OXL;
    float* hsh   = sm + OH;
    float* wa    = sm + OWA;
    float* wb    = sm + OWB;
    float* tw    = sm + OTW;
    float* score = sm + OSC;
    int*   flag  = (int*)(sm + OFL);
    int*   es    = (int*)(sm + OES);
    int*   ed    = (int*)(sm + OED);
    int*   cnt   = (int*)(sm + OCN);
    int*   start = (int*)(sm + OST);
    int*   cur   = (int*)(sm + OCU);
    int*   list  = (int*)(sm + OLS);

    const int tid = threadIdx.x;
    const int g0 = (int)(((long)blockIdx.x * NG) / DRUG_GRID);
    const int g1 = (int)(((long)(blockIdx.x + 1) * NG) / DRUG_GRID);
    const float winv = g_winv;

    if (tid < DN) { wa[tid] = g_wa2[tid]; wb[tid] = g_wb2[tid]; tw[tid] = g_tw[tid]; }
    __syncthreads();

    const int ni   = tid >> 3;
    const int part = tid & 7;
    const int c0   = part * 25;

    for (int g = g0; g < g1; ++g) {
        const int base = g * NPG;
        for (int i = tid; i < NPG * DN; i += 512) {
            int nn = i / DN, c = i - nn * DN;
            xl[nn * VXL + c] = g_xl[(size_t)(base + nn) * 400 + c];
        }
        if (tid < EPG) {
            es[tid] = edge_index[g*EPG + tid] - base;
            ed[tid] = edge_index[ET_TOT + g*EPG + tid] - base;
        }
        if (tid < NPG) cnt[tid] = 0;
        __syncthreads();
        if (tid < EPG) atomicAdd(&cnt[ed[tid]], 1);
        __syncthreads();
        if (tid == 0) {
            int run = 0;
            for (int nn = 0; nn < NPG; ++nn) { start[nn] = run; run += cnt[nn]; }
            start[NPG] = run;
        }
        __syncthreads();
        if (tid < NPG) cur[tid] = start[tid];
        __syncthreads();
        if (tid < EPG) {
            int pos = atomicAdd(&cur[ed[tid]], 1);
            list[pos] = es[tid];
        }
        __syncthreads();

        {
            float acc[25];
            const float* xr = g_xl + (size_t)(base + ni) * 400 + DN + c0;
            #pragma unroll
            for (int c = 0; c < 25; ++c) acc[c] = xr[c];
            const int b0 = start[ni], b1 = start[ni + 1];
            for (int e = b0; e < b1; ++e) {
                const float* xp = xl + list[e] * VXL + c0;
                #pragma unroll
                for (int c = 0; c < 25; ++c) acc[c] += xp[c];
            }
            #pragma unroll
            for (int c = 0; c < 25; ++c) {
                int cc = c0 + c;
                hsh[ni * VH + cc] = fmaxf(acc[c] * wa[cc] + wb[cc], 0.f);
            }
        }
        __syncthreads();

        {
            float s = 0.f;
            const float* hp  = &hsh[ni * VH + c0];
            const float* twp = &tw[c0];
            #pragma unroll
            for (int c = 0; c < 25; ++c) s += hp[c] * twp[c];
            s += __shfl_xor_sync(0xffffffffu, s, 1);
            s += __shfl_xor_sync(0xffffffffu, s, 2);
            s += __shfl_xor_sync(0xffffffffu, s, 4);
            if (part == 0) score[ni] = tanhf(s * winv);
        }
        __syncthreads();
        if (tid < NPG) {
            float sn = score[tid];
            int r = 0;
            for (int m2 = 0; m2 < NPG; ++m2) {
                float sv = score[m2];
                r += (sv > sn) || (sv == sn && m2 < tid);
            }
            flag[tid] = (r < KTOP) ? 1 : 0;
        }
        __syncthreads();
        if (tid < DN) {
            const int c = tid;
            float mx = -1e30f, sum = 0.f, mxs = -1e30f, sums = 0.f;
            for (int n2 = 0; n2 < NPG; ++n2) {
                float v = hsh[n2 * VH + c];
                mx = fmaxf(mx, v); sum += v;
                if (flag[n2]) {
                    float w = v * score[n2];
                    mxs = fmaxf(mxs, w); sums += w;
                }
            }
            g_dx[(size_t)g*400 + c]      = fmaxf(mx + 3.f*mxs, 0.f);
            g_dx[(size_t)g*400 + DN + c] = fmaxf(sum*(1.f/NPG) + 3.f*(sums*(1.f/KTOP)), 0.f);
        }
        __syncthreads();
    }
}

__global__ __launch_bounds__(256) void resp_kernel(
    const float* __restrict__ Wp, const float* __restrict__ bp,
    float* __restrict__ out)
{
    const int row = blockIdx.x * 8 + (threadIdx.x >> 5);
    const int lane = threadIdx.x & 31;
    float s = 0.f;
    for (int i = lane; i < 500; i += 32) {
        float z = (i < H2) ? out[(size_t)row*H2 + i] : g_dx[(size_t)row*400 + (i - H2)];
        s += z * Wp[i];
    }
    #pragma unroll
    for (int o = 16; o; o >>= 1) s += __shfl_down_sync(0xffffffffu, s, o);
    if (lane == 0) out[(size_t)2*NB*H2 + row] = s + bp[0];
}

extern "C" void kernel_launch(void* const* d_in, const int* in_sizes, int n_in,
                              void* d_out, int out_size)
{
    const float* x1     = (const float*)d_in[0];
    const float* x2     = (const float*)d_in[1];
    const int*   eidx   = (const int*)d_in[4];
    const float* drug_x = (const float*)d_in[5];
    const float* bn0_s  = (const float*)d_in[6];
    const float* bn0_t  = (const float*)d_in[7];
    const float* W1     = (const float*)d_in[8];
    const float* b1     = (const float*)d_in[9];
    const float* bn1_s  = (const float*)d_in[10];
    const float* bn1_t  = (const float*)d_in[11];
    const float* W2     = (const float*)d_in[12];
    const float* b2     = (const float*)d_in[13];
    const float* bn2_s  = (const float*)d_in[14];
    const float* bn2_t  = (const float*)d_in[15];
    const float* Wrel   = (const float*)d_in[16];
    const float* brel   = (const float*)d_in[17];
    const float* Wroot  = (const float*)d_in[18];
    const float* bnd_s  = (const float*)d_in[19];
    const float* bnd_t  = (const float*)d_in[20];
    const float* topk_w = (const float*)d_in[21];
    const float* Wp     = (const float*)d_in[22];
    const float* bp     = (const float*)d_in[23];
    float* out = (float*)d_out;

    cudaFuncSetAttribute(drug_kernel, cudaFuncAttributeMaxDynamicSharedMemorySize, DRUG_SMEM_BYTES);
    cudaFuncSetAttribute(gemm1_mma, cudaFuncAttributeMaxDynamicSharedMemorySize, G1_DSMEM);
    cudaFuncSetAttribute(xl_gemm, cudaFuncAttributeMaxDynamicSharedMemorySize, XL_DSMEM);

    wprep_kernel<<<63, 256>>>(Wrel, Wroot, brel, bnd_s, bnd_t, topk_w);
    const long NT4 = (long)M_TOT * 2000 + (long)H1 * 2000 + 128 * 256;
    prep_kernel<<<(int)((NT4 + 255) / 256), 256>>>(x1, x2, W1, W2, bn0_s, bn0_t);
    prep2_kernel<<<20480, 256>>>(drug_x);
    gemm1_mma<<<dim3(8, 16), 1024, G1_DSMEM>>>(b1, bn1_s, bn1_t);
    xl_gemm<<<dim3(5, 1024), 256, XL_DSMEM>>>();
    gemm2_mma<<<M_TOT / 32, 256>>>(b2, bn2_s, bn2_t, out);
    drug_kernel<<<DRUG_GRID, 512, DRUG_SMEM_BYTES>>>(eidx);
    resp_kernel<<<NG / 8, 256>>>(Wp, bp, out);
}

// round 13
// speedup vs baseline: 1.8259x; 1.0218x over previous
#include <cuda_runtime.h>
#include <cuda_bf16.h>
#include <cuda_fp16.h>
#include <math.h>
#include <stdint.h>

#define NB      2048
#define EXPR    8000
#define H1      1024
#define H2      100
#define M_TOT   4096
#define DD      78
#define DN      200
#define NPG     64
#define EPG     128
#define NG      2048
#define NT_ALL  131072
#define ET_TOT  262144
#define KTOP    52

__device__ __half g_h1h[(size_t)M_TOT * H1];
__device__ float g_dx[NG * 400];
__device__ __half g_Ah[(size_t)M_TOT * EXPR];
__device__ __half g_Bh[(size_t)H1 * EXPR];
__device__ __half g_W2h[(size_t)128 * H1];
__device__ __nv_bfloat16 g_dxhi[(size_t)NT_ALL * 80];
__device__ __nv_bfloat16 g_dxlo[(size_t)NT_ALL * 80];
__device__ __nv_bfloat16 g_wxhi[400 * 80];
__device__ __nv_bfloat16 g_wxlo[400 * 80];
__device__ float g_xl[(size_t)NT_ALL * 400];
__device__ float g_wa2[DN], g_wb2[DN];
__device__ float g_tw[DN];
__device__ float g_winv;

__device__ __forceinline__ unsigned smem_u32(const void* p) {
    unsigned a;
    asm("{ .reg .u64 t; cvta.to.shared.u64 t, %1; cvt.u32.u64 %0, t; }" : "=r"(a) : "l"(p));
    return a;
}
__device__ __forceinline__ void cpa16(unsigned s, const void* g) {
    asm volatile("cp.async.cg.shared.global [%0], [%1], 16;" :: "r"(s), "l"(g));
}
__device__ __forceinline__ void cpa_commit() { asm volatile("cp.async.commit_group;" ::: "memory"); }
template<int N> __device__ __forceinline__ void cpa_wait() {
    asm volatile("cp.async.wait_group %0;" :: "n"(N) : "memory");
}
__device__ __forceinline__ void ldmx4(unsigned* r, unsigned addr) {
    asm volatile("ldmatrix.sync.aligned.m8n8.x4.shared.b16 {%0,%1,%2,%3}, [%4];"
        : "=r"(r[0]), "=r"(r[1]), "=r"(r[2]), "=r"(r[3]) : "r"(addr));
}
__device__ __forceinline__ void mma16816bf(float* d, const unsigned* a, const unsigned* b) {
    asm volatile("mma.sync.aligned.m16n8k16.row.col.f32.bf16.bf16.f32 "
        "{%0,%1,%2,%3}, {%4,%5,%6,%7}, {%8,%9}, {%0,%1,%2,%3};"
        : "+f"(d[0]), "+f"(d[1]), "+f"(d[2]), "+f"(d[3])
        : "r"(a[0]), "r"(a[1]), "r"(a[2]), "r"(a[3]), "r"(b[0]), "r"(b[1]));
}
__device__ __forceinline__ void mma16816h(float* d, const unsigned* a, const unsigned* b) {
    asm volatile("mma.sync.aligned.m16n8k16.row.col.f32.f16.f16.f32 "
        "{%0,%1,%2,%3}, {%4,%5,%6,%7}, {%8,%9}, {%0,%1,%2,%3};"
        : "+f"(d[0]), "+f"(d[1]), "+f"(d[2]), "+f"(d[3])
        : "r"(a[0]), "r"(a[1]), "r"(a[2]), "r"(a[3]), "r"(b[0]), "r"(b[1]));
}

__device__ __forceinline__ void conv4h(__half* dst, float4 v) {
    union { __half b[4]; uint2 u; } H;
    H.b[0]=__float2half_rn(v.x); H.b[1]=__float2half_rn(v.y);
    H.b[2]=__float2half_rn(v.z); H.b[3]=__float2half_rn(v.w);
    *(uint2*)dst = H.u;
}
__device__ __forceinline__ void split2(__nv_bfloat16* hi, __nv_bfloat16* lo, float a, float b) {
    __nv_bfloat16 h0=__float2bfloat16_rn(a), h1=__float2bfloat16_rn(b);
    union { __nv_bfloat16 v[2]; unsigned u; } H, L;
    H.v[0]=h0; H.v[1]=h1;
    L.v[0]=__float2bfloat16_rn(a-__bfloat162float(h0));
    L.v[1]=__float2bfloat16_rn(b-__bfloat162float(h1));
    *(unsigned*)hi = H.u;  *(unsigned*)lo = L.u;
}

// ---------------- prep_all: every conversion in one kernel ----------------
#define R0 ((long)M_TOT * 2000)
#define R1 (R0 + (long)H1 * 2000)
#define R2 (R1 + 128 * 256)
#define R3 (R2 + (long)NT_ALL * 40)
#define R4 (R3 + 400 * 40)
#define R5 (R4 + 256)

__global__ __launch_bounds__(256) void prep_all(
    const float* __restrict__ x1, const float* __restrict__ x2,
    const float* __restrict__ W1, const float* __restrict__ W2,
    const float* __restrict__ bn0_s, const float* __restrict__ bn0_t,
    const float* __restrict__ dx,
    const float* __restrict__ Wrel, const float* __restrict__ Wroot,
    const float* __restrict__ brel,
    const float* __restrict__ bnd_s, const float* __restrict__ bnd_t,
    const float* __restrict__ topk_w)
{
    long i = (long)blockIdx.x * 256 + threadIdx.x;
    if (i >= R5) return;
    if (i < R0) {
        int row = (int)(i / 2000), k4 = (int)(i % 2000);
        const float* src = (row < NB) ? (x1 + (size_t)row * EXPR) : (x2 + (size_t)(row - NB) * EXPR);
        float4 v = *(const float4*)(src + k4 * 4);
        float4 s = *(const float4*)(bn0_s + k4 * 4);
        float4 t = *(const float4*)(bn0_t + k4 * 4);
        v.x = v.x*s.x + t.x;  v.y = v.y*s.y + t.y;  v.z = v.z*s.z + t.z;  v.w = v.w*s.w + t.w;
        conv4h(g_Ah + (size_t)row * EXPR + (size_t)k4 * 4, v);
    } else if (i < R1) {
        long j = i - R0;
        int row = (int)(j / 2000), k4 = (int)(j % 2000);
        float4 v = *(const float4*)(W1 + (size_t)row * EXPR + k4 * 4);
        conv4h(g_Bh + (size_t)row * EXPR + (size_t)k4 * 4, v);
    } else if (i < R2) {
        long j = i - R1;
        int row = (int)(j >> 8), k4 = (int)(j & 255);
        float4 v = make_float4(0.f, 0.f, 0.f, 0.f);
        if (row < H2) v = *(const float4*)(W2 + (size_t)row * H1 + k4 * 4);
        conv4h(g_W2h + (size_t)row * H1 + k4 * 4, v);
    } else if (i < R3) {
        long j = i - R2;
        int n = (int)(j / 40), kp = (int)(j % 40);
        int k0 = 2 * kp;
        float a = (k0     < DD) ? dx[(size_t)n * DD + k0]     : 0.f;
        float b = (k0 + 1 < DD) ? dx[(size_t)n * DD + k0 + 1] : 0.f;
        size_t eo = (size_t)n * 80 + k0;
        split2(g_dxhi + eo, g_dxlo + eo, a, b);
    } else if (i < R4) {
        long j = i - R3;
        int n = (int)(j / 40), kp = (int)(j % 40);
        int k0 = 2 * kp;
        float a = 0.f, b = 0.f;
        if (k0 < DD)     a = (n < DN) ? Wrel[n*DD + k0]     : Wroot[(n-DN)*DD + k0];
        if (k0 + 1 < DD) b = (n < DN) ? Wrel[n*DD + k0 + 1] : Wroot[(n-DN)*DD + k0 + 1];
        split2(g_wxhi + n*80 + k0, g_wxlo + n*80 + k0, a, b);
    } else {
        int j = (int)(i - R4);
        if (j < DN) {
            float al = bnd_s[j];
            g_wa2[j] = al;
            g_wb2[j] = brel[j]*al + bnd_t[j];
            g_tw[j]  = topk_w[j];
        }
        if (j == 0) {
            float s = 0.f;
            for (int c = 0; c < DN; ++c) s += topk_w[c]*topk_w[c];
            g_winv = rsqrtf(s);
        }
    }
}

// ---------------- MEGA: gemm1 (bid<128) + xl (bid>=128), 1024 threads ----------------
#define KC    32
#define NCH   250
#define AST   40
#define OFF_A 0
#define OFF_B 20480
#define STG   30720
#define XAST  88
#define XB_LO 14080
#define XA_BASE 28160
#define XA_LO 22528
#define XA_PER 45056
#define MEGA_DSMEM (XA_BASE + 4 * XA_PER)   // 208384 >= gemm1's 92160

__global__ void __launch_bounds__(1024, 1) mega_g1xl(
    const float* __restrict__ b1, const float* __restrict__ bn1_s,
    const float* __restrict__ bn1_t)
{
    extern __shared__ char dynsm[];
    __shared__ float s_alpha[128], s_beta[128];
    const unsigned sb = smem_u32(dynsm);
    const int tid = threadIdx.x;
    const int bid = blockIdx.x;
    const int lane = tid & 31;

    if (bid < 128) {
        // ---------------- gemm1 tile ----------------
        const int warp = tid >> 5;
        const int m0 = (bid >> 3) * 256;
        const int n0 = (bid & 7) * 128;
        const int wm = (warp >> 2) * 32;
        const int wn = (warp & 3) * 32;

        if (tid < 128) {
            float al = bn1_s[n0 + tid];
            s_alpha[tid] = al;
            s_beta[tid]  = b1[n0 + tid] * al + bn1_t[n0 + tid];
        }

        auto load_chunk = [&](int c, int s) {
            const unsigned st = sb + s * STG;
            const long k0 = (long)c * KC;
            {
                int r = tid >> 2, q = tid & 3;
                unsigned off = r * 80 + q * 16;
                size_t go = (size_t)(m0 + r) * EXPR + k0 + q * 8;
                cpa16(st + OFF_A + off, g_Ah + go);
            }
            if (tid < 512) {
                int r = tid >> 2, q = tid & 3;
                unsigned off = r * 80 + q * 16;
                size_t go = (size_t)(n0 + r) * EXPR + k0 + q * 8;
                cpa16(st + OFF_B + off, g_Bh + go);
            }
            cpa_commit();
        };

        float acc[2][4][4];
        #pragma unroll
        for (int i = 0; i < 2; ++i)
            #pragma unroll
            for (int j = 0; j < 4; ++j)
                #pragma unroll
                for (int q = 0; q < 4; ++q) acc[i][j][q] = 0.f;

        load_chunk(0, 0);
        load_chunk(1, 1);

        const int arow = lane & 15;
        const int acol = (lane >> 4) << 3;

        for (int c = 0; c < NCH; ++c) {
            const int s = c - (c / 3) * 3;
            if (c + 1 < NCH) cpa_wait<1>(); else cpa_wait<0>();
            __syncthreads();
            if (c + 2 < NCH) {
                int s2 = (c + 2) - ((c + 2) / 3) * 3;
                load_chunk(c + 2, s2);
            }
            const unsigned aA = sb + s * STG;
            const unsigned bB = aA + OFF_B;
            #pragma unroll
            for (int ks = 0; ks < KC; ks += 16) {
                unsigned ah[8], bh[8];
                #pragma unroll
                for (int i = 0; i < 2; ++i)
                    ldmx4(&ah[4*i], aA + ((wm + i*16 + arow) * AST + ks + acol) * 2);
                #pragma unroll
                for (int j2 = 0; j2 < 2; ++j2) {
                    unsigned tr[4];
                    ldmx4(tr, bB + ((wn + j2*16 + arow) * AST + ks + acol) * 2);
                    bh[4*j2 + 0] = tr[0];  bh[4*j2 + 1] = tr[2];
                    bh[4*j2 + 2] = tr[1];  bh[4*j2 + 3] = tr[3];
                }
                #pragma unroll
                for (int i = 0; i < 2; ++i)
                    #pragma unroll
                    for (int j = 0; j < 4; ++j)
                        mma16816h(acc[i][j], &ah[4*i], &bh[2*j]);
            }
        }

        const int er = lane >> 2, ec = (lane & 3) * 2;
        #pragma unroll
        for (int i = 0; i < 2; ++i) {
            #pragma unroll
            for (int j = 0; j < 4; ++j) {
                int nl = wn + j*8 + ec;
                float a0 = s_alpha[nl], a1 = s_alpha[nl+1];
                float e0 = s_beta[nl],  e1 = s_beta[nl+1];
                int mg0 = m0 + wm + i*16 + er;
                __half2 h0 = __floats2half2_rn(fmaxf(acc[i][j][0]*a0 + e0, 0.f),
                                               fmaxf(acc[i][j][1]*a1 + e1, 0.f));
                __half2 h1v = __floats2half2_rn(fmaxf(acc[i][j][2]*a0 + e0, 0.f),
                                                fmaxf(acc[i][j][3]*a1 + e1, 0.f));
                *(__half2*)&g_h1h[(size_t)mg0 * H1 + n0 + nl]       = h0;
                *(__half2*)&g_h1h[(size_t)(mg0 + 8) * H1 + n0 + nl] = h1v;
            }
        }
    } else {
        // ---------------- xl: 4 quarters, shared B tile ----------------
        const int bid2 = bid - 128;
        const int nt = bid2 >> 8;            // 0..4
        const int mt = bid2 & 255;           // 0..255
        const int q  = tid >> 8;             // quarter 0..3
        const int qtid = tid & 255;
        const int m0 = (mt * 4 + q) * 128;
        const int n0 = nt * 80;
        const unsigned sbB = sb;
        const unsigned sbA = sb + XA_BASE + q * XA_PER;

        // B: 80 rows x 10 chunks, hi+lo
        if (tid < 800) {
            int r = tid / 10, qq = tid - r * 10;
            unsigned off = r * 176 + qq * 16;
            size_t go = (size_t)(n0 + r) * 80 + qq * 8;
            cpa16(sbB + off, g_wxhi + go);
            cpa16(sbB + XB_LO + off, g_wxlo + go);
        }
        // A: per quarter, 128 rows x 10 chunks, hi+lo
        #pragma unroll
        for (int t = 0; t < 5; ++t) {
            int i = qtid + t * 256;
            int r = i / 10, qq = i - r * 10;
            unsigned off = r * 176 + qq * 16;
            size_t go = (size_t)(m0 + r) * 80 + qq * 8;
            cpa16(sbA + off, g_dxhi + go);
            cpa16(sbA + XA_LO + off, g_dxlo + go);
        }
        cpa_commit();
        cpa_wait<0>();
        __syncthreads();

        float acc[10][4];
        #pragma unroll
        for (int j = 0; j < 10; ++j)
            #pragma unroll
            for (int p = 0; p < 4; ++p) acc[j][p] = 0.f;

        const int warp = qtid >> 5;          // 0..7
        const int arow = lane & 15;
        const int acol = (lane >> 4) << 3;

        #pragma unroll
        for (int ks = 0; ks < 80; ks += 16) {
            unsigned ah[4], al[4];
            ldmx4(ah, sbA + ((warp*16 + arow) * XAST + ks + acol) * 2);
            ldmx4(al, sbA + XA_LO + ((warp*16 + arow) * XAST + ks + acol) * 2);
            #pragma unroll
            for (int jb = 0; jb < 5; ++jb) {
                unsigned trh[4], trl[4], b0[2], b1[2], c0[2], c1[2];
                ldmx4(trh, sbB + ((jb*16 + arow) * XAST + ks + acol) * 2);
                ldmx4(trl, sbB + XB_LO + ((jb*16 + arow) * XAST + ks + acol) * 2);
                b0[0] = trh[0]; b0[1] = trh[2];
                b1[0] = trh[1]; b1[1] = trh[3];
                c0[0] = trl[0]; c0[1] = trl[2];
                c1[0] = trl[1]; c1[1] = trl[3];
                mma16816bf(acc[2*jb],   ah, b0);
                mma16816bf(acc[2*jb],   ah, c0);
                mma16816bf(acc[2*jb],   al, b0);
                mma16816bf(acc[2*jb+1], ah, b1);
                mma16816bf(acc[2*jb+1], ah, c1);
                mma16816bf(acc[2*jb+1], al, b1);
            }
        }

        const int er = lane >> 2, ec = (lane & 3) * 2;
        const int grow = m0 + warp*16 + er;
        #pragma unroll
        for (int j = 0; j < 10; ++j) {
            int gc = n0 + 8*j + ec;
            *(float2*)&g_xl[(size_t)grow * 400 + gc]       = make_float2(acc[j][0], acc[j][1]);
            *(float2*)&g_xl[(size_t)(grow + 8) * 400 + gc] = make_float2(acc[j][2], acc[j][3]);
        }
    }
}

// ---------------- GEMM2 on tensor cores (unchanged) ----------------
__global__ __launch_bounds__(256) void gemm2_mma(
    const float* __restrict__ b2, const float* __restrict__ bn2_s,
    const float* __restrict__ bn2_t, float* __restrict__ out)
{
    __shared__ __align__(16) __half sm2[3 * 6400];
    const int tid = threadIdx.x;
    const int warp = tid >> 5, lane = tid & 31;
    const int m0 = blockIdx.x * 32;
    const int wm = (warp >> 2) * 16;
    const int wn = (warp & 3) * 32;
    const unsigned sb = smem_u32(sm2);

    auto load_chunk = [&](int c, int s) {
        const unsigned st = sb + s * 12800;
        if (tid < 128) {
            int r = tid >> 2, q = tid & 3;
            cpa16(st + (r * 40 + q * 8) * 2, g_h1h + (size_t)(m0 + r) * H1 + c * 32 + q * 8);
        }
        #pragma unroll
        for (int t = 0; t < 2; ++t) {
            int i = tid + t * 256;
            int r = i >> 2, q = i & 3;
            cpa16(st + 2560 + (r * 40 + q * 8) * 2, g_W2h + (size_t)r * H1 + c * 32 + q * 8);
        }
        cpa_commit();
    };

    float acc[4][4];
    #pragma unroll
    for (int j = 0; j < 4; ++j)
        #pragma unroll
        for (int q = 0; q < 4; ++q) acc[j][q] = 0.f;

    load_chunk(0, 0);
    load_chunk(1, 1);

    const int arow = lane & 15;
    const int acol = (lane >> 4) << 3;

    for (int c = 0; c < 32; ++c) {
        const int s = c - (c / 3) * 3;
        if (c + 1 < 32) cpa_wait<1>(); else cpa_wait<0>();
        __syncthreads();
        if (c + 2 < 32) {
            int s2 = (c + 2) - ((c + 2) / 3) * 3;
            load_chunk(c + 2, s2);
        }
        const unsigned aA = sb + s * 12800;
        const unsigned bB = aA + 2560;
        #pragma unroll
        for (int ks = 0; ks < 32; ks += 16) {
            unsigned ah[4], bh[8];
            ldmx4(ah, aA + ((wm + arow) * 40 + ks + acol) * 2);
            #pragma unroll
            for (int j2 = 0; j2 < 2; ++j2) {
                unsigned tr[4];
                ldmx4(tr, bB + ((wn + j2*16 + arow) * 40 + ks + acol) * 2);
                bh[4*j2 + 0] = tr[0];  bh[4*j2 + 1] = tr[2];
                bh[4*j2 + 2] = tr[1];  bh[4*j2 + 3] = tr[3];
            }
            #pragma unroll
            for (int j = 0; j < 4; ++j)
                mma16816h(acc[j], ah, &bh[2*j]);
        }
    }

    const int er = lane >> 2, ec = (lane & 3) * 2;
    #pragma unroll
    for (int j = 0; j < 4; ++j) {
        int n = wn + j*8 + ec;
        if (n >= H2) continue;
        float a0 = bn2_s[n],   a1 = bn2_s[n+1];
        float e0 = b2[n]*a0 + bn2_t[n];
        float e1 = b2[n+1]*a1 + bn2_t[n+1];
        int m_a = m0 + wm + er, m_b = m_a + 8;
        float va0 = fmaxf(acc[j][0]*a0 + e0, 0.f);
        float va1 = fmaxf(acc[j][1]*a1 + e1, 0.f);
        float vb0 = fmaxf(acc[j][2]*a0 + e0, 0.f);
        float vb1 = fmaxf(acc[j][3]*a1 + e1, 0.f);
        size_t oa = (m_a < NB) ? ((size_t)m_a*H2 + n) : ((size_t)NB*H2 + (size_t)(m_a - NB)*H2 + n);
        size_t ob = (m_b < NB) ? ((size_t)m_b*H2 + n) : ((size_t)NB*H2 + (size_t)(m_b - NB)*H2 + n);
        out[oa] = va0;  out[oa + 1] = va1;
        out[ob] = vb0;  out[ob + 1] = vb1;
    }
}

// ---------------- Drug encoder v6 (+ fused resp) ----------------
#define VXL 201
#define VH  209
#define OXL 0
#define OH  12864
#define OWA 26240
#define OWB 26440
#define OTW 26640
#define OSC 26840
#define OFL 26904
#define OES 26968
#define OED 27096
#define OCN 27224
#define OST 27288
#define OCU 27353
#define OLS 27417
#define DTOT 27545
#define DRUG_SMEM_BYTES (DTOT * 4)
#define DRUG_GRID 296

__global__ __launch_bounds__(512, 2) void drug_kernel(
    const int* __restrict__ edge_index,
    const float* __restrict__ Wp, const float* __restrict__ bp,
    float* __restrict__ out)
{
    extern __shared__ float sm[];
    float* xl    = sm + OXL;
    float* hsh   = sm + OH;
    float* wa    = sm + OWA;
    float* wb    = sm + OWB;
    float* tw    = sm + OTW;
    float* score = sm + OSC;
    int*   flag  = (int*)(sm + OFL);
    int*   es    = (int*)(sm + OES);
    int*   ed    = (int*)(sm + OED);
    int*   cnt   = (int*)(sm + OCN);
    int*   start = (int*)(sm + OST);
    int*   cur   = (int*)(sm + OCU);
    int*   list  = (int*)(sm + OLS);

    const int tid = threadIdx.x;
    const int g0 = (int)(((long)blockIdx.x * NG) / DRUG_GRID);
    const int g1 = (int)(((long)(blockIdx.x + 1) * NG) / DRUG_GRID);
    const float winv = g_winv;

    if (tid < DN) { wa[tid] = g_wa2[tid]; wb[tid] = g_wb2[tid]; tw[tid] = g_tw[tid]; }
    __syncthreads();

    const int ni   = tid >> 3;
    const int part = tid & 7;
    const int c0   = part * 25;

    for (int g = g0; g < g1; ++g) {
        const int base = g * NPG;
        for (int i = tid; i < NPG * DN; i += 512) {
            int nn = i / DN, c = i - nn * DN;
            xl[nn * VXL + c] = g_xl[(size_t)(base + nn) * 400 + c];
        }
        if (tid < EPG) {
            es[tid] = edge_index[g*EPG + tid] - base;
            ed[tid] = edge_index[ET_TOT + g*EPG + tid] - base;
        }
        if (tid < NPG) cnt[tid] = 0;
        __syncthreads();
        if (tid < EPG) atomicAdd(&cnt[ed[tid]], 1);
        __syncthreads();
        if (tid == 0) {
            int run = 0;
            for (int nn = 0; nn < NPG; ++nn) { start[nn] = run; run += cnt[nn]; }
            start[NPG] = run;
        }
        __syncthreads();
        if (tid < NPG) cur[tid] = start[tid];
        __syncthreads();
        if (tid < EPG) {
            int pos = atomicAdd(&cur[ed[tid]], 1);
            list[pos] = es[tid];
        }
        __syncthreads();

        {
            float acc[25];
            const float* xr = g_xl + (size_t)(base + ni) * 400 + DN + c0;
            #pragma unroll
            for (int c = 0; c < 25; ++c) acc[c] = xr[c];
            const int b0 = start[ni], b1 = start[ni + 1];
            for (int e = b0; e < b1; ++e) {
                const float* xp = xl + list[e] * VXL + c0;
                #pragma unroll
                for (int c = 0; c < 25; ++c) acc[c] += xp[c];
            }
            #pragma unroll
            for (int c = 0; c < 25; ++c) {
                int cc = c0 + c;
                hsh[ni * VH + cc] = fmaxf(acc[c] * wa[cc] + wb[cc], 0.f);
            }
        }
        __syncthreads();

        {
            float s = 0.f;
            const float* hp  = &hsh[ni * VH + c0];
            const float* twp = &tw[c0];
            #pragma unroll
            for (int c = 0; c < 25; ++c) s += hp[c] * twp[c];
            s += __shfl_xor_sync(0xffffffffu, s, 1);
            s += __shfl_xor_sync(0xffffffffu, s, 2);
            s += __shfl_xor_sync(0xffffffffu, s, 4);
            if (part == 0) score[ni] = tanhf(s * winv);
        }
        __syncthreads();
        if (tid < NPG) {
            float sn = score[tid];
            int r = 0;
            for (int m2 = 0; m2 < NPG; ++m2) {
                float sv = score[m2];
                r += (sv > sn) || (sv == sn && m2 < tid);
            }
            flag[tid] = (r < KTOP) ? 1 : 0;
        }
        __syncthreads();
        if (tid < DN) {
            const int c = tid;
            float mx = -1e30f, sum = 0.f, mxs = -1e30f, sums = 0.f;
            for (int n2 = 0; n2 < NPG; ++n2) {
                float v = hsh[n2 * VH + c];
                mx = fmaxf(mx, v); sum += v;
                if (flag[n2]) {
                    float w = v * score[n2];
                    mxs = fmaxf(mxs, w); sums += w;
                }
            }
            g_dx[(size_t)g*400 + c]      = fmaxf(mx + 3.f*mxs, 0.f);
            g_dx[(size_t)g*400 + DN + c] = fmaxf(sum*(1.f/NPG) + 3.f*(sums*(1.f/KTOP)), 0.f);
        }
        __syncthreads();
        // fused resp: resp[g] = [f1[g] | dx[g]] . Wp + bp
        if (tid < 32) {
            float s = 0.f;
            for (int i = tid; i < 500; i += 32) {
                float z = (i < H2) ? out[(size_t)g*H2 + i] : g_dx[(size_t)g*400 + (i - H2)];
                s += z * Wp[i];
            }
            #pragma unroll
            for (int o = 16; o; o >>= 1) s += __shfl_down_sync(0xffffffffu, s, o);
            if (tid == 0) out[(size_t)2*NB*H2 + g] = s + bp[0];
        }
        __syncthreads();
    }
}

extern "C" void kernel_launch(void* const* d_in, const int* in_sizes, int n_in,
                              void* d_out, int out_size)
{
    const float* x1     = (const float*)d_in[0];
    const float* x2     = (const float*)d_in[1];
    const int*   eidx   = (const int*)d_in[4];
    const float* drug_x = (const float*)d_in[5];
    const float* bn0_s  = (const float*)d_in[6];
    const float* bn0_t  = (const float*)d_in[7];
    const float* W1     = (const float*)d_in[8];
    const float* b1     = (const float*)d_in[9];
    const float* bn1_s  = (const float*)d_in[10];
    const float* bn1_t  = (const float*)d_in[11];
    const float* W2     = (const float*)d_in[12];
    const float* b2     = (const float*)d_in[13];
    const float* bn2_s  = (const float*)d_in[14];
    const float* bn2_t  = (const float*)d_in[15];
    const float* Wrel   = (const float*)d_in[16];
    const float* brel   = (const float*)d_in[17];
    const float* Wroot  = (const float*)d_in[18];
    const float* bnd_s  = (const float*)d_in[19];
    const float* bnd_t  = (const float*)d_in[20];
    const float* topk_w = (const float*)d_in[21];
    const float* Wp     = (const float*)d_in[22];
    const float* bp     = (const float*)d_in[23];
    float* out = (float*)d_out;

    cudaFuncSetAttribute(drug_kernel, cudaFuncAttributeMaxDynamicSharedMemorySize, DRUG_SMEM_BYTES);
    cudaFuncSetAttribute(mega_g1xl, cudaFuncAttributeMaxDynamicSharedMemorySize, MEGA_DSMEM);

    prep_all<<<(int)((R5 + 255) / 256), 256>>>(x1, x2, W1, W2, bn0_s, bn0_t,
                                               drug_x, Wrel, Wroot, brel,
                                               bnd_s, bnd_t, topk_w);
    mega_g1xl<<<128 + 1280, 1024, MEGA_DSMEM>>>(b1, bn1_s, bn1_t);
    gemm2_mma<<<M_TOT / 32, 256>>>(b2, bn2_s, bn2_t, out);
    drug_kernel<<<DRUG_GRID, 512, DRUG_SMEM_BYTES>>>(eidx, Wp, bp, out);
}

// round 14
// speedup vs baseline: 1.8516x; 1.0141x over previous
#include <cuda_runtime.h>
#include <cuda_bf16.h>
#include <cuda_fp16.h>
#include <math.h>
#include <stdint.h>

#define NB      2048
#define EXPR    8000
#define H1      1024
#define H2      100
#define M_TOT   4096
#define DD      78
#define DN      200
#define NPG     64
#define EPG     128
#define NG      2048
#define NT_ALL  131072
#define ET_TOT  262144
#define KTOP    52

__device__ __half g_h1h[(size_t)M_TOT * H1];
__device__ float g_dx[NG * 400];
__device__ __half g_Ah[(size_t)M_TOT * EXPR];
__device__ __half g_Bh[(size_t)H1 * EXPR];
__device__ __half g_W2h[(size_t)128 * H1];
__device__ __nv_bfloat16 g_dxhi[(size_t)NT_ALL * 80];
__device__ __nv_bfloat16 g_dxlo[(size_t)NT_ALL * 80];
__device__ __nv_bfloat16 g_wxhi[400 * 80];
__device__ __nv_bfloat16 g_wxlo[400 * 80];
__device__ float g_xlrel[(size_t)NT_ALL * 200];
__device__ float g_xlroot[(size_t)NT_ALL * 200];
__device__ float g_wa2[DN], g_wb2[DN];
__device__ float g_tw[DN];
__device__ float g_winv;

__device__ __forceinline__ unsigned smem_u32(const void* p) {
    unsigned a;
    asm("{ .reg .u64 t; cvta.to.shared.u64 t, %1; cvt.u32.u64 %0, t; }" : "=r"(a) : "l"(p));
    return a;
}
__device__ __forceinline__ void cpa16(unsigned s, const void* g) {
    asm volatile("cp.async.cg.shared.global [%0], [%1], 16;" :: "r"(s), "l"(g));
}
__device__ __forceinline__ void cpa_commit() { asm volatile("cp.async.commit_group;" ::: "memory"); }
template<int N> __device__ __forceinline__ void cpa_wait() {
    asm volatile("cp.async.wait_group %0;" :: "n"(N) : "memory");
}
__device__ __forceinline__ void ldmx4(unsigned* r, unsigned addr) {
    asm volatile("ldmatrix.sync.aligned.m8n8.x4.shared.b16 {%0,%1,%2,%3}, [%4];"
        : "=r"(r[0]), "=r"(r[1]), "=r"(r[2]), "=r"(r[3]) : "r"(addr));
}
__device__ __forceinline__ void mma16816bf(float* d, const unsigned* a, const unsigned* b) {
    asm volatile("mma.sync.aligned.m16n8k16.row.col.f32.bf16.bf16.f32 "
        "{%0,%1,%2,%3}, {%4,%5,%6,%7}, {%8,%9}, {%0,%1,%2,%3};"
        : "+f"(d[0]), "+f"(d[1]), "+f"(d[2]), "+f"(d[3])
        : "r"(a[0]), "r"(a[1]), "r"(a[2]), "r"(a[3]), "r"(b[0]), "r"(b[1]));
}
__device__ __forceinline__ void mma16816h(float* d, const unsigned* a, const unsigned* b) {
    asm volatile("mma.sync.aligned.m16n8k16.row.col.f32.f16.f16.f32 "
        "{%0,%1,%2,%3}, {%4,%5,%6,%7}, {%8,%9}, {%0,%1,%2,%3};"
        : "+f"(d[0]), "+f"(d[1]), "+f"(d[2]), "+f"(d[3])
        : "r"(a[0]), "r"(a[1]), "r"(a[2]), "r"(a[3]), "r"(b[0]), "r"(b[1]));
}

__device__ __forceinline__ void conv4h(__half* dst, float4 v) {
    union { __half b[4]; uint2 u; } H;
    H.b[0]=__float2half_rn(v.x); H.b[1]=__float2half_rn(v.y);
    H.b[2]=__float2half_rn(v.z); H.b[3]=__float2half_rn(v.w);
    *(uint2*)dst = H.u;
}
__device__ __forceinline__ void split2(__nv_bfloat16* hi, __nv_bfloat16* lo, float a, float b) {
    __nv_bfloat16 h0=__float2bfloat16_rn(a), h1=__float2bfloat16_rn(b);
    union { __nv_bfloat16 v[2]; unsigned u; } H, L;
    H.v[0]=h0; H.v[1]=h1;
    L.v[0]=__float2bfloat16_rn(a-__bfloat162float(h0));
    L.v[1]=__float2bfloat16_rn(b-__bfloat162float(h1));
    *(unsigned*)hi = H.u;  *(unsigned*)lo = L.u;
}

// ---------------- prep_all ----------------
#define R0 ((long)M_TOT * 2000)
#define R1 (R0 + (long)H1 * 2000)
#define R2 (R1 + 128 * 256)
#define R3 (R2 + (long)NT_ALL * 40)
#define R4 (R3 + 400 * 40)
#define R5 (R4 + 256)

__global__ __launch_bounds__(256) void prep_all(
    const float* __restrict__ x1, const float* __restrict__ x2,
    const float* __restrict__ W1, const float* __restrict__ W2,
    const float* __restrict__ bn0_s, const float* __restrict__ bn0_t,
    const float* __restrict__ dx,
    const float* __restrict__ Wrel, const float* __restrict__ Wroot,
    const float* __restrict__ brel,
    const float* __restrict__ bnd_s, const float* __restrict__ bnd_t,
    const float* __restrict__ topk_w)
{
    long i = (long)blockIdx.x * 256 + threadIdx.x;
    if (i >= R5) return;
    if (i < R0) {
        int row = (int)(i / 2000), k4 = (int)(i % 2000);
        const float* src = (row < NB) ? (x1 + (size_t)row * EXPR) : (x2 + (size_t)(row - NB) * EXPR);
        float4 v = *(const float4*)(src + k4 * 4);
        float4 s = *(const float4*)(bn0_s + k4 * 4);
        float4 t = *(const float4*)(bn0_t + k4 * 4);
        v.x = v.x*s.x + t.x;  v.y = v.y*s.y + t.y;  v.z = v.z*s.z + t.z;  v.w = v.w*s.w + t.w;
        conv4h(g_Ah + (size_t)row * EXPR + (size_t)k4 * 4, v);
    } else if (i < R1) {
        long j = i - R0;
        int row = (int)(j / 2000), k4 = (int)(j % 2000);
        float4 v = *(const float4*)(W1 + (size_t)row * EXPR + k4 * 4);
        conv4h(g_Bh + (size_t)row * EXPR + (size_t)k4 * 4, v);
    } else if (i < R2) {
        long j = i - R1;
        int row = (int)(j >> 8), k4 = (int)(j & 255);
        float4 v = make_float4(0.f, 0.f, 0.f, 0.f);
        if (row < H2) v = *(const float4*)(W2 + (size_t)row * H1 + k4 * 4);
        conv4h(g_W2h + (size_t)row * H1 + k4 * 4, v);
    } else if (i < R3) {
        long j = i - R2;
        int n = (int)(j / 40), kp = (int)(j % 40);
        int k0 = 2 * kp;
        float a = (k0     < DD) ? dx[(size_t)n * DD + k0]     : 0.f;
        float b = (k0 + 1 < DD) ? dx[(size_t)n * DD + k0 + 1] : 0.f;
        size_t eo = (size_t)n * 80 + k0;
        split2(g_dxhi + eo, g_dxlo + eo, a, b);
    } else if (i < R4) {
        long j = i - R3;
        int n = (int)(j / 40), kp = (int)(j % 40);
        int k0 = 2 * kp;
        float a = 0.f, b = 0.f;
        if (k0 < DD)     a = (n < DN) ? Wrel[n*DD + k0]     : Wroot[(n-DN)*DD + k0];
        if (k0 + 1 < DD) b = (n < DN) ? Wrel[n*DD + k0 + 1] : Wroot[(n-DN)*DD + k0 + 1];
        split2(g_wxhi + n*80 + k0, g_wxlo + n*80 + k0, a, b);
    } else {
        int j = (int)(i - R4);
        if (j < DN) {
            float al = bnd_s[j];
            g_wa2[j] = al;
            g_wb2[j] = brel[j]*al + bnd_t[j];
            g_tw[j]  = topk_w[j];
        }
        if (j == 0) {
            float s = 0.f;
            for (int c = 0; c < DN; ++c) s += topk_w[c]*topk_w[c];
            g_winv = rsqrtf(s);
        }
    }
}

// ---------------- MEGA: gemm1 (bid<128) + xl (bid>=128) ----------------
#define KC    32
#define NCH   250
#define AST   40
#define OFF_A 0
#define OFF_B 20480
#define STG   30720
#define XAST  88
#define XB_LO 14080
#define XA_BASE 28160
#define XA_LO 22528
#define XA_PER 45056
#define MEGA_DSMEM (XA_BASE + 4 * XA_PER)

__global__ void __launch_bounds__(1024, 1) mega_g1xl(
    const float* __restrict__ b1, const float* __restrict__ bn1_s,
    const float* __restrict__ bn1_t)
{
    extern __shared__ char dynsm[];
    __shared__ float s_alpha[128], s_beta[128];
    const unsigned sb = smem_u32(dynsm);
    const int tid = threadIdx.x;
    const int bid = blockIdx.x;
    const int lane = tid & 31;

    if (bid < 128) {
        const int warp = tid >> 5;
        const int m0 = (bid >> 3) * 256;
        const int n0 = (bid & 7) * 128;
        const int wm = (warp >> 2) * 32;
        const int wn = (warp & 3) * 32;

        if (tid < 128) {
            float al = bn1_s[n0 + tid];
            s_alpha[tid] = al;
            s_beta[tid]  = b1[n0 + tid] * al + bn1_t[n0 + tid];
        }

        auto load_chunk = [&](int c, int s) {
            const unsigned st = sb + s * STG;
            const long k0 = (long)c * KC;
            {
                int r = tid >> 2, q = tid & 3;
                unsigned off = r * 80 + q * 16;
                size_t go = (size_t)(m0 + r) * EXPR + k0 + q * 8;
                cpa16(st + OFF_A + off, g_Ah + go);
            }
            if (tid < 512) {
                int r = tid >> 2, q = tid & 3;
                unsigned off = r * 80 + q * 16;
                size_t go = (size_t)(n0 + r) * EXPR + k0 + q * 8;
                cpa16(st + OFF_B + off, g_Bh + go);
            }
            cpa_commit();
        };

        float acc[2][4][4];
        #pragma unroll
        for (int i = 0; i < 2; ++i)
            #pragma unroll
            for (int j = 0; j < 4; ++j)
                #pragma unroll
                for (int q = 0; q < 4; ++q) acc[i][j][q] = 0.f;

        load_chunk(0, 0);
        load_chunk(1, 1);

        const int arow = lane & 15;
        const int acol = (lane >> 4) << 3;

        for (int c = 0; c < NCH; ++c) {
            const int s = c - (c / 3) * 3;
            if (c + 1 < NCH) cpa_wait<1>(); else cpa_wait<0>();
            __syncthreads();
            if (c + 2 < NCH) {
                int s2 = (c + 2) - ((c + 2) / 3) * 3;
                load_chunk(c + 2, s2);
            }
            const unsigned aA = sb + s * STG;
            const unsigned bB = aA + OFF_B;
            #pragma unroll
            for (int ks = 0; ks < KC; ks += 16) {
                unsigned ah[8], bh[8];
                #pragma unroll
                for (int i = 0; i < 2; ++i)
                    ldmx4(&ah[4*i], aA + ((wm + i*16 + arow) * AST + ks + acol) * 2);
                #pragma unroll
                for (int j2 = 0; j2 < 2; ++j2) {
                    unsigned tr[4];
                    ldmx4(tr, bB + ((wn + j2*16 + arow) * AST + ks + acol) * 2);
                    bh[4*j2 + 0] = tr[0];  bh[4*j2 + 1] = tr[2];
                    bh[4*j2 + 2] = tr[1];  bh[4*j2 + 3] = tr[3];
                }
                #pragma unroll
                for (int i = 0; i < 2; ++i)
                    #pragma unroll
                    for (int j = 0; j < 4; ++j)
                        mma16816h(acc[i][j], &ah[4*i], &bh[2*j]);
            }
        }

        const int er = lane >> 2, ec = (lane & 3) * 2;
        #pragma unroll
        for (int i = 0; i < 2; ++i) {
            #pragma unroll
            for (int j = 0; j < 4; ++j) {
                int nl = wn + j*8 + ec;
                float a0 = s_alpha[nl], a1 = s_alpha[nl+1];
                float e0 = s_beta[nl],  e1 = s_beta[nl+1];
                int mg0 = m0 + wm + i*16 + er;
                __half2 h0 = __floats2half2_rn(fmaxf(acc[i][j][0]*a0 + e0, 0.f),
                                               fmaxf(acc[i][j][1]*a1 + e1, 0.f));
                __half2 h1v = __floats2half2_rn(fmaxf(acc[i][j][2]*a0 + e0, 0.f),
                                                fmaxf(acc[i][j][3]*a1 + e1, 0.f));
                *(__half2*)&g_h1h[(size_t)mg0 * H1 + n0 + nl]       = h0;
                *(__half2*)&g_h1h[(size_t)(mg0 + 8) * H1 + n0 + nl] = h1v;
            }
        }
    } else {
        const int bid2 = bid - 128;
        const int nt = bid2 >> 8;
        const int mt = bid2 & 255;
        const int q  = tid >> 8;
        const int qtid = tid & 255;
        const int m0 = (mt * 4 + q) * 128;
        const int n0 = nt * 80;
        const unsigned sbB = sb;
        const unsigned sbA = sb + XA_BASE + q * XA_PER;

        if (tid < 800) {
            int r = tid / 10, qq = tid - r * 10;
            unsigned off = r * 176 + qq * 16;
            size_t go = (size_t)(n0 + r) * 80 + qq * 8;
            cpa16(sbB + off, g_wxhi + go);
            cpa16(sbB + XB_LO + off, g_wxlo + go);
        }
        #pragma unroll
        for (int t = 0; t < 5; ++t) {
            int i = qtid + t * 256;
            int r = i / 10, qq = i - r * 10;
            unsigned off = r * 176 + qq * 16;
            size_t go = (size_t)(m0 + r) * 80 + qq * 8;
            cpa16(sbA + off, g_dxhi + go);
            cpa16(sbA + XA_LO + off, g_dxlo + go);
        }
        cpa_commit();
        cpa_wait<0>();
        __syncthreads();

        float acc[10][4];
        #pragma unroll
        for (int j = 0; j < 10; ++j)
            #pragma unroll
            for (int p = 0; p < 4; ++p) acc[j][p] = 0.f;

        const int warp = qtid >> 5;
        const int arow = lane & 15;
        const int acol = (lane >> 4) << 3;

        #pragma unroll
        for (int ks = 0; ks < 80; ks += 16) {
            unsigned ah[4], al[4];
            ldmx4(ah, sbA + ((warp*16 + arow) * XAST + ks + acol) * 2);
            ldmx4(al, sbA + XA_LO + ((warp*16 + arow) * XAST + ks + acol) * 2);
            #pragma unroll
            for (int jb = 0; jb < 5; ++jb) {
                unsigned trh[4], trl[4], b0[2], b1[2], c0[2], c1[2];
                ldmx4(trh, sbB + ((jb*16 + arow) * XAST + ks + acol) * 2);
                ldmx4(trl, sbB + XB_LO + ((jb*16 + arow) * XAST + ks + acol) * 2);
                b0[0] = trh[0]; b0[1] = trh[2];
                b1[0] = trh[1]; b1[1] = trh[3];
                c0[0] = trl[0]; c0[1] = trl[2];
                c1[0] = trl[1]; c1[1] = trl[3];
                mma16816bf(acc[2*jb],   ah, b0);
                mma16816bf(acc[2*jb],   ah, c0);
                mma16816bf(acc[2*jb],   al, b0);
                mma16816bf(acc[2*jb+1], ah, b1);
                mma16816bf(acc[2*jb+1], ah, c1);
                mma16816bf(acc[2*jb+1], al, b1);
            }
        }

        const int er = lane >> 2, ec = (lane & 3) * 2;
        const int grow = m0 + warp*16 + er;
        #pragma unroll
        for (int j = 0; j < 10; ++j) {
            int gc = n0 + 8*j + ec;
            float2 v0 = make_float2(acc[j][0], acc[j][1]);
            float2 v1 = make_float2(acc[j][2], acc[j][3]);
            if (gc < 200) {
                *(float2*)&g_xlrel[(size_t)grow * 200 + gc]       = v0;
                *(float2*)&g_xlrel[(size_t)(grow + 8) * 200 + gc] = v1;
            } else {
                *(float2*)&g_xlroot[(size_t)grow * 200 + gc - 200]       = v0;
                *(float2*)&g_xlroot[(size_t)(grow + 8) * 200 + gc - 200] = v1;
            }
        }
    }
}

// ---------------- GEMM2 on tensor cores (unchanged) ----------------
__global__ __launch_bounds__(256) void gemm2_mma(
    const float* __restrict__ b2, const float* __restrict__ bn2_s,
    const float* __restrict__ bn2_t, float* __restrict__ out)
{
    __shared__ __align__(16) __half sm2[3 * 6400];
    const int tid = threadIdx.x;
    const int warp = tid >> 5, lane = tid & 31;
    const int m0 = blockIdx.x * 32;
    const int wm = (warp >> 2) * 16;
    const int wn = (warp & 3) * 32;
    const unsigned sb = smem_u32(sm2);

    auto load_chunk = [&](int c, int s) {
        const unsigned st = sb + s * 12800;
        if (tid < 128) {
            int r = tid >> 2, q = tid & 3;
            cpa16(st + (r * 40 + q * 8) * 2, g_h1h + (size_t)(m0 + r) * H1 + c * 32 + q * 8);
        }
        #pragma unroll
        for (int t = 0; t < 2; ++t) {
            int i = tid + t * 256;
            int r = i >> 2, q = i & 3;
            cpa16(st + 2560 + (r * 40 + q * 8) * 2, g_W2h + (size_t)r * H1 + c * 32 + q * 8);
        }
        cpa_commit();
    };

    float acc[4][4];
    #pragma unroll
    for (int j = 0; j < 4; ++j)
        #pragma unroll
        for (int q = 0; q < 4; ++q) acc[j][q] = 0.f;

    load_chunk(0, 0);
    load_chunk(1, 1);

    const int arow = lane & 15;
    const int acol = (lane >> 4) << 3;

    for (int c = 0; c < 32; ++c) {
        const int s = c - (c / 3) * 3;
        if (c + 1 < 32) cpa_wait<1>(); else cpa_wait<0>();
        __syncthreads();
        if (c + 2 < 32) {
            int s2 = (c + 2) - ((c + 2) / 3) * 3;
            load_chunk(c + 2, s2);
        }
        const unsigned aA = sb + s * 12800;
        const unsigned bB = aA + 2560;
        #pragma unroll
        for (int ks = 0; ks < 32; ks += 16) {
            unsigned ah[4], bh[8];
            ldmx4(ah, aA + ((wm + arow) * 40 + ks + acol) * 2);
            #pragma unroll
            for (int j2 = 0; j2 < 2; ++j2) {
                unsigned tr[4];
                ldmx4(tr, bB + ((wn + j2*16 + arow) * 40 + ks + acol) * 2);
                bh[4*j2 + 0] = tr[0];  bh[4*j2 + 1] = tr[2];
                bh[4*j2 + 2] = tr[1];  bh[4*j2 + 3] = tr[3];
            }
            #pragma unroll
            for (int j = 0; j < 4; ++j)
                mma16816h(acc[j], ah, &bh[2*j]);
        }
    }

    const int er = lane >> 2, ec = (lane & 3) * 2;
    #pragma unroll
    for (int j = 0; j < 4; ++j) {
        int n = wn + j*8 + ec;
        if (n >= H2) continue;
        float a0 = bn2_s[n],   a1 = bn2_s[n+1];
        float e0 = b2[n]*a0 + bn2_t[n];
        float e1 = b2[n+1]*a1 + bn2_t[n+1];
        int m_a = m0 + wm + er, m_b = m_a + 8;
        float va0 = fmaxf(acc[j][0]*a0 + e0, 0.f);
        float va1 = fmaxf(acc[j][1]*a1 + e1, 0.f);
        float vb0 = fmaxf(acc[j][2]*a0 + e0, 0.f);
        float vb1 = fmaxf(acc[j][3]*a1 + e1, 0.f);
        size_t oa = (m_a < NB) ? ((size_t)m_a*H2 + n) : ((size_t)NB*H2 + (size_t)(m_a - NB)*H2 + n);
        size_t ob = (m_b < NB) ? ((size_t)m_b*H2 + n) : ((size_t)NB*H2 + (size_t)(m_b - NB)*H2 + n);
        out[oa] = va0;  out[oa + 1] = va1;
        out[ob] = vb0;  out[ob + 1] = vb1;
    }
}

// ---------------- Drug encoder v7: parallel rank/readout/scan ----------------
#define VXL 201
#define VH  209
#define OXL 0
#define OH  12864
#define OWA 26240
#define OWB 26440
#define OTW 26640
#define OSC 26840
#define OFL 26904
#define OES 26968
#define OED 27096
#define OCN 27224
#define OST 27288
#define OCU 27353
#define OLS 27417
#define DTOT 27545
#define DRUG_SMEM_BYTES (DTOT * 4)
#define DRUG_GRID 296

__global__ __launch_bounds__(512, 2) void drug_kernel(
    const int* __restrict__ edge_index,
    const float* __restrict__ Wp, const float* __restrict__ bp,
    float* __restrict__ out)
{
    extern __shared__ float sm[];
    float* xl    = sm + OXL;       // also reused as reduction scratch after h-compute
    float* hsh   = sm + OH;
    float* wa    = sm + OWA;
    float* wb    = sm + OWB;
    float* tw    = sm + OTW;
    float* score = sm + OSC;
    int*   flag  = (int*)(sm + OFL);
    int*   es    = (int*)(sm + OES);
    int*   ed    = (int*)(sm + OED);
    int*   cnt   = (int*)(sm + OCN);
    int*   start = (int*)(sm + OST);
    int*   cur   = (int*)(sm + OCU);
    int*   list  = (int*)(sm + OLS);

    const int tid = threadIdx.x;
    const int lane = tid & 31;
    const int g0 = (int)(((long)blockIdx.x * NG) / DRUG_GRID);
    const int g1 = (int)(((long)(blockIdx.x + 1) * NG) / DRUG_GRID);
    const float winv = g_winv;

    if (tid < DN) { wa[tid] = g_wa2[tid]; wb[tid] = g_wb2[tid]; tw[tid] = g_tw[tid]; }
    __syncthreads();

    const int ni   = tid >> 3;
    const int part = tid & 7;
    const int c0   = part * 25;

    for (int g = g0; g < g1; ++g) {
        const int base = g * NPG;
        // stage rel-xl (contiguous rows of 200)
        for (int i = tid; i < NPG * DN; i += 512) {
            int nn = i / DN, c = i - nn * DN;
            xl[nn * VXL + c] = g_xlrel[(size_t)(base + nn) * 200 + c];
        }
        if (tid < EPG) {
            es[tid] = edge_index[g*EPG + tid] - base;
            ed[tid] = edge_index[ET_TOT + g*EPG + tid] - base;
        }
        if (tid < NPG) cnt[tid] = 0;
        __syncthreads();
        if (tid < EPG) atomicAdd(&cnt[ed[tid]], 1);
        __syncthreads();
        // warp-scan CSR prefix (writes start AND cur)
        if (tid < 32) {
            int ca = cnt[2*tid], cb = cnt[2*tid+1];
            int pairv = ca + cb;
            int s = pairv;
            #pragma unroll
            for (int o = 1; o < 32; o <<= 1) {
                int t = __shfl_up_sync(0xffffffffu, s, o);
                if (lane >= o) s += t;
            }
            int excl = s - pairv;
            start[2*tid] = excl;        cur[2*tid] = excl;
            start[2*tid+1] = excl + ca; cur[2*tid+1] = excl + ca;
            if (tid == 31) start[64] = s;
        }
        __syncthreads();
        if (tid < EPG) {
            int pos = atomicAdd(&cur[ed[tid]], 1);
            list[pos] = es[tid];
        }
        __syncthreads();

        // h = relu((sum_in xl_rel[src] + x@Wroot + brel)*s + t)
        {
            float acc[25];
            const float* xr = g_xlroot + (size_t)(base + ni) * 200 + c0;
            #pragma unroll
            for (int c = 0; c < 25; ++c) acc[c] = xr[c];
            const int b0 = start[ni], b1 = start[ni + 1];
            for (int e = b0; e < b1; ++e) {
                const float* xp = xl + list[e] * VXL + c0;
                #pragma unroll
                for (int c = 0; c < 25; ++c) acc[c] += xp[c];
            }
            #pragma unroll
            for (int c = 0; c < 25; ++c) {
                int cc = c0 + c;
                hsh[ni * VH + cc] = fmaxf(acc[c] * wa[cc] + wb[cc], 0.f);
            }
        }
        __syncthreads();

        // score (all 512 threads)
        {
            float s = 0.f;
            const float* hp  = &hsh[ni * VH + c0];
            const float* twp = &tw[c0];
            #pragma unroll
            for (int c = 0; c < 25; ++c) s += hp[c] * twp[c];
            s += __shfl_xor_sync(0xffffffffu, s, 1);
            s += __shfl_xor_sync(0xffffffffu, s, 2);
            s += __shfl_xor_sync(0xffffffffu, s, 4);
            if (part == 0) score[ni] = tanhf(s * winv);
        }
        __syncthreads();

        // parallel rank: 64 nodes x 8 partials
        {
            float sn = score[ni];
            int r = 0;
            #pragma unroll
            for (int m2 = part*8; m2 < part*8 + 8; ++m2) {
                float sv = score[m2];
                r += (sv > sn) || (sv == sn && m2 < ni);
            }
            r += __shfl_xor_sync(0xffffffffu, r, 1);
            r += __shfl_xor_sync(0xffffffffu, r, 2);
            r += __shfl_xor_sync(0xffffffffu, r, 4);
            if (part == 0) flag[ni] = (r < KTOP) ? 1 : 0;
        }
        __syncthreads();

        // parallel readout: 400 threads = 200 cols x 2 node-halves (xl region reused)
        if (tid < 400) {
            int c = (tid < 200) ? tid : tid - 200;
            int h = (tid < 200) ? 0 : 1;
            float mx = -1e30f, sum = 0.f, mxs = -1e30f, sums = 0.f;
            for (int n2 = h*32; n2 < h*32 + 32; ++n2) {
                float v = hsh[n2 * VH + c];
                mx = fmaxf(mx, v); sum += v;
                if (flag[n2]) {
                    float w = v * score[n2];
                    mxs = fmaxf(mxs, w); sums += w;
                }
            }
            xl[tid]        = mx;
            xl[400 + tid]  = sum;
            xl[800 + tid]  = mxs;
            xl[1200 + tid] = sums;
        }
        __syncthreads();
        // combine + write dx (also cache into smem for resp)
        if (tid < 200) {
            float mx   = fmaxf(xl[tid], xl[200 + tid]);
            float sum  = xl[400 + tid] + xl[600 + tid];
            float mxs  = fmaxf(xl[800 + tid], xl[1000 + tid]);
            float sums = xl[1200 + tid] + xl[1400 + tid];
            float d0 = fmaxf(mx + 3.f*mxs, 0.f);
            float d1 = fmaxf(sum*(1.f/NPG) + 3.f*(sums*(1.f/KTOP)), 0.f);
            g_dx[(size_t)g*400 + tid]      = d0;
            g_dx[(size_t)g*400 + DN + tid] = d1;
            xl[1600 + tid] = d0;
            xl[1800 + tid] = d1;
        }
        __syncthreads();
        // fused resp from smem dx + global f1
        if (tid < 32) {
            float s = 0.f;
            for (int i = tid; i < 100; i += 32) s += out[(size_t)g*H2 + i] * Wp[i];
            for (int i = tid; i < 400; i += 32) s += xl[1600 + i] * Wp[100 + i];
            #pragma unroll
            for (int o = 16; o; o >>= 1) s += __shfl_down_sync(0xffffffffu, s, o);
            if (tid == 0) out[(size_t)2*NB*H2 + g] = s + bp[0];
        }
        __syncthreads();
    }
}

extern "C" void kernel_launch(void* const* d_in, const int* in_sizes, int n_in,
                              void* d_out, int out_size)
{
    const float* x1     = (const float*)d_in[0];
    const float* x2     = (const float*)d_in[1];
    const int*   eidx   = (const int*)d_in[4];
    const float* drug_x = (const float*)d_in[5];
    const float* bn0_s  = (const float*)d_in[6];
    const float* bn0_t  = (const float*)d_in[7];
    const float* W1     = (const float*)d_in[8];
    const float* b1     = (const float*)d_in[9];
    const float* bn1_s  = (const float*)d_in[10];
    const float* bn1_t  = (const float*)d_in[11];
    const float* W2     = (const float*)d_in[12];
    const float* b2     = (const float*)d_in[13];
    const float* bn2_s  = (const float*)d_in[14];
    const float* bn2_t  = (const float*)d_in[15];
    const float* Wrel   = (const float*)d_in[16];
    const float* brel   = (const float*)d_in[17];
    const float* Wroot  = (const float*)d_in[18];
    const float* bnd_s  = (const float*)d_in[19];
    const float* bnd_t  = (const float*)d_in[20];
    const float* topk_w = (const float*)d_in[21];
    const float* Wp     = (const float*)d_in[22];
    const float* bp     = (const float*)d_in[23];
    float* out = (float*)d_out;

    cudaFuncSetAttribute(drug_kernel, cudaFuncAttributeMaxDynamicSharedMemorySize, DRUG_SMEM_BYTES);
    cudaFuncSetAttribute(mega_g1xl, cudaFuncAttributeMaxDynamicSharedMemorySize, MEGA_DSMEM);

    prep_all<<<(int)((R5 + 255) / 256), 256>>>(x1, x2, W1, W2, bn0_s, bn0_t,
                                               drug_x, Wrel, Wroot, brel,
                                               bnd_s, bnd_t, topk_w);
    mega_g1xl<<<128 + 1280, 1024, MEGA_DSMEM>>>(b1, bn1_s, bn1_t);
    gemm2_mma<<<M_TOT / 32, 256>>>(b2, bn2_s, bn2_t, out);
    drug_kernel<<<DRUG_GRID, 512, DRUG_SMEM_BYTES>>>(eidx, Wp, bp, out);
}

// round 15
// speedup vs baseline: 1.9508x; 1.0536x over previous
#include <cuda_runtime.h>
#include <cuda_bf16.h>
#include <cuda_fp16.h>
#include <math.h>
#include <stdint.h>

#define NB      2048
#define EXPR    8000
#define H1      1024
#define H2      100
#define M_TOT   4096
#define DD      78
#define DN      200
#define NPG     64
#define EPG     128
#define NG      2048
#define NT_ALL  131072
#define ET_TOT  262144
#define KTOP    52

__device__ __half g_h1h[(size_t)M_TOT * H1];
__device__ __half g_Ah[(size_t)M_TOT * EXPR];
__device__ __half g_Bh[(size_t)H1 * EXPR];
__device__ __half g_W2h[(size_t)128 * H1];
__device__ __nv_bfloat16 g_dxhi[(size_t)NT_ALL * 80];
__device__ __nv_bfloat16 g_dxlo[(size_t)NT_ALL * 80];
__device__ __nv_bfloat16 g_wxhi[400 * 80];
__device__ __nv_bfloat16 g_wxlo[400 * 80];
__device__ float g_xlrel[(size_t)NT_ALL * 200];
__device__ float g_xlroot[(size_t)NT_ALL * 200];
__device__ int   g_list[NG * 128];
__device__ int   g_start[NG * 68];
__device__ float g_wa2[DN], g_wb2[DN];
__device__ float g_tw[DN];
__device__ float g_winv;

__device__ __forceinline__ unsigned smem_u32(const void* p) {
    unsigned a;
    asm("{ .reg .u64 t; cvta.to.shared.u64 t, %1; cvt.u32.u64 %0, t; }" : "=r"(a) : "l"(p));
    return a;
}
__device__ __forceinline__ void cpa16(unsigned s, const void* g) {
    asm volatile("cp.async.cg.shared.global [%0], [%1], 16;" :: "r"(s), "l"(g));
}
__device__ __forceinline__ void cpa_commit() { asm volatile("cp.async.commit_group;" ::: "memory"); }
template<int N> __device__ __forceinline__ void cpa_wait() {
    asm volatile("cp.async.wait_group %0;" :: "n"(N) : "memory");
}
__device__ __forceinline__ void ldmx4(unsigned* r, unsigned addr) {
    asm volatile("ldmatrix.sync.aligned.m8n8.x4.shared.b16 {%0,%1,%2,%3}, [%4];"
        : "=r"(r[0]), "=r"(r[1]), "=r"(r[2]), "=r"(r[3]) : "r"(addr));
}
__device__ __forceinline__ void mma16816bf(float* d, const unsigned* a, const unsigned* b) {
    asm volatile("mma.sync.aligned.m16n8k16.row.col.f32.bf16.bf16.f32 "
        "{%0,%1,%2,%3}, {%4,%5,%6,%7}, {%8,%9}, {%0,%1,%2,%3};"
        : "+f"(d[0]), "+f"(d[1]), "+f"(d[2]), "+f"(d[3])
        : "r"(a[0]), "r"(a[1]), "r"(a[2]), "r"(a[3]), "r"(b[0]), "r"(b[1]));
}
__device__ __forceinline__ void mma16816h(float* d, const unsigned* a, const unsigned* b) {
    asm volatile("mma.sync.aligned.m16n8k16.row.col.f32.f16.f16.f32 "
        "{%0,%1,%2,%3}, {%4,%5,%6,%7}, {%8,%9}, {%0,%1,%2,%3};"
        : "+f"(d[0]), "+f"(d[1]), "+f"(d[2]), "+f"(d[3])
        : "r"(a[0]), "r"(a[1]), "r"(a[2]), "r"(a[3]), "r"(b[0]), "r"(b[1]));
}

__device__ __forceinline__ void conv4h(__half* dst, float4 v) {
    union { __half b[4]; uint2 u; } H;
    H.b[0]=__float2half_rn(v.x); H.b[1]=__float2half_rn(v.y);
    H.b[2]=__float2half_rn(v.z); H.b[3]=__float2half_rn(v.w);
    *(uint2*)dst = H.u;
}
__device__ __forceinline__ void split2(__nv_bfloat16* hi, __nv_bfloat16* lo, float a, float b) {
    __nv_bfloat16 h0=__float2bfloat16_rn(a), h1=__float2bfloat16_rn(b);
    union { __nv_bfloat16 v[2]; unsigned u; } H, L;
    H.v[0]=h0; H.v[1]=h1;
    L.v[0]=__float2bfloat16_rn(a-__bfloat162float(h0));
    L.v[1]=__float2bfloat16_rn(b-__bfloat162float(h1));
    *(unsigned*)hi = H.u;  *(unsigned*)lo = L.u;
}

// ---------------- prep_all ----------------
#define R0 ((long)M_TOT * 2000)
#define R1 (R0 + (long)H1 * 2000)
#define R2 (R1 + 128 * 256)
#define R3 (R2 + (long)NT_ALL * 40)
#define R4 (R3 + 400 * 40)
#define R5 (R4 + 256)

__global__ __launch_bounds__(256) void prep_all(
    const float* __restrict__ x1, const float* __restrict__ x2,
    const float* __restrict__ W1, const float* __restrict__ W2,
    const float* __restrict__ bn0_s, const float* __restrict__ bn0_t,
    const float* __restrict__ dx,
    const float* __restrict__ Wrel, const float* __restrict__ Wroot,
    const float* __restrict__ brel,
    const float* __restrict__ bnd_s, const float* __restrict__ bnd_t,
    const float* __restrict__ topk_w)
{
    long i = (long)blockIdx.x * 256 + threadIdx.x;
    if (i >= R5) return;
    if (i < R0) {
        int row = (int)(i / 2000), k4 = (int)(i % 2000);
        const float* src = (row < NB) ? (x1 + (size_t)row * EXPR) : (x2 + (size_t)(row - NB) * EXPR);
        float4 v = *(const float4*)(src + k4 * 4);
        float4 s = *(const float4*)(bn0_s + k4 * 4);
        float4 t = *(const float4*)(bn0_t + k4 * 4);
        v.x = v.x*s.x + t.x;  v.y = v.y*s.y + t.y;  v.z = v.z*s.z + t.z;  v.w = v.w*s.w + t.w;
        conv4h(g_Ah + (size_t)row * EXPR + (size_t)k4 * 4, v);
    } else if (i < R1) {
        long j = i - R0;
        int row = (int)(j / 2000), k4 = (int)(j % 2000);
        float4 v = *(const float4*)(W1 + (size_t)row * EXPR + k4 * 4);
        conv4h(g_Bh + (size_t)row * EXPR + (size_t)k4 * 4, v);
    } else if (i < R2) {
        long j = i - R1;
        int row = (int)(j >> 8), k4 = (int)(j & 255);
        float4 v = make_float4(0.f, 0.f, 0.f, 0.f);
        if (row < H2) v = *(const float4*)(W2 + (size_t)row * H1 + k4 * 4);
        conv4h(g_W2h + (size_t)row * H1 + k4 * 4, v);
    } else if (i < R3) {
        long j = i - R2;
        int n = (int)(j / 40), kp = (int)(j % 40);
        int k0 = 2 * kp;
        float a = (k0     < DD) ? dx[(size_t)n * DD + k0]     : 0.f;
        float b = (k0 + 1 < DD) ? dx[(size_t)n * DD + k0 + 1] : 0.f;
        size_t eo = (size_t)n * 80 + k0;
        split2(g_dxhi + eo, g_dxlo + eo, a, b);
    } else if (i < R4) {
        long j = i - R3;
        int n = (int)(j / 40), kp = (int)(j % 40);
        int k0 = 2 * kp;
        float a = 0.f, b = 0.f;
        if (k0 < DD)     a = (n < DN) ? Wrel[n*DD + k0]     : Wroot[(n-DN)*DD + k0];
        if (k0 + 1 < DD) b = (n < DN) ? Wrel[n*DD + k0 + 1] : Wroot[(n-DN)*DD + k0 + 1];
        split2(g_wxhi + n*80 + k0, g_wxlo + n*80 + k0, a, b);
    } else {
        int j = (int)(i - R4);
        if (j < DN) {
            float al = bnd_s[j];
            g_wa2[j] = al;
            g_wb2[j] = brel[j]*al + bnd_t[j];
            g_tw[j]  = topk_w[j];
        }
        if (j == 0) {
            float s = 0.f;
            for (int c = 0; c < DN; ++c) s += topk_w[c]*topk_w[c];
            g_winv = rsqrtf(s);
        }
    }
}

// ---------------- edge_prep: deterministic global CSR ----------------
__global__ __launch_bounds__(128) void edge_prep(const int* __restrict__ edge_index)
{
    __shared__ int es[EPG], ed[EPG], cnt[NPG], start[NPG + 1];
    const int g = blockIdx.x;
    const int tid = threadIdx.x;
    es[tid] = edge_index[g*EPG + tid] - g*NPG;
    ed[tid] = edge_index[ET_TOT + g*EPG + tid] - g*NPG;
    __syncthreads();
    if (tid < NPG) {
        int c = 0;
        for (int e = 0; e < EPG; ++e) c += (ed[e] == tid);
        cnt[tid] = c;
    }
    __syncthreads();
    if (tid < 32) {
        int ca = cnt[2*tid], cb = cnt[2*tid+1];
        int pv = ca + cb, s = pv;
        #pragma unroll
        for (int o = 1; o < 32; o <<= 1) {
            int t = __shfl_up_sync(0xffffffffu, s, o);
            if (tid >= o) s += t;
        }
        int excl = s - pv;
        start[2*tid] = excl;
        start[2*tid+1] = excl + ca;
        if (tid == 31) start[NPG] = s;
    }
    __syncthreads();
    if (tid < NPG) {
        int pos = start[tid];
        for (int e = 0; e < EPG; ++e)
            if (ed[e] == tid) g_list[g*128 + pos++] = es[e];
    }
    if (tid < 68) g_start[g*68 + tid] = (tid <= NPG) ? start[tid] : 0;
}

// ---------------- MEGA: gemm1 (bid<128) + xl (bid>=128) ----------------
#define KC    32
#define NCH   250
#define AST   40
#define OFF_A 0
#define OFF_B 20480
#define STG   30720
#define XAST  88
#define XB_LO 14080
#define XA_BASE 28160
#define XA_LO 22528
#define XA_PER 45056
#define MEGA_DSMEM (XA_BASE + 4 * XA_PER)

__global__ void __launch_bounds__(1024, 1) mega_g1xl(
    const float* __restrict__ b1, const float* __restrict__ bn1_s,
    const float* __restrict__ bn1_t)
{
    extern __shared__ char dynsm[];
    __shared__ float s_alpha[128], s_beta[128];
    const unsigned sb = smem_u32(dynsm);
    const int tid = threadIdx.x;
    const int bid = blockIdx.x;
    const int lane = tid & 31;

    if (bid < 128) {
        const int warp = tid >> 5;
        const int m0 = (bid >> 3) * 256;
        const int n0 = (bid & 7) * 128;
        const int wm = (warp >> 2) * 32;
        const int wn = (warp & 3) * 32;

        if (tid < 128) {
            float al = bn1_s[n0 + tid];
            s_alpha[tid] = al;
            s_beta[tid]  = b1[n0 + tid] * al + bn1_t[n0 + tid];
        }

        auto load_chunk = [&](int c, int s) {
            const unsigned st = sb + s * STG;
            const long k0 = (long)c * KC;
            {
                int r = tid >> 2, q = tid & 3;
                unsigned off = r * 80 + q * 16;
                size_t go = (size_t)(m0 + r) * EXPR + k0 + q * 8;
                cpa16(st + OFF_A + off, g_Ah + go);
            }
            if (tid < 512) {
                int r = tid >> 2, q = tid & 3;
                unsigned off = r * 80 + q * 16;
                size_t go = (size_t)(n0 + r) * EXPR + k0 + q * 8;
                cpa16(st + OFF_B + off, g_Bh + go);
            }
            cpa_commit();
        };

        float acc[2][4][4];
        #pragma unroll
        for (int i = 0; i < 2; ++i)
            #pragma unroll
            for (int j = 0; j < 4; ++j)
                #pragma unroll
                for (int q = 0; q < 4; ++q) acc[i][j][q] = 0.f;

        load_chunk(0, 0);
        load_chunk(1, 1);

        const int arow = lane & 15;
        const int acol = (lane >> 4) << 3;

        for (int c = 0; c < NCH; ++c) {
            const int s = c - (c / 3) * 3;
            if (c + 1 < NCH) cpa_wait<1>(); else cpa_wait<0>();
            __syncthreads();
            if (c + 2 < NCH) {
                int s2 = (c + 2) - ((c + 2) / 3) * 3;
                load_chunk(c + 2, s2);
            }
            const unsigned aA = sb + s * STG;
            const unsigned bB = aA + OFF_B;
            #pragma unroll
            for (int ks = 0; ks < KC; ks += 16) {
                unsigned ah[8], bh[8];
                #pragma unroll
                for (int i = 0; i < 2; ++i)
                    ldmx4(&ah[4*i], aA + ((wm + i*16 + arow) * AST + ks + acol) * 2);
                #pragma unroll
                for (int j2 = 0; j2 < 2; ++j2) {
                    unsigned tr[4];
                    ldmx4(tr, bB + ((wn + j2*16 + arow) * AST + ks + acol) * 2);
                    bh[4*j2 + 0] = tr[0];  bh[4*j2 + 1] = tr[2];
                    bh[4*j2 + 2] = tr[1];  bh[4*j2 + 3] = tr[3];
                }
                #pragma unroll
                for (int i = 0; i < 2; ++i)
                    #pragma unroll
                    for (int j = 0; j < 4; ++j)
                        mma16816h(acc[i][j], &ah[4*i], &bh[2*j]);
            }
        }

        const int er = lane >> 2, ec = (lane & 3) * 2;
        #pragma unroll
        for (int i = 0; i < 2; ++i) {
            #pragma unroll
            for (int j = 0; j < 4; ++j) {
                int nl = wn + j*8 + ec;
                float a0 = s_alpha[nl], a1 = s_alpha[nl+1];
                float e0 = s_beta[nl],  e1 = s_beta[nl+1];
                int mg0 = m0 + wm + i*16 + er;
                __half2 h0 = __floats2half2_rn(fmaxf(acc[i][j][0]*a0 + e0, 0.f),
                                               fmaxf(acc[i][j][1]*a1 + e1, 0.f));
                __half2 h1v = __floats2half2_rn(fmaxf(acc[i][j][2]*a0 + e0, 0.f),
                                                fmaxf(acc[i][j][3]*a1 + e1, 0.f));
                *(__half2*)&g_h1h[(size_t)mg0 * H1 + n0 + nl]       = h0;
                *(__half2*)&g_h1h[(size_t)(mg0 + 8) * H1 + n0 + nl] = h1v;
            }
        }
    } else {
        const int bid2 = bid - 128;
        const int nt = bid2 >> 8;
        const int mt = bid2 & 255;
        const int q  = tid >> 8;
        const int qtid = tid & 255;
        const int m0 = (mt * 4 + q) * 128;
        const int n0 = nt * 80;
        const unsigned sbB = sb;
        const unsigned sbA = sb + XA_BASE + q * XA_PER;

        if (tid < 800) {
            int r = tid / 10, qq = tid - r * 10;
            unsigned off = r * 176 + qq * 16;
            size_t go = (size_t)(n0 + r) * 80 + qq * 8;
            cpa16(sbB + off, g_wxhi + go);
            cpa16(sbB + XB_LO + off, g_wxlo + go);
        }
        #pragma unroll
        for (int t = 0; t < 5; ++t) {
            int i = qtid + t * 256;
            int r = i / 10, qq = i - r * 10;
            unsigned off = r * 176 + qq * 16;
            size_t go = (size_t)(m0 + r) * 80 + qq * 8;
            cpa16(sbA + off, g_dxhi + go);
            cpa16(sbA + XA_LO + off, g_dxlo + go);
        }
        cpa_commit();
        cpa_wait<0>();
        __syncthreads();

        float acc[10][4];
        #pragma unroll
        for (int j = 0; j < 10; ++j)
            #pragma unroll
            for (int p = 0; p < 4; ++p) acc[j][p] = 0.f;

        const int warp = qtid >> 5;
        const int arow = lane & 15;
        const int acol = (lane >> 4) << 3;

        #pragma unroll
        for (int ks = 0; ks < 80; ks += 16) {
            unsigned ah[4], al[4];
            ldmx4(ah, sbA + ((warp*16 + arow) * XAST + ks + acol) * 2);
            ldmx4(al, sbA + XA_LO + ((warp*16 + arow) * XAST + ks + acol) * 2);
            #pragma unroll
            for (int jb = 0; jb < 5; ++jb) {
                unsigned trh[4], trl[4], b0[2], b1[2], c0[2], c1[2];
                ldmx4(trh, sbB + ((jb*16 + arow) * XAST + ks + acol) * 2);
                ldmx4(trl, sbB + XB_LO + ((jb*16 + arow) * XAST + ks + acol) * 2);
                b0[0] = trh[0]; b0[1] = trh[2];
                b1[0] = trh[1]; b1[1] = trh[3];
                c0[0] = trl[0]; c0[1] = trl[2];
                c1[0] = trl[1]; c1[1] = trl[3];
                mma16816bf(acc[2*jb],   ah, b0);
                mma16816bf(acc[2*jb],   ah, c0);
                mma16816bf(acc[2*jb],   al, b0);
                mma16816bf(acc[2*jb+1], ah, b1);
                mma16816bf(acc[2*jb+1], ah, c1);
                mma16816bf(acc[2*jb+1], al, b1);
            }
        }

        const int er = lane >> 2, ec = (lane & 3) * 2;
        const int grow = m0 + warp*16 + er;
        #pragma unroll
        for (int j = 0; j < 10; ++j) {
            int gc = n0 + 8*j + ec;
            float2 v0 = make_float2(acc[j][0], acc[j][1]);
            float2 v1 = make_float2(acc[j][2], acc[j][3]);
            if (gc < 200) {
                *(float2*)&g_xlrel[(size_t)grow * 200 + gc]       = v0;
                *(float2*)&g_xlrel[(size_t)(grow + 8) * 200 + gc] = v1;
            } else {
                *(float2*)&g_xlroot[(size_t)grow * 200 + gc - 200]       = v0;
                *(float2*)&g_xlroot[(size_t)(grow + 8) * 200 + gc - 200] = v1;
            }
        }
    }
}

// ---------------- GEMM2 (unchanged) ----------------
__global__ __launch_bounds__(256) void gemm2_mma(
    const float* __restrict__ b2, const float* __restrict__ bn2_s,
    const float* __restrict__ bn2_t, float* __restrict__ out)
{
    __shared__ __align__(16) __half sm2[3 * 6400];
    const int tid = threadIdx.x;
    const int warp = tid >> 5, lane = tid & 31;
    const int m0 = blockIdx.x * 32;
    const int wm = (warp >> 2) * 16;
    const int wn = (warp & 3) * 32;
    const unsigned sb = smem_u32(sm2);

    auto load_chunk = [&](int c, int s) {
        const unsigned st = sb + s * 12800;
        if (tid < 128) {
            int r = tid >> 2, q = tid & 3;
            cpa16(st + (r * 40 + q * 8) * 2, g_h1h + (size_t)(m0 + r) * H1 + c * 32 + q * 8);
        }
        #pragma unroll
        for (int t = 0; t < 2; ++t) {
            int i = tid + t * 256;
            int r = i >> 2, q = i & 3;
            cpa16(st + 2560 + (r * 40 + q * 8) * 2, g_W2h + (size_t)r * H1 + c * 32 + q * 8);
        }
        cpa_commit();
    };

    float acc[4][4];
    #pragma unroll
    for (int j = 0; j < 4; ++j)
        #pragma unroll
        for (int q = 0; q < 4; ++q) acc[j][q] = 0.f;

    load_chunk(0, 0);
    load_chunk(1, 1);

    const int arow = lane & 15;
    const int acol = (lane >> 4) << 3;

    for (int c = 0; c < 32; ++c) {
        const int s = c - (c / 3) * 3;
        if (c + 1 < 32) cpa_wait<1>(); else cpa_wait<0>();
        __syncthreads();
        if (c + 2 < 32) {
            int s2 = (c + 2) - ((c + 2) / 3) * 3;
            load_chunk(c + 2, s2);
        }
        const unsigned aA = sb + s * 12800;
        const unsigned bB = aA + 2560;
        #pragma unroll
        for (int ks = 0; ks < 32; ks += 16) {
            unsigned ah[4], bh[8];
            ldmx4(ah, aA + ((wm + arow) * 40 + ks + acol) * 2);
            #pragma unroll
            for (int j2 = 0; j2 < 2; ++j2) {
                unsigned tr[4];
                ldmx4(tr, bB + ((wn + j2*16 + arow) * 40 + ks + acol) * 2);
                bh[4*j2 + 0] = tr[0];  bh[4*j2 + 1] = tr[2];
                bh[4*j2 + 2] = tr[1];  bh[4*j2 + 3] = tr[3];
            }
            #pragma unroll
            for (int j = 0; j < 4; ++j)
                mma16816h(acc[j], ah, &bh[2*j]);
        }
    }

    const int er = lane >> 2, ec = (lane & 3) * 2;
    #pragma unroll
    for (int j = 0; j < 4; ++j) {
        int n = wn + j*8 + ec;
        if (n >= H2) continue;
        float a0 = bn2_s[n],   a1 = bn2_s[n+1];
        float e0 = b2[n]*a0 + bn2_t[n];
        float e1 = b2[n+1]*a1 + bn2_t[n+1];
        int m_a = m0 + wm + er, m_b = m_a + 8;
        float va0 = fmaxf(acc[j][0]*a0 + e0, 0.f);
        float va1 = fmaxf(acc[j][1]*a1 + e1, 0.f);
        float vb0 = fmaxf(acc[j][2]*a0 + e0, 0.f);
        float vb1 = fmaxf(acc[j][3]*a1 + e1, 0.f);
        size_t oa = (m_a < NB) ? ((size_t)m_a*H2 + n) : ((size_t)NB*H2 + (size_t)(m_a - NB)*H2 + n);
        size_t ob = (m_b < NB) ? ((size_t)m_b*H2 + n) : ((size_t)NB*H2 + (size_t)(m_b - NB)*H2 + n);
        out[oa] = va0;  out[oa + 1] = va1;
        out[ob] = vb0;  out[ob + 1] = vb1;
    }
}

// ---------------- Drug v8: pipelined staging, no CSR in loop, fused resp ----------------
#define VXL 204
#define VH  201
#define OXL 0
#define OH  13056
#define OWA 25920
#define OWB 26120
#define OTW 26320
#define OSC 26520
#define OFL 26584
#define OST 26648
#define OLS 26716
#define OWS 26844
#define DTOT 26860
#define DRUG_SMEM_BYTES (DTOT * 4)
#define DRUG_GRID 296

__global__ __launch_bounds__(512, 2) void drug_kernel(
    const float* __restrict__ Wp, const float* __restrict__ bp,
    float* __restrict__ out)
{
    extern __shared__ float sm[];
    float* xl    = sm + OXL;
    float* hsh   = sm + OH;
    float* wa    = sm + OWA;
    float* wb    = sm + OWB;
    float* tw    = sm + OTW;
    float* score = sm + OSC;
    int*   flag  = (int*)(sm + OFL);
    int*   start = (int*)(sm + OST);
    int*   list  = (int*)(sm + OLS);
    float* ws    = sm + OWS;

    const int tid = threadIdx.x;
    const int lane = tid & 31;
    const int warp = tid >> 5;
    const int g0 = (int)(((long)blockIdx.x * NG) / DRUG_GRID);
    const int g1 = (int)(((long)(blockIdx.x + 1) * NG) / DRUG_GRID);
    const float winv = g_winv;
    const unsigned sb = smem_u32(sm);

    if (tid < DN) { wa[tid] = g_wa2[tid]; wb[tid] = g_wb2[tid]; tw[tid] = g_tw[tid]; }

    auto stage = [&](int g) {
        const int base = g * NPG;
        for (int i = tid; i < 3200; i += 512) {
            int nn = i / 50, q = i - nn * 50;
            cpa16(sb + (OXL + nn * VXL + q * 4) * 4, g_xlrel + (size_t)(base + nn) * 200 + q * 4);
        }
        if (tid < 32) cpa16(sb + (OLS + tid * 4) * 4, g_list + g * 128 + tid * 4);
        else if (tid < 49) cpa16(sb + (OST + (tid - 32) * 4) * 4, g_start + g * 68 + (tid - 32) * 4);
        cpa_commit();
    };

    stage(g0);

    const int ni   = tid >> 3;
    const int part = tid & 7;
    const int c0   = part * 25;

    for (int g = g0; g < g1; ++g) {
        const int base = g * NPG;
        // root prefetch (LDGs issued here, consumed after 1 barrier)
        float acc[25];
        {
            const float* xr = g_xlroot + (size_t)(base + ni) * 200 + c0;
            #pragma unroll
            for (int c = 0; c < 25; ++c) acc[c] = xr[c];
        }
        cpa_wait<0>();
        __syncthreads();

        // h = relu((root + sum_in xl_rel[src])*wa + wb)
        {
            const int b0 = start[ni], b1 = start[ni + 1];
            for (int e = b0; e < b1; ++e) {
                const float* xp = xl + list[e] * VXL + c0;
                #pragma unroll
                for (int c = 0; c < 25; ++c) acc[c] += xp[c];
            }
            #pragma unroll
            for (int c = 0; c < 25; ++c) {
                int cc = c0 + c;
                hsh[ni * VH + cc] = fmaxf(acc[c] * wa[cc] + wb[cc], 0.f);
            }
        }
        __syncthreads();
        // xl buffer is dead: prefetch next graph now (overlaps score/rank/readout)
        if (g + 1 < g1) stage(g + 1);

        // score
        {
            float s = 0.f;
            const float* hp  = &hsh[ni * VH + c0];
            const float* twp = &tw[c0];
            #pragma unroll
            for (int c = 0; c < 25; ++c) s += hp[c] * twp[c];
            s += __shfl_xor_sync(0xffffffffu, s, 1);
            s += __shfl_xor_sync(0xffffffffu, s, 2);
            s += __shfl_xor_sync(0xffffffffu, s, 4);
            if (part == 0) score[ni] = tanhf(s * winv);
        }
        __syncthreads();

        // rank: 64 nodes x 8 partials
        {
            float sn = score[ni];
            int r = 0;
            #pragma unroll
            for (int m2 = part*8; m2 < part*8 + 8; ++m2) {
                float sv = score[m2];
                r += (sv > sn) || (sv == sn && m2 < ni);
            }
            r += __shfl_xor_sync(0xffffffffu, r, 1);
            r += __shfl_xor_sync(0xffffffffu, r, 2);
            r += __shfl_xor_sync(0xffffffffu, r, 4);
            if (part == 0) flag[ni] = (r < KTOP) ? 1 : 0;
        }
        __syncthreads();

        // readout + resp partials
        float p = 0.f;
        if (tid < 200) {
            const int c = tid;
            float mx = -1e30f, sum = 0.f, mxs = -1e30f, sums = 0.f;
            for (int n2 = 0; n2 < NPG; ++n2) {
                float v = hsh[n2 * VH + c];
                mx = fmaxf(mx, v); sum += v;
                if (flag[n2]) {
                    float w = v * score[n2];
                    mxs = fmaxf(mxs, w); sums += w;
                }
            }
            float d0 = fmaxf(mx + 3.f*mxs, 0.f);
            float d1 = fmaxf(sum*(1.f/NPG) + 3.f*(sums*(1.f/KTOP)), 0.f);
            p = d0 * Wp[100 + c] + d1 * Wp[300 + c];
        } else if (tid < 300) {
            int i = tid - 200;
            p = out[(size_t)g*H2 + i] * Wp[i];
        }
        #pragma unroll
        for (int o = 16; o; o >>= 1) p += __shfl_down_sync(0xffffffffu, p, o);
        if (lane == 0) ws[warp] = p;
        __syncthreads();
        if (tid == 0) {
            float s = 0.f;
            #pragma unroll
            for (int w = 0; w < 16; ++w) s += ws[w];
            out[(size_t)2*NB*H2 + g] = s + bp[0];
        }
        __syncthreads();
    }
}

extern "C" void kernel_launch(void* const* d_in, const int* in_sizes, int n_in,
                              void* d_out, int out_size)
{
    const float* x1     = (const float*)d_in[0];
    const float* x2     = (const float*)d_in[1];
    const int*   eidx   = (const int*)d_in[4];
    const float* drug_x = (const float*)d_in[5];
    const float* bn0_s  = (const float*)d_in[6];
    const float* bn0_t  = (const float*)d_in[7];
    const float* W1     = (const float*)d_in[8];
    const float* b1     = (const float*)d_in[9];
    const float* bn1_s  = (const float*)d_in[10];
    const float* bn1_t  = (const float*)d_in[11];
    const float* W2     = (const float*)d_in[12];
    const float* b2     = (const float*)d_in[13];
    const float* bn2_s  = (const float*)d_in[14];
    const float* bn2_t  = (const float*)d_in[15];
    const float* Wrel   = (const float*)d_in[16];
    const float* brel   = (const float*)d_in[17];
    const float* Wroot  = (const float*)d_in[18];
    const float* bnd_s  = (const float*)d_in[19];
    const float* bnd_t  = (const float*)d_in[20];
    const float* topk_w = (const float*)d_in[21];
    const float* Wp     = (const float*)d_in[22];
    const float* bp     = (const float*)d_in[23];
    float* out = (float*)d_out;

    cudaFuncSetAttribute(drug_kernel, cudaFuncAttributeMaxDynamicSharedMemorySize, DRUG_SMEM_BYTES);
    cudaFuncSetAttribute(mega_g1xl, cudaFuncAttributeMaxDynamicSharedMemorySize, MEGA_DSMEM);

    prep_all<<<(int)((R5 + 255) / 256), 256>>>(x1, x2, W1, W2, bn0_s, bn0_t,
                                               drug_x, Wrel, Wroot, brel,
                                               bnd_s, bnd_t, topk_w);
    edge_prep<<<NG, 128>>>(eidx);
    mega_g1xl<<<128 + 1280, 1024, MEGA_DSMEM>>>(b1, bn1_s, bn1_t);
    gemm2_mma<<<M_TOT / 32, 256>>>(b2, bn2_s, bn2_t, out);
    drug_kernel<<<DRUG_GRID, 512, DRUG_SMEM_BYTES>>>(Wp, bp, out);
}

// round 16
// speedup vs baseline: 2.2776x; 1.1675x over previous
#include <cuda_runtime.h>
#include <cuda_bf16.h>
#include <cuda_fp16.h>
#include <math.h>
#include <stdint.h>

#define NB      2048
#define EXPR    8000
#define H1      1024
#define H2      100
#define M_TOT   4096
#define DD      78
#define DN      200
#define NPG     64
#define EPG     128
#define NG      2048
#define NT_ALL  131072
#define ET_TOT  262144
#define KTOP    52

__device__ __half g_h1h[(size_t)M_TOT * H1];
__device__ __half g_Ah[(size_t)M_TOT * EXPR];
__device__ __half g_Bh[(size_t)H1 * EXPR];
__device__ __half g_W2h[(size_t)128 * H1];
__device__ __nv_bfloat16 g_dxhi[(size_t)NT_ALL * 80];
__device__ __nv_bfloat16 g_dxlo[(size_t)NT_ALL * 80];
__device__ __nv_bfloat16 g_wxhi[400 * 80];
__device__ __nv_bfloat16 g_wxlo[400 * 80];
__device__ float g_xlrel[(size_t)NT_ALL * 200];
__device__ float g_xlroot[(size_t)NT_ALL * 200];
__device__ int   g_list[NG * 128];
__device__ int   g_start[NG * 68];
__device__ float g_wa2[DN], g_wb2[DN];
__device__ float g_tw[DN];
__device__ float g_winv;

__device__ __forceinline__ unsigned smem_u32(const void* p) {
    unsigned a;
    asm("{ .reg .u64 t; cvta.to.shared.u64 t, %1; cvt.u32.u64 %0, t; }" : "=r"(a) : "l"(p));
    return a;
}
__device__ __forceinline__ void cpa16(unsigned s, const void* g) {
    asm volatile("cp.async.cg.shared.global [%0], [%1], 16;" :: "r"(s), "l"(g));
}
__device__ __forceinline__ void cpa_commit() { asm volatile("cp.async.commit_group;" ::: "memory"); }
template<int N> __device__ __forceinline__ void cpa_wait() {
    asm volatile("cp.async.wait_group %0;" :: "n"(N) : "memory");
}
__device__ __forceinline__ void ldmx4(unsigned* r, unsigned addr) {
    asm volatile("ldmatrix.sync.aligned.m8n8.x4.shared.b16 {%0,%1,%2,%3}, [%4];"
        : "=r"(r[0]), "=r"(r[1]), "=r"(r[2]), "=r"(r[3]) : "r"(addr));
}
__device__ __forceinline__ void mma16816bf(float* d, const unsigned* a, const unsigned* b) {
    asm volatile("mma.sync.aligned.m16n8k16.row.col.f32.bf16.bf16.f32 "
        "{%0,%1,%2,%3}, {%4,%5,%6,%7}, {%8,%9}, {%0,%1,%2,%3};"
        : "+f"(d[0]), "+f"(d[1]), "+f"(d[2]), "+f"(d[3])
        : "r"(a[0]), "r"(a[1]), "r"(a[2]), "r"(a[3]), "r"(b[0]), "r"(b[1]));
}
__device__ __forceinline__ void mma16816h(float* d, const unsigned* a, const unsigned* b) {
    asm volatile("mma.sync.aligned.m16n8k16.row.col.f32.f16.f16.f32 "
        "{%0,%1,%2,%3}, {%4,%5,%6,%7}, {%8,%9}, {%0,%1,%2,%3};"
        : "+f"(d[0]), "+f"(d[1]), "+f"(d[2]), "+f"(d[3])
        : "r"(a[0]), "r"(a[1]), "r"(a[2]), "r"(a[3]), "r"(b[0]), "r"(b[1]));
}

__device__ __forceinline__ void conv4h(__half* dst, float4 v) {
    union { __half b[4]; uint2 u; } H;
    H.b[0]=__float2half_rn(v.x); H.b[1]=__float2half_rn(v.y);
    H.b[2]=__float2half_rn(v.z); H.b[3]=__float2half_rn(v.w);
    *(uint2*)dst = H.u;
}
__device__ __forceinline__ void split2(__nv_bfloat16* hi, __nv_bfloat16* lo, float a, float b) {
    __nv_bfloat16 h0=__float2bfloat16_rn(a), h1=__float2bfloat16_rn(b);
    union { __nv_bfloat16 v[2]; unsigned u; } H, L;
    H.v[0]=h0; H.v[1]=h1;
    L.v[0]=__float2bfloat16_rn(a-__bfloat162float(h0));
    L.v[1]=__float2bfloat16_rn(b-__bfloat162float(h1));
    *(unsigned*)hi = H.u;  *(unsigned*)lo = L.u;
}

// ---------------- prep_all ----------------
#define R0 ((long)M_TOT * 2000)
#define R1 (R0 + (long)H1 * 2000)
#define R2 (R1 + 128 * 256)
#define R3 (R2 + (long)NT_ALL * 40)
#define R4 (R3 + 400 * 40)
#define R5 (R4 + 256)

__global__ __launch_bounds__(256) void prep_all(
    const float* __restrict__ x1, const float* __restrict__ x2,
    const float* __restrict__ W1, const float* __restrict__ W2,
    const float* __restrict__ bn0_s, const float* __restrict__ bn0_t,
    const float* __restrict__ dx,
    const float* __restrict__ Wrel, const float* __restrict__ Wroot,
    const float* __restrict__ brel,
    const float* __restrict__ bnd_s, const float* __restrict__ bnd_t,
    const float* __restrict__ topk_w)
{
    long i = (long)blockIdx.x * 256 + threadIdx.x;
    if (i >= R5) return;
    if (i < R0) {
        int row = (int)(i / 2000), k4 = (int)(i % 2000);
        const float* src = (row < NB) ? (x1 + (size_t)row * EXPR) : (x2 + (size_t)(row - NB) * EXPR);
        float4 v = *(const float4*)(src + k4 * 4);
        float4 s = *(const float4*)(bn0_s + k4 * 4);
        float4 t = *(const float4*)(bn0_t + k4 * 4);
        v.x = v.x*s.x + t.x;  v.y = v.y*s.y + t.y;  v.z = v.z*s.z + t.z;  v.w = v.w*s.w + t.w;
        conv4h(g_Ah + (size_t)row * EXPR + (size_t)k4 * 4, v);
    } else if (i < R1) {
        long j = i - R0;
        int row = (int)(j / 2000), k4 = (int)(j % 2000);
        float4 v = *(const float4*)(W1 + (size_t)row * EXPR + k4 * 4);
        conv4h(g_Bh + (size_t)row * EXPR + (size_t)k4 * 4, v);
    } else if (i < R2) {
        long j = i - R1;
        int row = (int)(j >> 8), k4 = (int)(j & 255);
        float4 v = make_float4(0.f, 0.f, 0.f, 0.f);
        if (row < H2) v = *(const float4*)(W2 + (size_t)row * H1 + k4 * 4);
        conv4h(g_W2h + (size_t)row * H1 + k4 * 4, v);
    } else if (i < R3) {
        long j = i - R2;
        int n = (int)(j / 40), kp = (int)(j % 40);
        int k0 = 2 * kp;
        float a = (k0     < DD) ? dx[(size_t)n * DD + k0]     : 0.f;
        float b = (k0 + 1 < DD) ? dx[(size_t)n * DD + k0 + 1] : 0.f;
        size_t eo = (size_t)n * 80 + k0;
        split2(g_dxhi + eo, g_dxlo + eo, a, b);
    } else if (i < R4) {
        long j = i - R3;
        int n = (int)(j / 40), kp = (int)(j % 40);
        int k0 = 2 * kp;
        float a = 0.f, b = 0.f;
        if (k0 < DD)     a = (n < DN) ? Wrel[n*DD + k0]     : Wroot[(n-DN)*DD + k0];
        if (k0 + 1 < DD) b = (n < DN) ? Wrel[n*DD + k0 + 1] : Wroot[(n-DN)*DD + k0 + 1];
        split2(g_wxhi + n*80 + k0, g_wxlo + n*80 + k0, a, b);
    } else {
        int j = (int)(i - R4);
        if (j < DN) {
            float al = bnd_s[j];
            g_wa2[j] = al;
            g_wb2[j] = brel[j]*al + bnd_t[j];
            g_tw[j]  = topk_w[j];
        }
        if (j == 0) {
            float s = 0.f;
            for (int c = 0; c < DN; ++c) s += topk_w[c]*topk_w[c];
            g_winv = rsqrtf(s);
        }
    }
}

// ---------------- edge_prep ----------------
__global__ __launch_bounds__(128) void edge_prep(const int* __restrict__ edge_index)
{
    __shared__ int es[EPG], ed[EPG], cnt[NPG], start[NPG + 1];
    const int g = blockIdx.x;
    const int tid = threadIdx.x;
    es[tid] = edge_index[g*EPG + tid] - g*NPG;
    ed[tid] = edge_index[ET_TOT + g*EPG + tid] - g*NPG;
    __syncthreads();
    if (tid < NPG) {
        int c = 0;
        for (int e = 0; e < EPG; ++e) c += (ed[e] == tid);
        cnt[tid] = c;
    }
    __syncthreads();
    if (tid < 32) {
        int ca = cnt[2*tid], cb = cnt[2*tid+1];
        int pv = ca + cb, s = pv;
        #pragma unroll
        for (int o = 1; o < 32; o <<= 1) {
            int t = __shfl_up_sync(0xffffffffu, s, o);
            if (tid >= o) s += t;
        }
        int excl = s - pv;
        start[2*tid] = excl;
        start[2*tid+1] = excl + ca;
        if (tid == 31) start[NPG] = s;
    }
    __syncthreads();
    if (tid < NPG) {
        int pos = start[tid];
        for (int e = 0; e < EPG; ++e)
            if (ed[e] == tid) g_list[g*128 + pos++] = es[e];
    }
    if (tid < 68) g_start[g*68 + tid] = (tid <= NPG) ? start[tid] : 0;
}

// ---------------- MEGA: gemm1 (bid<128) + xl (bid>=128) ----------------
#define KC    32
#define NCH   250
#define AST   40
#define OFF_A 0
#define OFF_B 20480
#define STG   30720
#define XAST  88
#define XB_LO 14080
#define XA_BASE 28160
#define XA_LO 22528
#define XA_PER 45056
#define MEGA_DSMEM (XA_BASE + 4 * XA_PER)

__global__ void __launch_bounds__(1024, 1) mega_g1xl(
    const float* __restrict__ b1, const float* __restrict__ bn1_s,
    const float* __restrict__ bn1_t)
{
    extern __shared__ char dynsm[];
    __shared__ float s_alpha[128], s_beta[128];
    const unsigned sb = smem_u32(dynsm);
    const int tid = threadIdx.x;
    const int bid = blockIdx.x;
    const int lane = tid & 31;

    if (bid < 128) {
        const int warp = tid >> 5;
        const int m0 = (bid >> 3) * 256;
        const int n0 = (bid & 7) * 128;
        const int wm = (warp >> 2) * 32;
        const int wn = (warp & 3) * 32;

        if (tid < 128) {
            float al = bn1_s[n0 + tid];
            s_alpha[tid] = al;
            s_beta[tid]  = b1[n0 + tid] * al + bn1_t[n0 + tid];
        }

        auto load_chunk = [&](int c, int s) {
            const unsigned st = sb + s * STG;
            const long k0 = (long)c * KC;
            {
                int r = tid >> 2, q = tid & 3;
                unsigned off = r * 80 + q * 16;
                size_t go = (size_t)(m0 + r) * EXPR + k0 + q * 8;
                cpa16(st + OFF_A + off, g_Ah + go);
            }
            if (tid < 512) {
                int r = tid >> 2, q = tid & 3;
                unsigned off = r * 80 + q * 16;
                size_t go = (size_t)(n0 + r) * EXPR + k0 + q * 8;
                cpa16(st + OFF_B + off, g_Bh + go);
            }
            cpa_commit();
        };

        float acc[2][4][4];
        #pragma unroll
        for (int i = 0; i < 2; ++i)
            #pragma unroll
            for (int j = 0; j < 4; ++j)
                #pragma unroll
                for (int q = 0; q < 4; ++q) acc[i][j][q] = 0.f;

        load_chunk(0, 0);
        load_chunk(1, 1);

        const int arow = lane & 15;
        const int acol = (lane >> 4) << 3;

        for (int c = 0; c < NCH; ++c) {
            const int s = c - (c / 3) * 3;
            if (c + 1 < NCH) cpa_wait<1>(); else cpa_wait<0>();
            __syncthreads();
            if (c + 2 < NCH) {
                int s2 = (c + 2) - ((c + 2) / 3) * 3;
                load_chunk(c + 2, s2);
            }
            const unsigned aA = sb + s * STG;
            const unsigned bB = aA + OFF_B;
            #pragma unroll
            for (int ks = 0; ks < KC; ks += 16) {
                unsigned ah[8], bh[8];
                #pragma unroll
                for (int i = 0; i < 2; ++i)
                    ldmx4(&ah[4*i], aA + ((wm + i*16 + arow) * AST + ks + acol) * 2);
                #pragma unroll
                for (int j2 = 0; j2 < 2; ++j2) {
                    unsigned tr[4];
                    ldmx4(tr, bB + ((wn + j2*16 + arow) * AST + ks + acol) * 2);
                    bh[4*j2 + 0] = tr[0];  bh[4*j2 + 1] = tr[2];
                    bh[4*j2 + 2] = tr[1];  bh[4*j2 + 3] = tr[3];
                }
                #pragma unroll
                for (int i = 0; i < 2; ++i)
                    #pragma unroll
                    for (int j = 0; j < 4; ++j)
                        mma16816h(acc[i][j], &ah[4*i], &bh[2*j]);
            }
        }

        const int er = lane >> 2, ec = (lane & 3) * 2;
        #pragma unroll
        for (int i = 0; i < 2; ++i) {
            #pragma unroll
            for (int j = 0; j < 4; ++j) {
                int nl = wn + j*8 + ec;
                float a0 = s_alpha[nl], a1 = s_alpha[nl+1];
                float e0 = s_beta[nl],  e1 = s_beta[nl+1];
                int mg0 = m0 + wm + i*16 + er;
                __half2 h0 = __floats2half2_rn(fmaxf(acc[i][j][0]*a0 + e0, 0.f),
                                               fmaxf(acc[i][j][1]*a1 + e1, 0.f));
                __half2 h1v = __floats2half2_rn(fmaxf(acc[i][j][2]*a0 + e0, 0.f),
                                                fmaxf(acc[i][j][3]*a1 + e1, 0.f));
                *(__half2*)&g_h1h[(size_t)mg0 * H1 + n0 + nl]       = h0;
                *(__half2*)&g_h1h[(size_t)(mg0 + 8) * H1 + n0 + nl] = h1v;
            }
        }
    } else {
        const int bid2 = bid - 128;
        const int nt = bid2 >> 8;
        const int mt = bid2 & 255;
        const int q  = tid >> 8;
        const int qtid = tid & 255;
        const int m0 = (mt * 4 + q) * 128;
        const int n0 = nt * 80;
        const unsigned sbB = sb;
        const unsigned sbA = sb + XA_BASE + q * XA_PER;

        if (tid < 800) {
            int r = tid / 10, qq = tid - r * 10;
            unsigned off = r * 176 + qq * 16;
            size_t go = (size_t)(n0 + r) * 80 + qq * 8;
            cpa16(sbB + off, g_wxhi + go);
            cpa16(sbB + XB_LO + off, g_wxlo + go);
        }
        #pragma unroll
        for (int t = 0; t < 5; ++t) {
            int i = qtid + t * 256;
            int r = i / 10, qq = i - r * 10;
            unsigned off = r * 176 + qq * 16;
            size_t go = (size_t)(m0 + r) * 80 + qq * 8;
            cpa16(sbA + off, g_dxhi + go);
            cpa16(sbA + XA_LO + off, g_dxlo + go);
        }
        cpa_commit();
        cpa_wait<0>();
        __syncthreads();

        float acc[10][4];
        #pragma unroll
        for (int j = 0; j < 10; ++j)
            #pragma unroll
            for (int p = 0; p < 4; ++p) acc[j][p] = 0.f;

        const int warp = qtid >> 5;
        const int arow = lane & 15;
        const int acol = (lane >> 4) << 3;

        #pragma unroll
        for (int ks = 0; ks < 80; ks += 16) {
            unsigned ah[4], al[4];
            ldmx4(ah, sbA + ((warp*16 + arow) * XAST + ks + acol) * 2);
            ldmx4(al, sbA + XA_LO + ((warp*16 + arow) * XAST + ks + acol) * 2);
            #pragma unroll
            for (int jb = 0; jb < 5; ++jb) {
                unsigned trh[4], trl[4], b0[2], b1[2], c0[2], c1[2];
                ldmx4(trh, sbB + ((jb*16 + arow) * XAST + ks + acol) * 2);
                ldmx4(trl, sbB + XB_LO + ((jb*16 + arow) * XAST + ks + acol) * 2);
                b0[0] = trh[0]; b0[1] = trh[2];
                b1[0] = trh[1]; b1[1] = trh[3];
                c0[0] = trl[0]; c0[1] = trl[2];
                c1[0] = trl[1]; c1[1] = trl[3];
                mma16816bf(acc[2*jb],   ah, b0);
                mma16816bf(acc[2*jb],   ah, c0);
                mma16816bf(acc[2*jb],   al, b0);
                mma16816bf(acc[2*jb+1], ah, b1);
                mma16816bf(acc[2*jb+1], ah, c1);
                mma16816bf(acc[2*jb+1], al, b1);
            }
        }

        const int er = lane >> 2, ec = (lane & 3) * 2;
        const int grow = m0 + warp*16 + er;
        #pragma unroll
        for (int j = 0; j < 10; ++j) {
            int gc = n0 + 8*j + ec;
            float2 v0 = make_float2(acc[j][0], acc[j][1]);
            float2 v1 = make_float2(acc[j][2], acc[j][3]);
            if (gc < 200) {
                *(float2*)&g_xlrel[(size_t)grow * 200 + gc]       = v0;
                *(float2*)&g_xlrel[(size_t)(grow + 8) * 200 + gc] = v1;
            } else {
                *(float2*)&g_xlroot[(size_t)grow * 200 + gc - 200]       = v0;
                *(float2*)&g_xlroot[(size_t)(grow + 8) * 200 + gc - 200] = v1;
            }
        }
    }
}

// ---------------- GEMM2 (unchanged) ----------------
__global__ __launch_bounds__(256) void gemm2_mma(
    const float* __restrict__ b2, const float* __restrict__ bn2_s,
    const float* __restrict__ bn2_t, float* __restrict__ out)
{
    __shared__ __align__(16) __half sm2[3 * 6400];
    const int tid = threadIdx.x;
    const int warp = tid >> 5, lane = tid & 31;
    const int m0 = blockIdx.x * 32;
    const int wm = (warp >> 2) * 16;
    const int wn = (warp & 3) * 32;
    const unsigned sb = smem_u32(sm2);

    auto load_chunk = [&](int c, int s) {
        const unsigned st = sb + s * 12800;
        if (tid < 128) {
            int r = tid >> 2, q = tid & 3;
            cpa16(st + (r * 40 + q * 8) * 2, g_h1h + (size_t)(m0 + r) * H1 + c * 32 + q * 8);
        }
        #pragma unroll
        for (int t = 0; t < 2; ++t) {
            int i = tid + t * 256;
            int r = i >> 2, q = i & 3;
            cpa16(st + 2560 + (r * 40 + q * 8) * 2, g_W2h + (size_t)r * H1 + c * 32 + q * 8);
        }
        cpa_commit();
    };

    float acc[4][4];
    #pragma unroll
    for (int j = 0; j < 4; ++j)
        #pragma unroll
        for (int q = 0; q < 4; ++q) acc[j][q] = 0.f;

    load_chunk(0, 0);
    load_chunk(1, 1);

    const int arow = lane & 15;
    const int acol = (lane >> 4) << 3;

    for (int c = 0; c < 32; ++c) {
        const int s = c - (c / 3) * 3;
        if (c + 1 < 32) cpa_wait<1>(); else cpa_wait<0>();
        __syncthreads();
        if (c + 2 < 32) {
            int s2 = (c + 2) - ((c + 2) / 3) * 3;
            load_chunk(c + 2, s2);
        }
        const unsigned aA = sb + s * 12800;
        const unsigned bB = aA + 2560;
        #pragma unroll
        for (int ks = 0; ks < 32; ks += 16) {
            unsigned ah[4], bh[8];
            ldmx4(ah, aA + ((wm + arow) * 40 + ks + acol) * 2);
            #pragma unroll
            for (int j2 = 0; j2 < 2; ++j2) {
                unsigned tr[4];
                ldmx4(tr, bB + ((wn + j2*16 + arow) * 40 + ks + acol) * 2);
                bh[4*j2 + 0] = tr[0];  bh[4*j2 + 1] = tr[2];
                bh[4*j2 + 2] = tr[1];  bh[4*j2 + 3] = tr[3];
            }
            #pragma unroll
            for (int j = 0; j < 4; ++j)
                mma16816h(acc[j], ah, &bh[2*j]);
        }
    }

    const int er = lane >> 2, ec = (lane & 3) * 2;
    #pragma unroll
    for (int j = 0; j < 4; ++j) {
        int n = wn + j*8 + ec;
        if (n >= H2) continue;
        float a0 = bn2_s[n],   a1 = bn2_s[n+1];
        float e0 = b2[n]*a0 + bn2_t[n];
        float e1 = b2[n+1]*a1 + bn2_t[n+1];
        int m_a = m0 + wm + er, m_b = m_a + 8;
        float va0 = fmaxf(acc[j][0]*a0 + e0, 0.f);
        float va1 = fmaxf(acc[j][1]*a1 + e1, 0.f);
        float vb0 = fmaxf(acc[j][2]*a0 + e0, 0.f);
        float vb1 = fmaxf(acc[j][3]*a1 + e1, 0.f);
        size_t oa = (m_a < NB) ? ((size_t)m_a*H2 + n) : ((size_t)NB*H2 + (size_t)(m_a - NB)*H2 + n);
        size_t ob = (m_b < NB) ? ((size_t)m_b*H2 + n) : ((size_t)NB*H2 + (size_t)(m_b - NB)*H2 + n);
        out[oa] = va0;  out[oa + 1] = va1;
        out[ob] = vb0;  out[ob + 1] = vb1;
    }
}

// ---------------- Drug v9: strided column mapping (coalesced root reads) ----------------
#define VXL 204
#define VH  201
#define OXL 0
#define OH  13056
#define OWA 25920
#define OWB 26120
#define OTW 26320
#define OSC 26520
#define OFL 26584
#define OST 26648
#define OLS 26716
#define OWS 26844
#define DTOT 26860
#define DRUG_SMEM_BYTES (DTOT * 4)
#define DRUG_GRID 296

__global__ __launch_bounds__(512, 2) void drug_kernel(
    const float* __restrict__ Wp, const float* __restrict__ bp,
    float* __restrict__ out)
{
    extern __shared__ float sm[];
    float* xl    = sm + OXL;
    float* hsh   = sm + OH;
    float* wa    = sm + OWA;
    float* wb    = sm + OWB;
    float* tw    = sm + OTW;
    float* score = sm + OSC;
    int*   flag  = (int*)(sm + OFL);
    int*   start = (int*)(sm + OST);
    int*   list  = (int*)(sm + OLS);
    float* ws    = sm + OWS;

    const int tid = threadIdx.x;
    const int lane = tid & 31;
    const int warp = tid >> 5;
    const int g0 = (int)(((long)blockIdx.x * NG) / DRUG_GRID);
    const int g1 = (int)(((long)(blockIdx.x + 1) * NG) / DRUG_GRID);
    const float winv = g_winv;
    const unsigned sb = smem_u32(sm);

    if (tid < DN) { wa[tid] = g_wa2[tid]; wb[tid] = g_wb2[tid]; tw[tid] = g_tw[tid]; }

    auto stage = [&](int g) {
        const int base = g * NPG;
        for (int i = tid; i < 3200; i += 512) {
            int nn = i / 50, q = i - nn * 50;
            cpa16(sb + (OXL + nn * VXL + q * 4) * 4, g_xlrel + (size_t)(base + nn) * 200 + q * 4);
        }
        if (tid < 32) cpa16(sb + (OLS + tid * 4) * 4, g_list + g * 128 + tid * 4);
        else if (tid < 49) cpa16(sb + (OST + (tid - 32) * 4) * 4, g_start + g * 68 + (tid - 32) * 4);
        cpa_commit();
    };

    stage(g0);

    const int ni   = tid >> 3;
    const int part = tid & 7;

    for (int g = g0; g < g1; ++g) {
        const int base = g * NPG;
        // root prefetch: strided columns c = part + 8*j -> coalesced 32B sectors
        float acc[25];
        {
            const float* xr = g_xlroot + (size_t)(base + ni) * 200 + part;
            #pragma unroll
            for (int j = 0; j < 25; ++j) acc[j] = xr[8*j];
        }
        cpa_wait<0>();
        __syncthreads();

        // h = relu((root + sum_in xl_rel[src])*wa + wb), columns part+8j
        {
            const int b0 = start[ni], b1 = start[ni + 1];
            for (int e = b0; e < b1; ++e) {
                const float* xp = xl + list[e] * VXL + part;
                #pragma unroll
                for (int j = 0; j < 25; ++j) acc[j] += xp[8*j];
            }
            #pragma unroll
            for (int j = 0; j < 25; ++j) {
                int cc = part + 8*j;
                hsh[ni * VH + cc] = fmaxf(acc[j] * wa[cc] + wb[cc], 0.f);
            }
        }
        __syncthreads();
        if (g + 1 < g1) stage(g + 1);

        // score (partials over strided columns)
        {
            float s = 0.f;
            const float* hp  = &hsh[ni * VH + part];
            const float* twp = &tw[part];
            #pragma unroll
            for (int j = 0; j < 25; ++j) s += hp[8*j] * twp[8*j];
            s += __shfl_xor_sync(0xffffffffu, s, 1);
            s += __shfl_xor_sync(0xffffffffu, s, 2);
            s += __shfl_xor_sync(0xffffffffu, s, 4);
            if (part == 0) score[ni] = tanhf(s * winv);
        }
        __syncthreads();

        // rank
        {
            float sn = score[ni];
            int r = 0;
            #pragma unroll
            for (int m2 = part*8; m2 < part*8 + 8; ++m2) {
                float sv = score[m2];
                r += (sv > sn) || (sv == sn && m2 < ni);
            }
            r += __shfl_xor_sync(0xffffffffu, r, 1);
            r += __shfl_xor_sync(0xffffffffu, r, 2);
            r += __shfl_xor_sync(0xffffffffu, r, 4);
            if (part == 0) flag[ni] = (r < KTOP) ? 1 : 0;
        }
        __syncthreads();

        // readout + resp partials
        float p = 0.f;
        if (tid < 200) {
            const int c = tid;
            float mx = -1e30f, sum = 0.f, mxs = -1e30f, sums = 0.f;
            for (int n2 = 0; n2 < NPG; ++n2) {
                float v = hsh[n2 * VH + c];
                mx = fmaxf(mx, v); sum += v;
                if (flag[n2]) {
                    float w = v * score[n2];
                    mxs = fmaxf(mxs, w); sums += w;
                }
            }
            float d0 = fmaxf(mx + 3.f*mxs, 0.f);
            float d1 = fmaxf(sum*(1.f/NPG) + 3.f*(sums*(1.f/KTOP)), 0.f);
            p = d0 * Wp[100 + c] + d1 * Wp[300 + c];
        } else if (tid < 300) {
            int i = tid - 200;
            p = out[(size_t)g*H2 + i] * Wp[i];
        }
        #pragma unroll
        for (int o = 16; o; o >>= 1) p += __shfl_down_sync(0xffffffffu, p, o);
        if (lane == 0) ws[warp] = p;
        __syncthreads();
        if (tid == 0) {
            float s = 0.f;
            #pragma unroll
            for (int w = 0; w < 16; ++w) s += ws[w];
            out[(size_t)2*NB*H2 + g] = s + bp[0];
        }
        __syncthreads();
    }
}

extern "C" void kernel_launch(void* const* d_in, const int* in_sizes, int n_in,
                              void* d_out, int out_size)
{
    const float* x1     = (const float*)d_in[0];
    const float* x2     = (const float*)d_in[1];
    const int*   eidx   = (const int*)d_in[4];
    const float* drug_x = (const float*)d_in[5];
    const float* bn0_s  = (const float*)d_in[6];
    const float* bn0_t  = (const float*)d_in[7];
    const float* W1     = (const float*)d_in[8];
    const float* b1     = (const float*)d_in[9];
    const float* bn1_s  = (const float*)d_in[10];
    const float* bn1_t  = (const float*)d_in[11];
    const float* W2     = (const float*)d_in[12];
    const float* b2     = (const float*)d_in[13];
    const float* bn2_s  = (const float*)d_in[14];
    const float* bn2_t  = (const float*)d_in[15];
    const float* Wrel   = (const float*)d_in[16];
    const float* brel   = (const float*)d_in[17];
    const float* Wroot  = (const float*)d_in[18];
    const float* bnd_s  = (const float*)d_in[19];
    const float* bnd_t  = (const float*)d_in[20];
    const float* topk_w = (const float*)d_in[21];
    const float* Wp     = (const float*)d_in[22];
    const float* bp     = (const float*)d_in[23];
    float* out = (float*)d_out;

    cudaFuncSetAttribute(drug_kernel, cudaFuncAttributeMaxDynamicSharedMemorySize, DRUG_SMEM_BYTES);
    cudaFuncSetAttribute(mega_g1xl, cudaFuncAttributeMaxDynamicSharedMemorySize, MEGA_DSMEM);

    prep_all<<<(int)((R5 + 255) / 256), 256>>>(x1, x2, W1, W2, bn0_s, bn0_t,
                                               drug_x, Wrel, Wroot, brel,
                                               bnd_s, bnd_t, topk_w);
    edge_prep<<<NG, 128>>>(eidx);
    mega_g1xl<<<128 + 1280, 1024, MEGA_DSMEM>>>(b1, bn1_s, bn1_t);
    gemm2_mma<<<M_TOT / 32, 256>>>(b2, bn2_s, bn2_t, out);
    drug_kernel<<<DRUG_GRID, 512, DRUG_SMEM_BYTES>>>(Wp, bp, out);
}

// round 17
// speedup vs baseline: 2.3581x; 1.0354x over previous
#include <cuda_runtime.h>
#include <cuda_bf16.h>
#include <cuda_fp16.h>
#include <math.h>
#include <stdint.h>

#define NB      2048
#define EXPR    8000
#define H1      1024
#define H2      100
#define M_TOT   4096
#define DD      78
#define DN      200
#define NPG     64
#define EPG     128
#define NG      2048
#define NT_ALL  131072
#define ET_TOT  262144
#define KTOP    52

__device__ __half g_h1h[(size_t)M_TOT * H1];
__device__ __half g_Ah[(size_t)M_TOT * EXPR];
__device__ __half g_Bh[(size_t)H1 * EXPR];
__device__ __half g_W2h[(size_t)128 * H1];
__device__ __nv_bfloat16 g_dxhi[(size_t)NT_ALL * 80];
__device__ __nv_bfloat16 g_dxlo[(size_t)NT_ALL * 80];
__device__ __nv_bfloat16 g_wxhi[400 * 80];
__device__ __nv_bfloat16 g_wxlo[400 * 80];
__device__ float g_xlrel[(size_t)NT_ALL * 200];
__device__ float g_xlroot[(size_t)NT_ALL * 200];
__device__ int   g_list[NG * 128];
__device__ int   g_start[NG * 68];
__device__ float g_wa2[DN], g_wb2[DN];
__device__ float g_tw[DN];
__device__ float g_winv;

__device__ __forceinline__ unsigned smem_u32(const void* p) {
    unsigned a;
    asm("{ .reg .u64 t; cvta.to.shared.u64 t, %1; cvt.u32.u64 %0, t; }" : "=r"(a) : "l"(p));
    return a;
}
__device__ __forceinline__ void cpa16(unsigned s, const void* g) {
    asm volatile("cp.async.cg.shared.global [%0], [%1], 16;" :: "r"(s), "l"(g));
}
__device__ __forceinline__ void cpa_commit() { asm volatile("cp.async.commit_group;" ::: "memory"); }
template<int N> __device__ __forceinline__ void cpa_wait() {
    asm volatile("cp.async.wait_group %0;" :: "n"(N) : "memory");
}
__device__ __forceinline__ void ldmx4(unsigned* r, unsigned addr) {
    asm volatile("ldmatrix.sync.aligned.m8n8.x4.shared.b16 {%0,%1,%2,%3}, [%4];"
        : "=r"(r[0]), "=r"(r[1]), "=r"(r[2]), "=r"(r[3]) : "r"(addr));
}
__device__ __forceinline__ void mma16816bf(float* d, const unsigned* a, const unsigned* b) {
    asm volatile("mma.sync.aligned.m16n8k16.row.col.f32.bf16.bf16.f32 "
        "{%0,%1,%2,%3}, {%4,%5,%6,%7}, {%8,%9}, {%0,%1,%2,%3};"
        : "+f"(d[0]), "+f"(d[1]), "+f"(d[2]), "+f"(d[3])
        : "r"(a[0]), "r"(a[1]), "r"(a[2]), "r"(a[3]), "r"(b[0]), "r"(b[1]));
}
__device__ __forceinline__ void mma16816h(float* d, const unsigned* a, const unsigned* b) {
    asm volatile("mma.sync.aligned.m16n8k16.row.col.f32.f16.f16.f32 "
        "{%0,%1,%2,%3}, {%4,%5,%6,%7}, {%8,%9}, {%0,%1,%2,%3};"
        : "+f"(d[0]), "+f"(d[1]), "+f"(d[2]), "+f"(d[3])
        : "r"(a[0]), "r"(a[1]), "r"(a[2]), "r"(a[3]), "r"(b[0]), "r"(b[1]));
}

__device__ __forceinline__ void conv4h(__half* dst, float4 v) {
    union { __half b[4]; uint2 u; } H;
    H.b[0]=__float2half_rn(v.x); H.b[1]=__float2half_rn(v.y);
    H.b[2]=__float2half_rn(v.z); H.b[3]=__float2half_rn(v.w);
    *(uint2*)dst = H.u;
}
__device__ __forceinline__ void split2(__nv_bfloat16* hi, __nv_bfloat16* lo, float a, float b) {
    __nv_bfloat16 h0=__float2bfloat16_rn(a), h1=__float2bfloat16_rn(b);
    union { __nv_bfloat16 v[2]; unsigned u; } H, L;
    H.v[0]=h0; H.v[1]=h1;
    L.v[0]=__float2bfloat16_rn(a-__bfloat162float(h0));
    L.v[1]=__float2bfloat16_rn(b-__bfloat162float(h1));
    *(unsigned*)hi = H.u;  *(unsigned*)lo = L.u;
}

// ---------------- prep_all ----------------
#define R0 ((long)M_TOT * 2000)
#define R1 (R0 + (long)H1 * 2000)
#define R2 (R1 + 128 * 256)
#define R3 (R2 + (long)NT_ALL * 40)
#define R4 (R3 + 400 * 40)
#define R5 (R4 + 256)

__global__ __launch_bounds__(256) void prep_all(
    const float* __restrict__ x1, const float* __restrict__ x2,
    const float* __restrict__ W1, const float* __restrict__ W2,
    const float* __restrict__ bn0_s, const float* __restrict__ bn0_t,
    const float* __restrict__ dx,
    const float* __restrict__ Wrel, const float* __restrict__ Wroot,
    const float* __restrict__ brel,
    const float* __restrict__ bnd_s, const float* __restrict__ bnd_t,
    const float* __restrict__ topk_w)
{
    long i = (long)blockIdx.x * 256 + threadIdx.x;
    if (i >= R5) return;
    if (i < R0) {
        int row = (int)(i / 2000), k4 = (int)(i % 2000);
        const float* src = (row < NB) ? (x1 + (size_t)row * EXPR) : (x2 + (size_t)(row - NB) * EXPR);
        float4 v = *(const float4*)(src + k4 * 4);
        float4 s = *(const float4*)(bn0_s + k4 * 4);
        float4 t = *(const float4*)(bn0_t + k4 * 4);
        v.x = v.x*s.x + t.x;  v.y = v.y*s.y + t.y;  v.z = v.z*s.z + t.z;  v.w = v.w*s.w + t.w;
        conv4h(g_Ah + (size_t)row * EXPR + (size_t)k4 * 4, v);
    } else if (i < R1) {
        long j = i - R0;
        int row = (int)(j / 2000), k4 = (int)(j % 2000);
        float4 v = *(const float4*)(W1 + (size_t)row * EXPR + k4 * 4);
        conv4h(g_Bh + (size_t)row * EXPR + (size_t)k4 * 4, v);
    } else if (i < R2) {
        long j = i - R1;
        int row = (int)(j >> 8), k4 = (int)(j & 255);
        float4 v = make_float4(0.f, 0.f, 0.f, 0.f);
        if (row < H2) v = *(const float4*)(W2 + (size_t)row * H1 + k4 * 4);
        conv4h(g_W2h + (size_t)row * H1 + k4 * 4, v);
    } else if (i < R3) {
        long j = i - R2;
        int n = (int)(j / 40), kp = (int)(j % 40);
        int k0 = 2 * kp;
        float a = (k0     < DD) ? dx[(size_t)n * DD + k0]     : 0.f;
        float b = (k0 + 1 < DD) ? dx[(size_t)n * DD + k0 + 1] : 0.f;
        size_t eo = (size_t)n * 80 + k0;
        split2(g_dxhi + eo, g_dxlo + eo, a, b);
    } else if (i < R4) {
        long j = i - R3;
        int n = (int)(j / 40), kp = (int)(j % 40);
        int k0 = 2 * kp;
        float a = 0.f, b = 0.f;
        if (k0 < DD)     a = (n < DN) ? Wrel[n*DD + k0]     : Wroot[(n-DN)*DD + k0];
        if (k0 + 1 < DD) b = (n < DN) ? Wrel[n*DD + k0 + 1] : Wroot[(n-DN)*DD + k0 + 1];
        split2(g_wxhi + n*80 + k0, g_wxlo + n*80 + k0, a, b);
    } else {
        int j = (int)(i - R4);
        if (j < DN) {
            float al = bnd_s[j];
            g_wa2[j] = al;
            g_wb2[j] = brel[j]*al + bnd_t[j];
            g_tw[j]  = topk_w[j];
        }
        if (j == 0) {
            float s = 0.f;
            for (int c = 0; c < DN; ++c) s += topk_w[c]*topk_w[c];
            g_winv = rsqrtf(s);
        }
    }
}

// ---------------- MEGA: gemm1 (bid<128) + xl (bid>=128) ----------------
#define KC    32
#define NCH   250
#define AST   40
#define OFF_A 0
#define OFF_B 20480
#define STG   30720
#define XAST  88
#define XB_LO 14080
#define XA_BASE 28160
#define XA_LO 22528
#define XA_PER 45056
#define MEGA_DSMEM (XA_BASE + 4 * XA_PER)

__global__ void __launch_bounds__(1024, 1) mega_g1xl(
    const float* __restrict__ b1, const float* __restrict__ bn1_s,
    const float* __restrict__ bn1_t)
{
    extern __shared__ char dynsm[];
    __shared__ float s_alpha[128], s_beta[128];
    const unsigned sb = smem_u32(dynsm);
    const int tid = threadIdx.x;
    const int bid = blockIdx.x;
    const int lane = tid & 31;

    if (bid < 128) {
        const int warp = tid >> 5;
        const int m0 = (bid >> 3) * 256;
        const int n0 = (bid & 7) * 128;
        const int wm = (warp >> 2) * 32;
        const int wn = (warp & 3) * 32;

        if (tid < 128) {
            float al = bn1_s[n0 + tid];
            s_alpha[tid] = al;
            s_beta[tid]  = b1[n0 + tid] * al + bn1_t[n0 + tid];
        }

        auto load_chunk = [&](int c, int s) {
            const unsigned st = sb + s * STG;
            const long k0 = (long)c * KC;
            {
                int r = tid >> 2, q = tid & 3;
                unsigned off = r * 80 + q * 16;
                size_t go = (size_t)(m0 + r) * EXPR + k0 + q * 8;
                cpa16(st + OFF_A + off, g_Ah + go);
            }
            if (tid < 512) {
                int r = tid >> 2, q = tid & 3;
                unsigned off = r * 80 + q * 16;
                size_t go = (size_t)(n0 + r) * EXPR + k0 + q * 8;
                cpa16(st + OFF_B + off, g_Bh + go);
            }
            cpa_commit();
        };

        float acc[2][4][4];
        #pragma unroll
        for (int i = 0; i < 2; ++i)
            #pragma unroll
            for (int j = 0; j < 4; ++j)
                #pragma unroll
                for (int q = 0; q < 4; ++q) acc[i][j][q] = 0.f;

        load_chunk(0, 0);
        load_chunk(1, 1);

        const int arow = lane & 15;
        const int acol = (lane >> 4) << 3;

        for (int c = 0; c < NCH; ++c) {
            const int s = c - (c / 3) * 3;
            if (c + 1 < NCH) cpa_wait<1>(); else cpa_wait<0>();
            __syncthreads();
            if (c + 2 < NCH) {
                int s2 = (c + 2) - ((c + 2) / 3) * 3;
                load_chunk(c + 2, s2);
            }
            const unsigned aA = sb + s * STG;
            const unsigned bB = aA + OFF_B;
            #pragma unroll
            for (int ks = 0; ks < KC; ks += 16) {
                unsigned ah[8], bh[8];
                #pragma unroll
                for (int i = 0; i < 2; ++i)
                    ldmx4(&ah[4*i], aA + ((wm + i*16 + arow) * AST + ks + acol) * 2);
                #pragma unroll
                for (int j2 = 0; j2 < 2; ++j2) {
                    unsigned tr[4];
                    ldmx4(tr, bB + ((wn + j2*16 + arow) * AST + ks + acol) * 2);
                    bh[4*j2 + 0] = tr[0];  bh[4*j2 + 1] = tr[2];
                    bh[4*j2 + 2] = tr[1];  bh[4*j2 + 3] = tr[3];
                }
                #pragma unroll
                for (int i = 0; i < 2; ++i)
                    #pragma unroll
                    for (int j = 0; j < 4; ++j)
                        mma16816h(acc[i][j], &ah[4*i], &bh[2*j]);
            }
        }

        const int er = lane >> 2, ec = (lane & 3) * 2;
        #pragma unroll
        for (int i = 0; i < 2; ++i) {
            #pragma unroll
            for (int j = 0; j < 4; ++j) {
                int nl = wn + j*8 + ec;
                float a0 = s_alpha[nl], a1 = s_alpha[nl+1];
                float e0 = s_beta[nl],  e1 = s_beta[nl+1];
                int mg0 = m0 + wm + i*16 + er;
                __half2 h0 = __floats2half2_rn(fmaxf(acc[i][j][0]*a0 + e0, 0.f),
                                               fmaxf(acc[i][j][1]*a1 + e1, 0.f));
                __half2 h1v = __floats2half2_rn(fmaxf(acc[i][j][2]*a0 + e0, 0.f),
                                                fmaxf(acc[i][j][3]*a1 + e1, 0.f));
                *(__half2*)&g_h1h[(size_t)mg0 * H1 + n0 + nl]       = h0;
                *(__half2*)&g_h1h[(size_t)(mg0 + 8) * H1 + n0 + nl] = h1v;
            }
        }
    } else {
        const int bid2 = bid - 128;
        const int nt = bid2 >> 8;
        const int mt = bid2 & 255;
        const int q  = tid >> 8;
        const int qtid = tid & 255;
        const int m0 = (mt * 4 + q) * 128;
        const int n0 = nt * 80;
        const unsigned sbB = sb;
        const unsigned sbA = sb + XA_BASE + q * XA_PER;

        if (tid < 800) {
            int r = tid / 10, qq = tid - r * 10;
            unsigned off = r * 176 + qq * 16;
            size_t go = (size_t)(n0 + r) * 80 + qq * 8;
            cpa16(sbB + off, g_wxhi + go);
            cpa16(sbB + XB_LO + off, g_wxlo + go);
        }
        #pragma unroll
        for (int t = 0; t < 5; ++t) {
            int i = qtid + t * 256;
            int r = i / 10, qq = i - r * 10;
            unsigned off = r * 176 + qq * 16;
            size_t go = (size_t)(m0 + r) * 80 + qq * 8;
            cpa16(sbA + off, g_dxhi + go);
            cpa16(sbA + XA_LO + off, g_dxlo + go);
        }
        cpa_commit();
        cpa_wait<0>();
        __syncthreads();

        float acc[10][4];
        #pragma unroll
        for (int j = 0; j < 10; ++j)
            #pragma unroll
            for (int p = 0; p < 4; ++p) acc[j][p] = 0.f;

        const int warp = qtid >> 5;
        const int arow = lane & 15;
        const int acol = (lane >> 4) << 3;

        #pragma unroll
        for (int ks = 0; ks < 80; ks += 16) {
            unsigned ah[4], al[4];
            ldmx4(ah, sbA + ((warp*16 + arow) * XAST + ks + acol) * 2);
            ldmx4(al, sbA + XA_LO + ((warp*16 + arow) * XAST + ks + acol) * 2);
            #pragma unroll
            for (int jb = 0; jb < 5; ++jb) {
                unsigned trh[4], trl[4], b0[2], b1[2], c0[2], c1[2];
                ldmx4(trh, sbB + ((jb*16 + arow) * XAST + ks + acol) * 2);
                ldmx4(trl, sbB + XB_LO + ((jb*16 + arow) * XAST + ks + acol) * 2);
                b0[0] = trh[0]; b0[1] = trh[2];
                b1[0] = trh[1]; b1[1] = trh[3];
                c0[0] = trl[0]; c0[1] = trl[2];
                c1[0] = trl[1]; c1[1] = trl[3];
                mma16816bf(acc[2*jb],   ah, b0);
                mma16816bf(acc[2*jb],   ah, c0);
                mma16816bf(acc[2*jb],   al, b0);
                mma16816bf(acc[2*jb+1], ah, b1);
                mma16816bf(acc[2*jb+1], ah, c1);
                mma16816bf(acc[2*jb+1], al, b1);
            }
        }

        const int er = lane >> 2, ec = (lane & 3) * 2;
        const int grow = m0 + warp*16 + er;
        #pragma unroll
        for (int j = 0; j < 10; ++j) {
            int gc = n0 + 8*j + ec;
            float2 v0 = make_float2(acc[j][0], acc[j][1]);
            float2 v1 = make_float2(acc[j][2], acc[j][3]);
            if (gc < 200) {
                *(float2*)&g_xlrel[(size_t)grow * 200 + gc]       = v0;
                *(float2*)&g_xlrel[(size_t)(grow + 8) * 200 + gc] = v1;
            } else {
                *(float2*)&g_xlroot[(size_t)grow * 200 + gc - 200]       = v0;
                *(float2*)&g_xlroot[(size_t)(grow + 8) * 200 + gc - 200] = v1;
            }
        }
    }
}

// ---------------- GEMM2 + edge_prep merged ----------------
__global__ __launch_bounds__(256) void gemm2_edge(
    const float* __restrict__ b2, const float* __restrict__ bn2_s,
    const float* __restrict__ bn2_t, float* __restrict__ out,
    const int* __restrict__ edge_index)
{
    __shared__ __align__(16) __half sm2[3 * 6400];
    const int tid = threadIdx.x;

    if (blockIdx.x < 128) {
        const int warp = tid >> 5, lane = tid & 31;
        const int m0 = blockIdx.x * 32;
        const int wm = (warp >> 2) * 16;
        const int wn = (warp & 3) * 32;
        const unsigned sb = smem_u32(sm2);

        auto load_chunk = [&](int c, int s) {
            const unsigned st = sb + s * 12800;
            if (tid < 128) {
                int r = tid >> 2, q = tid & 3;
                cpa16(st + (r * 40 + q * 8) * 2, g_h1h + (size_t)(m0 + r) * H1 + c * 32 + q * 8);
            }
            #pragma unroll
            for (int t = 0; t < 2; ++t) {
                int i = tid + t * 256;
                int r = i >> 2, q = i & 3;
                cpa16(st + 2560 + (r * 40 + q * 8) * 2, g_W2h + (size_t)r * H1 + c * 32 + q * 8);
            }
            cpa_commit();
        };

        float acc[4][4];
        #pragma unroll
        for (int j = 0; j < 4; ++j)
            #pragma unroll
            for (int q = 0; q < 4; ++q) acc[j][q] = 0.f;

        load_chunk(0, 0);
        load_chunk(1, 1);

        const int arow = lane & 15;
        const int acol = (lane >> 4) << 3;

        for (int c = 0; c < 32; ++c) {
            const int s = c - (c / 3) * 3;
            if (c + 1 < 32) cpa_wait<1>(); else cpa_wait<0>();
            __syncthreads();
            if (c + 2 < 32) {
                int s2 = (c + 2) - ((c + 2) / 3) * 3;
                load_chunk(c + 2, s2);
            }
            const unsigned aA = sb + s * 12800;
            const unsigned bB = aA + 2560;
            #pragma unroll
            for (int ks = 0; ks < 32; ks += 16) {
                unsigned ah[4], bh[8];
                ldmx4(ah, aA + ((wm + arow) * 40 + ks + acol) * 2);
                #pragma unroll
                for (int j2 = 0; j2 < 2; ++j2) {
                    unsigned tr[4];
                    ldmx4(tr, bB + ((wn + j2*16 + arow) * 40 + ks + acol) * 2);
                    bh[4*j2 + 0] = tr[0];  bh[4*j2 + 1] = tr[2];
                    bh[4*j2 + 2] = tr[1];  bh[4*j2 + 3] = tr[3];
                }
                #pragma unroll
                for (int j = 0; j < 4; ++j)
                    mma16816h(acc[j], ah, &bh[2*j]);
            }
        }

        const int er = lane >> 2, ec = (lane & 3) * 2;
        #pragma unroll
        for (int j = 0; j < 4; ++j) {
            int n = wn + j*8 + ec;
            if (n >= H2) continue;
            float a0 = bn2_s[n],   a1 = bn2_s[n+1];
            float e0 = b2[n]*a0 + bn2_t[n];
            float e1 = b2[n+1]*a1 + bn2_t[n+1];
            int m_a = m0 + wm + er, m_b = m_a + 8;
            float va0 = fmaxf(acc[j][0]*a0 + e0, 0.f);
            float va1 = fmaxf(acc[j][1]*a1 + e1, 0.f);
            float vb0 = fmaxf(acc[j][2]*a0 + e0, 0.f);
            float vb1 = fmaxf(acc[j][3]*a1 + e1, 0.f);
            size_t oa = (m_a < NB) ? ((size_t)m_a*H2 + n) : ((size_t)NB*H2 + (size_t)(m_a - NB)*H2 + n);
            size_t ob = (m_b < NB) ? ((size_t)m_b*H2 + n) : ((size_t)NB*H2 + (size_t)(m_b - NB)*H2 + n);
            out[oa] = va0;  out[oa + 1] = va1;
            out[ob] = vb0;  out[ob + 1] = vb1;
        }
    } else {
        // edge CSR build: 2 graphs per CTA (warp-aligned 128-thread halves)
        int* ish = (int*)sm2;
        const int sub  = tid >> 7;
        const int stid = tid & 127;
        const int g = (blockIdx.x - 128) * 2 + sub;
        int* es    = ish + sub * EPG;
        int* ed    = ish + 256 + sub * EPG;
        int* cnt   = ish + 512 + sub * NPG;
        int* start = ish + 640 + sub * (NPG + 1);

        es[stid] = edge_index[g*EPG + stid] - g*NPG;
        ed[stid] = edge_index[ET_TOT + g*EPG + stid] - g*NPG;
        __syncthreads();
        if (stid < NPG) {
            int c = 0;
            for (int e = 0; e < EPG; ++e) c += (ed[e] == stid);
            cnt[stid] = c;
        }
        __syncthreads();
        if (stid < 32) {
            int ca = cnt[2*stid], cb = cnt[2*stid+1];
            int pv = ca + cb, s = pv;
            #pragma unroll
            for (int o = 1; o < 32; o <<= 1) {
                int t = __shfl_up_sync(0xffffffffu, s, o);
                if (stid >= o) s += t;
            }
            int excl = s - pv;
            start[2*stid] = excl;
            start[2*stid+1] = excl + ca;
            if (stid == 31) start[NPG] = s;
        }
        __syncthreads();
        if (stid < NPG) {
            int pos = start[stid];
            for (int e = 0; e < EPG; ++e)
                if (ed[e] == stid) g_list[g*128 + pos++] = es[e];
        }
        if (stid < 68) g_start[g*68 + stid] = (stid <= NPG) ? start[stid] : 0;
    }
}

// ---------------- Drug v10: fused score, split readout ----------------
#define VXL 204
#define VH  201
#define OXL 0
#define OH  13056
#define OWA 25920
#define OWB 26120
#define OTW 26320
#define OSC 26520
#define OFL 26584
#define OST 26648
#define OLS 26716
#define OWS 26844
#define OSCR 26860
#define DTOT 28460
#define DRUG_SMEM_BYTES (DTOT * 4)
#define DRUG_GRID 296

__global__ __launch_bounds__(512, 2) void drug_kernel(
    const float* __restrict__ Wp, const float* __restrict__ bp,
    float* __restrict__ out)
{
    extern __shared__ float sm[];
    float* xl    = sm + OXL;
    float* hsh   = sm + OH;
    float* wa    = sm + OWA;
    float* wb    = sm + OWB;
    float* tw    = sm + OTW;
    float* score = sm + OSC;
    int*   flag  = (int*)(sm + OFL);
    int*   start = (int*)(sm + OST);
    int*   list  = (int*)(sm + OLS);
    float* ws    = sm + OWS;
    float* scr   = sm + OSCR;

    const int tid = threadIdx.x;
    const int lane = tid & 31;
    const int warp = tid >> 5;
    const int g0 = (int)(((long)blockIdx.x * NG) / DRUG_GRID);
    const int g1 = (int)(((long)(blockIdx.x + 1) * NG) / DRUG_GRID);
    const float winv = g_winv;
    const unsigned sb = smem_u32(sm);

    if (tid < DN) { wa[tid] = g_wa2[tid]; wb[tid] = g_wb2[tid]; tw[tid] = g_tw[tid]; }

    auto stage = [&](int g) {
        const int base = g * NPG;
        for (int i = tid; i < 3200; i += 512) {
            int nn = i / 50, q = i - nn * 50;
            cpa16(sb + (OXL + nn * VXL + q * 4) * 4, g_xlrel + (size_t)(base + nn) * 200 + q * 4);
        }
        if (tid < 32) cpa16(sb + (OLS + tid * 4) * 4, g_list + g * 128 + tid * 4);
        else if (tid < 49) cpa16(sb + (OST + (tid - 32) * 4) * 4, g_start + g * 68 + (tid - 32) * 4);
        cpa_commit();
    };

    stage(g0);

    const int ni   = tid >> 3;
    const int part = tid & 7;

    for (int g = g0; g < g1; ++g) {
        const int base = g * NPG;
        // root + f1 prefetch (issued before barriers)
        float acc[25];
        {
            const float* xr = g_xlroot + (size_t)(base + ni) * 200 + part;
            #pragma unroll
            for (int j = 0; j < 25; ++j) acc[j] = xr[8*j];
        }
        float f1v = 0.f;
        if (tid >= 200 && tid < 300) f1v = out[(size_t)g*H2 + (tid - 200)];
        cpa_wait<0>();
        __syncthreads();

        // h + score partial (score computed from in-register h)
        {
            const int b0 = start[ni], b1 = start[ni + 1];
            for (int e = b0; e < b1; ++e) {
                const float* xp = xl + list[e] * VXL + part;
                #pragma unroll
                for (int j = 0; j < 25; ++j) acc[j] += xp[8*j];
            }
            float s = 0.f;
            #pragma unroll
            for (int j = 0; j < 25; ++j) {
                int cc = part + 8*j;
                float h = fmaxf(acc[j] * wa[cc] + wb[cc], 0.f);
                hsh[ni * VH + cc] = h;
                s += h * tw[cc];
            }
            s += __shfl_xor_sync(0xffffffffu, s, 1);
            s += __shfl_xor_sync(0xffffffffu, s, 2);
            s += __shfl_xor_sync(0xffffffffu, s, 4);
            if (part == 0) score[ni] = tanhf(s * winv);
        }
        __syncthreads();
        if (g + 1 < g1) stage(g + 1);

        // rank
        {
            float sn = score[ni];
            int r = 0;
            #pragma unroll
            for (int m2 = part*8; m2 < part*8 + 8; ++m2) {
                float sv = score[m2];
                r += (sv > sn) || (sv == sn && m2 < ni);
            }
            r += __shfl_xor_sync(0xffffffffu, r, 1);
            r += __shfl_xor_sync(0xffffffffu, r, 2);
            r += __shfl_xor_sync(0xffffffffu, r, 4);
            if (part == 0) flag[ni] = (r < KTOP) ? 1 : 0;
        }
        __syncthreads();

        // readout halves: 400 threads = 200 cols x 2 node-halves
        if (tid < 400) {
            const int c = (tid < 200) ? tid : tid - 200;
            const int h0 = (tid < 200) ? 0 : 32;
            float mx = -1e30f, sum = 0.f, mxs = -1e30f, sums = 0.f;
            for (int n2 = h0; n2 < h0 + 32; ++n2) {
                float v = hsh[n2 * VH + c];
                mx = fmaxf(mx, v); sum += v;
                if (flag[n2]) {
                    float w = v * score[n2];
                    mxs = fmaxf(mxs, w); sums += w;
                }
            }
            scr[tid]        = mx;
            scr[400 + tid]  = sum;
            scr[800 + tid]  = mxs;
            scr[1200 + tid] = sums;
        }
        __syncthreads();

        // combine + resp partials
        float p = 0.f;
        if (tid < 200) {
            float mx   = fmaxf(scr[tid],        scr[200 + tid]);
            float sum  = scr[400 + tid] + scr[600 + tid];
            float mxs  = fmaxf(scr[800 + tid],  scr[1000 + tid]);
            float sums = scr[1200 + tid] + scr[1400 + tid];
            float d0 = fmaxf(mx + 3.f*mxs, 0.f);
            float d1 = fmaxf(sum*(1.f/NPG) + 3.f*(sums*(1.f/KTOP)), 0.f);
            p = d0 * Wp[100 + tid] + d1 * Wp[300 + tid];
        } else if (tid < 300) {
            p = f1v * Wp[tid - 200];
        }
        #pragma unroll
        for (int o = 16; o; o >>= 1) p += __shfl_down_sync(0xffffffffu, p, o);
        if (lane == 0) ws[warp] = p;
        __syncthreads();
        if (tid == 0) {
            float s = 0.f;
            #pragma unroll
            for (int w = 0; w < 16; ++w) s += ws[w];
            out[(size_t)2*NB*H2 + g] = s + bp[0];
        }
        __syncthreads();
    }
}

extern "C" void kernel_launch(void* const* d_in, const int* in_sizes, int n_in,
                              void* d_out, int out_size)
{
    const float* x1     = (const float*)d_in[0];
    const float* x2     = (const float*)d_in[1];
    const int*   eidx   = (const int*)d_in[4];
    const float* drug_x = (const float*)d_in[5];
    const float* bn0_s  = (const float*)d_in[6];
    const float* bn0_t  = (const float*)d_in[7];
    const float* W1     = (const float*)d_in[8];
    const float* b1     = (const float*)d_in[9];
    const float* bn1_s  = (const float*)d_in[10];
    const float* bn1_t  = (const float*)d_in[11];
    const float* W2     = (const float*)d_in[12];
    const float* b2     = (const float*)d_in[13];
    const float* bn2_s  = (const float*)d_in[14];
    const float* bn2_t  = (const float*)d_in[15];
    const float* Wrel   = (const float*)d_in[16];
    const float* brel   = (const float*)d_in[17];
    const float* Wroot  = (const float*)d_in[18];
    const float* bnd_s  = (const float*)d_in[19];
    const float* bnd_t  = (const float*)d_in[20];
    const float* topk_w = (const float*)d_in[21];
    const float* Wp     = (const float*)d_in[22];
    const float* bp     = (const float*)d_in[23];
    float* out = (float*)d_out;

    cudaFuncSetAttribute(drug_kernel, cudaFuncAttributeMaxDynamicSharedMemorySize, DRUG_SMEM_BYTES);
    cudaFuncSetAttribute(mega_g1xl, cudaFuncAttributeMaxDynamicSharedMemorySize, MEGA_DSMEM);

    prep_all<<<(int)((R5 + 255) / 256), 256>>>(x1, x2, W1, W2, bn0_s, bn0_t,
                                               drug_x, Wrel, Wroot, brel,
                                               bnd_s, bnd_t, topk_w);
    mega_g1xl<<<128 + 1280, 1024, MEGA_DSMEM>>>(b1, bn1_s, bn1_t);
    gemm2_edge<<<128 + 1024, 256>>>(b2, bn2_s, bn2_t, out, eidx);
    drug_kernel<<<DRUG_GRID, 512, DRUG_SMEM_BYTES>>>(Wp, bp, out);
}